// round 6
// baseline (speedup 1.0000x reference)
#include <cuda_runtime.h>
#include <math.h>

#define BB 2
#define TT 2048
#define DD 1024
#define HH 16
#define HIDD 4096
#define BT (BB*TT)   // 4096 rows

// ---------------- scratch ----------------
__device__ float g_xn [BB*TT*DD];
__device__ float g_y  [BB*TT*DD];
__device__ float g_q  [BB*TT*DD];
__device__ float g_k  [BB*TT*DD];
__device__ float g_v  [BB*TT*DD];
__device__ float g_ao [BB*TT*DD];
__device__ float g_x1 [BB*TT*DD];
__device__ float g_xn2[BB*TT*DD];
__device__ float g_hb [BB*TT*HIDD];

// ---------------- helpers ----------------
__device__ __forceinline__ unsigned f2tf32(float x)
{
    unsigned r;
    asm("cvt.rna.tf32.f32 %0, %1;" : "=r"(r) : "f"(x));
    return r;
}
__device__ __forceinline__ float f2tf32f(float x) { return __uint_as_float(f2tf32(x)); }

__device__ __forceinline__ void ldmx4(unsigned& a0, unsigned& a1, unsigned& a2, unsigned& a3,
                                      unsigned addr)
{
    asm volatile("ldmatrix.sync.aligned.m8n8.x4.shared.b16 {%0,%1,%2,%3}, [%4];"
                 : "=r"(a0), "=r"(a1), "=r"(a2), "=r"(a3) : "r"(addr));
}
__device__ __forceinline__ void ldmx2(unsigned& a0, unsigned& a1, unsigned addr)
{
    asm volatile("ldmatrix.sync.aligned.m8n8.x2.shared.b16 {%0,%1}, [%2];"
                 : "=r"(a0), "=r"(a1) : "r"(addr));
}
__device__ __forceinline__ void mma_tf32(float* d, const unsigned* a, unsigned b0, unsigned b1)
{
    asm volatile(
        "mma.sync.aligned.m16n8k8.row.col.f32.tf32.tf32.f32 "
        "{%0,%1,%2,%3}, {%4,%5,%6,%7}, {%8,%9}, {%0,%1,%2,%3};\n"
        : "+f"(d[0]), "+f"(d[1]), "+f"(d[2]), "+f"(d[3])
        : "r"(a[0]), "r"(a[1]), "r"(a[2]), "r"(a[3]), "r"(b0), "r"(b1));
}
__device__ __forceinline__ void cpasync16(void* smem, const void* gmem)
{
    unsigned s = (unsigned)__cvta_generic_to_shared(smem);
    asm volatile("cp.async.cg.shared.global [%0], [%1], 16;" :: "r"(s), "l"(gmem));
}
#define CP_COMMIT() asm volatile("cp.async.commit_group;")
#define CP_WAIT(n)  asm volatile("cp.async.wait_group %0;" :: "n"(n))

// ---------------- rmsnorm ----------------
__global__ void rmsnorm_kernel(const float* __restrict__ x, const float* __restrict__ g,
                               float* __restrict__ out)
{
    int row = blockIdx.x;
    int tid = threadIdx.x;
    const float4* xr = (const float4*)(x + (size_t)row * DD);
    float4 v = xr[tid];
    float s = v.x*v.x + v.y*v.y + v.z*v.z + v.w*v.w;
    #pragma unroll
    for (int o = 16; o; o >>= 1) s += __shfl_xor_sync(0xffffffffu, s, o);
    __shared__ float red[8];
    if ((tid & 31) == 0) red[tid >> 5] = s;
    __syncthreads();
    float tot = red[0]+red[1]+red[2]+red[3]+red[4]+red[5]+red[6]+red[7];
    float inv = rsqrtf(tot * (1.0f / (float)DD) + 1e-6f);
    const float4* gr = (const float4*)g;
    float4 gv = gr[tid];
    float4 o4;
    o4.x = gv.x * (v.x * inv);
    o4.y = gv.y * (v.y * inv);
    o4.z = gv.z * (v.z * inv);
    o4.w = gv.w * (v.w * inv);
    ((float4*)(out + (size_t)row * DD))[tid] = o4;
}

// ---------------- EMA scan ----------------
__global__ void ema_kernel(const float* __restrict__ xn,
                           const float* __restrict__ ap, const float* __restrict__ dp,
                           const float* __restrict__ beta, const float* __restrict__ eta,
                           float* __restrict__ y)
{
    int idx = blockIdx.x * blockDim.x + threadIdx.x;
    int n = idx & 15;
    int d = (idx >> 4) & (DD - 1);
    int b = idx >> 14;
    int dn = d * 16 + n;
    float a   = 1.0f / (1.0f + expf(-ap[dn]));
    float ddv = 1.0f / (1.0f + expf(-dp[dn]));
    float dec = 1.0f - a * ddv;
    float ab  = a * beta[dn];
    float et  = eta[dn];
    const float* xp = xn + (size_t)b * TT * DD + d;
    float* yp       = y  + (size_t)b * TT * DD + d;
    float h = 0.0f;
    for (int t = 0; t < TT; t++) {
        float u = xp[(size_t)t * DD];
        h = fmaf(dec, h, ab * u);
        float s = et * h;
        s += __shfl_xor_sync(0xffffffffu, s, 8, 16);
        s += __shfl_xor_sync(0xffffffffu, s, 4, 16);
        s += __shfl_xor_sync(0xffffffffu, s, 2, 16);
        s += __shfl_xor_sync(0xffffffffu, s, 1, 16);
        if (n == 0) yp[(size_t)t * DD] = s;
    }
}

// ---------------- RoPE ----------------
__global__ void rope_kernel(float* __restrict__ q, float* __restrict__ k, float* __restrict__ v)
{
    int idx = blockIdx.x * blockDim.x + threadIdx.x;
    int i = idx & 15;
    int h = (idx >> 4) & 15;
    int t = (idx >> 8) & (TT - 1);
    int b = idx >> 19;
    double fd = pow(10000.0, -(double)i / 16.0);
    float freq = (float)fd;
    float ang = (float)t * freq;
    double da = (double)ang;
    float c = (float)cos(da);
    float s = (float)sin(da);
    size_t base = ((size_t)(b * TT + t)) * DD + h * 64;
    {
        float x1 = q[base + i], x2 = q[base + 16 + i];
        q[base + i]      = x1 * c - x2 * s;
        q[base + 16 + i] = x2 * c + x1 * s;
    }
    {
        float x1 = k[base + i], x2 = k[base + 16 + i];
        k[base + i]      = x1 * c - x2 * s;
        k[base + 16 + i] = x2 * c + x1 * s;
    }
    {
        float x1 = v[base + i], x2 = v[base + 16 + i];
        v[base + i]      = x1 * c - x2 * s;
        v[base + 16 + i] = x2 * c + x1 * s;
    }
}

// ---------------- tf32 GEMM core: 128x128x16, cp.async 4-stage ----------------
__device__ __forceinline__ float gelu_tanh(float x)
{
    float x3 = x * x * x;
    float t = tanhf(0.7978845608028654f * (x + 0.044715f * x3));
    return 0.5f * x * (1.0f + t);
}

#define GSTAGES 4
#define AS_STRIDE (128*20)
#define BS_STRIDE (16*132)
#define SMEM_GEMM ((GSTAGES * (AS_STRIDE + BS_STRIDE)) * 4)

// EPI: 0 = none, 1 = +resid, 2 = gelu(acc+bias), 3 = acc+bias+resid
template<int EPI>
__device__ __forceinline__ void gemm_core(const float* __restrict__ A,
                                          const float* __restrict__ B,
                                          float* __restrict__ C,
                                          const float* __restrict__ bias,
                                          const float* __restrict__ resid,
                                          int N, int K, int bx, int by, float* sm)
{
    float* As = sm;                          // [GSTAGES][128][20] raw fp32 bits
    float* Bs = sm + GSTAGES * AS_STRIDE;    // [GSTAGES][16][132]

    const int tid  = threadIdx.x;
    const int lane = tid & 31;
    const int warp = tid >> 5;
    const int wm = (warp & 1) * 64;
    const int wn = (warp >> 1) * 32;
    const int lr = lane >> 2;
    const int lc = lane & 3;
    const int lrow  = (lane & 7) + (lane & 8);
    const int lkoff = (lane >> 4) * 4;

    const int am = tid >> 2;
    const int ak = (tid & 3) << 2;
    const int bk = tid >> 5;
    const int bn = (tid & 31) << 2;
    const float* Abase = A + (size_t)(by * 128 + am) * K + ak;
    const float* Bbase = B + (size_t)bk * N + bx * 128 + bn;

    const int kt = K >> 4;

    #pragma unroll
    for (int s = 0; s < GSTAGES - 1; s++) {
        const float* Ag = Abase + s * 16;
        const float* Bg = Bbase + (size_t)(s * 16) * N;
        cpasync16(As + s * AS_STRIDE + am * 20 + ak,        Ag);
        cpasync16(As + s * AS_STRIDE + (am + 64) * 20 + ak, Ag + (size_t)64 * K);
        cpasync16(Bs + s * BS_STRIDE + bk * 132 + bn,       Bg);
        cpasync16(Bs + s * BS_STRIDE + (bk + 8) * 132 + bn, Bg + (size_t)8 * N);
        CP_COMMIT();
    }

    float acc[4][4][4];
    #pragma unroll
    for (int mt = 0; mt < 4; mt++)
        #pragma unroll
        for (int nt = 0; nt < 4; nt++)
            #pragma unroll
            for (int r = 0; r < 4; r++) acc[mt][nt][r] = 0.0f;

    for (int it = 0; it < kt; it++) {
        CP_WAIT(GSTAGES - 2);
        __syncthreads();

        int nx = it + GSTAGES - 1;
        if (nx < kt) {
            int s = nx & (GSTAGES - 1);
            const float* Ag = Abase + nx * 16;
            const float* Bg = Bbase + (size_t)(nx * 16) * N;
            cpasync16(As + s * AS_STRIDE + am * 20 + ak,        Ag);
            cpasync16(As + s * AS_STRIDE + (am + 64) * 20 + ak, Ag + (size_t)64 * K);
            cpasync16(Bs + s * BS_STRIDE + bk * 132 + bn,       Bg);
            cpasync16(Bs + s * BS_STRIDE + (bk + 8) * 132 + bn, Bg + (size_t)8 * N);
        }
        CP_COMMIT();

        const int cb = it & (GSTAGES - 1);
        const float* Asc = As + cb * AS_STRIDE;
        const float* Bsc = Bs + cb * BS_STRIDE;

        #pragma unroll
        for (int kb = 0; kb < 2; kb++) {
            unsigned af[4][4];
            #pragma unroll
            for (int mt = 0; mt < 4; mt++) {
                unsigned addr = (unsigned)__cvta_generic_to_shared(
                    Asc + (wm + mt * 16 + lrow) * 20 + kb * 8 + lkoff);
                ldmx4(af[mt][0], af[mt][1], af[mt][2], af[mt][3], addr);
            }
            unsigned bf[4][2];
            #pragma unroll
            for (int nt = 0; nt < 4; nt++) {
                int n = wn + nt * 8 + lr;
                bf[nt][0] = __float_as_uint(Bsc[(kb * 8 + lc) * 132 + n]);
                bf[nt][1] = __float_as_uint(Bsc[(kb * 8 + lc + 4) * 132 + n]);
            }
            #pragma unroll
            for (int mt = 0; mt < 4; mt++)
                #pragma unroll
                for (int nt = 0; nt < 4; nt++)
                    mma_tf32(acc[mt][nt], af[mt], bf[nt][0], bf[nt][1]);
        }
    }

    #pragma unroll
    for (int mt = 0; mt < 4; mt++) {
        #pragma unroll
        for (int nt = 0; nt < 4; nt++) {
            int row = by * 128 + wm + mt * 16 + lr;
            int col = bx * 128 + wn + nt * 8 + 2 * lc;
            #pragma unroll
            for (int half = 0; half < 2; half++) {
                int r = row + half * 8;
                size_t off = (size_t)r * N + col;
                float v0 = acc[mt][nt][half * 2 + 0];
                float v1 = acc[mt][nt][half * 2 + 1];
                if (EPI == 2 || EPI == 3) { v0 += bias[col]; v1 += bias[col + 1]; }
                if (EPI == 2) { v0 = gelu_tanh(v0); v1 = gelu_tanh(v1); }
                if (EPI == 1 || EPI == 3) { v0 += resid[off]; v1 += resid[off + 1]; }
                *(float2*)(C + off) = make_float2(v0, v1);
            }
        }
    }
}

template<int EPI>
__global__ __launch_bounds__(256)
void tgemm_kernel(const float* __restrict__ A, const float* __restrict__ B,
                  float* __restrict__ C, const float* __restrict__ bias,
                  const float* __restrict__ resid, int N, int K)
{
    extern __shared__ float smg[];
    gemm_core<EPI>(A, B, C, bias, resid, N, K, blockIdx.x, blockIdx.y, smg);
}

// merged q/k/v projection: blockIdx.z selects operand set
__global__ __launch_bounds__(256)
void qkv_kernel(const float* __restrict__ y, const float* __restrict__ xn,
                const float* __restrict__ w_q, const float* __restrict__ w_k,
                const float* __restrict__ w_v,
                float* __restrict__ q, float* __restrict__ k, float* __restrict__ v)
{
    extern __shared__ float smg[];
    int z = blockIdx.z;
    const float* A = (z == 2) ? xn : y;
    const float* B = (z == 0) ? w_q : (z == 1) ? w_k : w_v;
    float*       C = (z == 0) ? q   : (z == 1) ? k   : v;
    gemm_core<0>(A, B, C, nullptr, nullptr, 1024, 1024, blockIdx.x, blockIdx.y, smg);
}

// ---------------- tf32 mma flash attention, BM=128, BN=64 ----------------
#define AT_QS 0
#define AT_KS (128*68)
#define AT_VS (192*68)
#define AT_PS (256*68)
#define ATTN_SMEM_BYTES (384*68*4)

__global__ __launch_bounds__(256, 1)
void attn_kernel(const float* __restrict__ Q, const float* __restrict__ Kk,
                 const float* __restrict__ V, float* __restrict__ O)
{
    extern __shared__ float sm[];

    const int qt = blockIdx.x;
    const int bh = blockIdx.y;
    const int b = bh >> 4, h = bh & 15;
    const size_t ld = DD;
    const float* Qb = Q  + (size_t)b * TT * ld + h * 64;
    const float* Kb = Kk + (size_t)b * TT * ld + h * 64;
    const float* Vb = V  + (size_t)b * TT * ld + h * 64;
    float*       Ob = O  + (size_t)b * TT * ld + h * 64;

    const int tid  = threadIdx.x;
    const int lane = tid & 31;
    const int warp = tid >> 5;
    const int lr = lane >> 2;
    const int lc = lane & 3;
    const int lrow  = (lane & 7) + (lane & 8);
    const int lkoff = (lane >> 4) * 4;

    for (int i = tid; i < 128 * 16; i += 256) {
        int r = i >> 4, c4 = (i & 15) << 2;
        float4 qv = *(const float4*)(Qb + (size_t)(qt * 128 + r) * ld + c4);
        float4 o4 = make_float4(f2tf32f(qv.x * 0.125f), f2tf32f(qv.y * 0.125f),
                                f2tf32f(qv.z * 0.125f), f2tf32f(qv.w * 0.125f));
        *(float4*)&sm[AT_QS + r * 68 + c4] = o4;
    }

    float m_i[2] = {-1e30f, -1e30f};
    float l_i[2] = {0.0f, 0.0f};
    float o[8][4];
    #pragma unroll
    for (int nt = 0; nt < 8; nt++)
        #pragma unroll
        for (int r = 0; r < 4; r++) o[nt][r] = 0.0f;

    const int row_min = qt * 128 + warp * 16;
    const int nkt = 2 * qt + 2;

    for (int kt = 0; kt < nkt; kt++) {
        __syncthreads();
        for (int i = tid; i < 64 * 16; i += 256) {
            int r = i >> 4, c4 = (i & 15) << 2;
            float4 kv = *(const float4*)(Kb + (size_t)(kt * 64 + r) * ld + c4);
            float4 o4 = make_float4(f2tf32f(kv.x), f2tf32f(kv.y), f2tf32f(kv.z), f2tf32f(kv.w));
            *(float4*)&sm[AT_KS + r * 68 + c4] = o4;
        }
        for (int i = tid; i < 64 * 16; i += 256) {
            int r = i & 63;
            int d4 = (i >> 6) << 2;
            float4 vv = *(const float4*)(Vb + (size_t)(kt * 64 + r) * ld + d4);
            sm[AT_VS + (d4 + 0) * 68 + r] = f2tf32f(vv.x);
            sm[AT_VS + (d4 + 1) * 68 + r] = f2tf32f(vv.y);
            sm[AT_VS + (d4 + 2) * 68 + r] = f2tf32f(vv.z);
            sm[AT_VS + (d4 + 3) * 68 + r] = f2tf32f(vv.w);
        }
        __syncthreads();

        if (kt * 64 <= row_min + 15) {
            float s[8][4];
            #pragma unroll
            for (int nt = 0; nt < 8; nt++)
                #pragma unroll
                for (int r = 0; r < 4; r++) s[nt][r] = 0.0f;

            #pragma unroll
            for (int kb = 0; kb < 8; kb++) {
                unsigned af[4];
                unsigned qaddr = (unsigned)__cvta_generic_to_shared(
                    &sm[AT_QS + (warp * 16 + lrow) * 68 + kb * 8 + lkoff]);
                ldmx4(af[0], af[1], af[2], af[3], qaddr);
                #pragma unroll
                for (int nt = 0; nt < 8; nt++) {
                    unsigned b0, b1;
                    unsigned kaddr = (unsigned)__cvta_generic_to_shared(
                        &sm[AT_KS + (nt * 8 + (lane & 7)) * 68 + kb * 8 + ((lane >> 3) & 1) * 4]);
                    ldmx2(b0, b1, kaddr);
                    mma_tf32(s[nt], af, b0, b1);
                }
            }

            if (kt * 64 + 63 > row_min) {
                #pragma unroll
                for (int nt = 0; nt < 8; nt++)
                    #pragma unroll
                    for (int r = 0; r < 4; r++) {
                        int col = kt * 64 + nt * 8 + 2 * lc + (r & 1);
                        int row = row_min + lr + 8 * (r >> 1);
                        if (col > row) s[nt][r] = -1e30f;
                    }
            }

            #pragma unroll
            for (int h2 = 0; h2 < 2; h2++) {
                float rm = -1e30f;
                #pragma unroll
                for (int nt = 0; nt < 8; nt++)
                    rm = fmaxf(rm, fmaxf(s[nt][2*h2], s[nt][2*h2+1]));
                rm = fmaxf(rm, __shfl_xor_sync(0xffffffffu, rm, 1));
                rm = fmaxf(rm, __shfl_xor_sync(0xffffffffu, rm, 2));
                float mn = fmaxf(m_i[h2], rm);
                float alpha = __expf(m_i[h2] - mn);
                m_i[h2] = mn;
                float rs = 0.0f;
                #pragma unroll
                for (int nt = 0; nt < 8; nt++) {
                    float p0 = __expf(s[nt][2*h2]   - mn);
                    float p1 = __expf(s[nt][2*h2+1] - mn);
                    s[nt][2*h2]   = p0;
                    s[nt][2*h2+1] = p1;
                    rs += p0 + p1;
                }
                rs += __shfl_xor_sync(0xffffffffu, rs, 1);
                rs += __shfl_xor_sync(0xffffffffu, rs, 2);
                l_i[h2] = l_i[h2] * alpha + rs;
                #pragma unroll
                for (int nt = 0; nt < 8; nt++) {
                    o[nt][2*h2]   *= alpha;
                    o[nt][2*h2+1] *= alpha;
                }
            }

            #pragma unroll
            for (int nt = 0; nt < 8; nt++)
                #pragma unroll
                for (int r = 0; r < 4; r++) {
                    int row = warp * 16 + lr + 8 * (r >> 1);
                    int col = nt * 8 + 2 * lc + (r & 1);
                    sm[AT_PS + row * 68 + col] = f2tf32f(s[nt][r]);
                }
            __syncwarp();

            #pragma unroll
            for (int kb = 0; kb < 8; kb++) {
                unsigned af[4];
                unsigned paddr = (unsigned)__cvta_generic_to_shared(
                    &sm[AT_PS + (warp * 16 + lrow) * 68 + kb * 8 + lkoff]);
                ldmx4(af[0], af[1], af[2], af[3], paddr);
                #pragma unroll
                for (int nt = 0; nt < 8; nt++) {
                    unsigned b0, b1;
                    unsigned vaddr = (unsigned)__cvta_generic_to_shared(
                        &sm[AT_VS + (nt * 8 + (lane & 7)) * 68 + kb * 8 + ((lane >> 3) & 1) * 4]);
                    ldmx2(b0, b1, vaddr);
                    mma_tf32(o[nt], af, b0, b1);
                }
            }
        }
    }

    #pragma unroll
    for (int h2 = 0; h2 < 2; h2++) {
        float inv = 1.0f / l_i[h2];
        int row = qt * 128 + warp * 16 + lr + 8 * h2;
        #pragma unroll
        for (int nt = 0; nt < 8; nt++) {
            int col = nt * 8 + 2 * lc;
            *(float2*)(Ob + (size_t)row * ld + col) =
                make_float2(o[nt][2*h2] * inv, o[nt][2*h2+1] * inv);
        }
    }
}

// ---------------- launch ----------------
extern "C" void kernel_launch(void* const* d_in, const int* in_sizes, int n_in,
                              void* d_out, int out_size)
{
    const float* x       = (const float*)d_in[0];
    const float* w_q     = (const float*)d_in[1];
    const float* w_k     = (const float*)d_in[2];
    const float* w_v     = (const float*)d_in[3];
    const float* w_o     = (const float*)d_in[4];
    const float* alpha_p = (const float*)d_in[5];
    const float* delta_p = (const float*)d_in[6];
    const float* beta    = (const float*)d_in[7];
    const float* eta     = (const float*)d_in[8];
    const float* g1      = (const float*)d_in[9];
    const float* g2      = (const float*)d_in[10];
    const float* w_in    = (const float*)d_in[11];
    const float* b_in    = (const float*)d_in[12];
    const float* w_out   = (const float*)d_in[13];
    const float* b_out   = (const float*)d_in[14];
    float* out = (float*)d_out;

    float *xn, *y, *q, *k, *v, *ao, *x1, *xn2, *hb;
    cudaGetSymbolAddress((void**)&xn,  g_xn);
    cudaGetSymbolAddress((void**)&y,   g_y);
    cudaGetSymbolAddress((void**)&q,   g_q);
    cudaGetSymbolAddress((void**)&k,   g_k);
    cudaGetSymbolAddress((void**)&v,   g_v);
    cudaGetSymbolAddress((void**)&ao,  g_ao);
    cudaGetSymbolAddress((void**)&x1,  g_x1);
    cudaGetSymbolAddress((void**)&xn2, g_xn2);
    cudaGetSymbolAddress((void**)&hb,  g_hb);

    cudaFuncSetAttribute(attn_kernel, cudaFuncAttributeMaxDynamicSharedMemorySize,
                         ATTN_SMEM_BYTES);
    cudaFuncSetAttribute(qkv_kernel, cudaFuncAttributeMaxDynamicSharedMemorySize, SMEM_GEMM);
    cudaFuncSetAttribute(tgemm_kernel<1>, cudaFuncAttributeMaxDynamicSharedMemorySize, SMEM_GEMM);
    cudaFuncSetAttribute(tgemm_kernel<2>, cudaFuncAttributeMaxDynamicSharedMemorySize, SMEM_GEMM);
    cudaFuncSetAttribute(tgemm_kernel<3>, cudaFuncAttributeMaxDynamicSharedMemorySize, SMEM_GEMM);

    rmsnorm_kernel<<<BT, 256>>>(x, g1, xn);
    ema_kernel<<<(BB * DD * 16) / 256, 256>>>(xn, alpha_p, delta_p, beta, eta, y);

    qkv_kernel<<<dim3(1024 / 128, BT / 128, 3), 256, SMEM_GEMM>>>(y, xn, w_q, w_k, w_v, q, k, v);

    rope_kernel<<<(BB * TT * HH * 16) / 256, 256>>>(q, k, v);

    attn_kernel<<<dim3(TT / 128, BB * HH), 256, ATTN_SMEM_BYTES>>>(q, k, v, ao);

    dim3 gN1024(1024 / 128, BT / 128);
    tgemm_kernel<1><<<gN1024, 256, SMEM_GEMM>>>(ao, w_o, x1, nullptr, x, 1024, 1024);

    rmsnorm_kernel<<<BT, 256>>>(x1, g2, xn2);

    dim3 gN4096(4096 / 128, BT / 128);
    tgemm_kernel<2><<<gN4096, 256, SMEM_GEMM>>>(xn2, w_in, hb, b_in, nullptr, 4096, 1024);
    tgemm_kernel<3><<<gN1024, 256, SMEM_GEMM>>>(hb, w_out, out, b_out, x1, 1024, 4096);
}

// round 7
// speedup vs baseline: 1.0142x; 1.0142x over previous
#include <cuda_runtime.h>
#include <math.h>

#define BB 2
#define TT 2048
#define DD 1024
#define HH 16
#define HIDD 4096
#define BT (BB*TT)   // 4096 rows

// ---------------- scratch ----------------
__device__ float g_xn [BB*TT*DD];
__device__ float g_y  [BB*TT*DD];
__device__ float g_q  [BB*TT*DD];
__device__ float g_k  [BB*TT*DD];
__device__ float g_v  [BB*TT*DD];
__device__ float g_ao [BB*TT*DD];
__device__ float g_x1 [BB*TT*DD];
__device__ float g_xn2[BB*TT*DD];
__device__ float g_hb [BB*TT*HIDD];
__device__ float g_w  [12*1024*1024];   // rounded weights: wq|wk|wv|wo|win|wout

// ---------------- helpers ----------------
__device__ __forceinline__ unsigned f2tf32(float x)
{
    unsigned r;
    asm("cvt.rna.tf32.f32 %0, %1;" : "=r"(r) : "f"(x));
    return r;
}
__device__ __forceinline__ float f2tf32f(float x) { return __uint_as_float(f2tf32(x)); }
__device__ __forceinline__ float4 cvt4(float4 v)
{
    return make_float4(f2tf32f(v.x), f2tf32f(v.y), f2tf32f(v.z), f2tf32f(v.w));
}

__device__ __forceinline__ void ldmx4(unsigned& a0, unsigned& a1, unsigned& a2, unsigned& a3,
                                      unsigned addr)
{
    asm volatile("ldmatrix.sync.aligned.m8n8.x4.shared.b16 {%0,%1,%2,%3}, [%4];"
                 : "=r"(a0), "=r"(a1), "=r"(a2), "=r"(a3) : "r"(addr));
}
__device__ __forceinline__ void ldmx2(unsigned& a0, unsigned& a1, unsigned addr)
{
    asm volatile("ldmatrix.sync.aligned.m8n8.x2.shared.b16 {%0,%1}, [%2];"
                 : "=r"(a0), "=r"(a1) : "r"(addr));
}
__device__ __forceinline__ void mma_tf32(float* d, const unsigned* a, unsigned b0, unsigned b1)
{
    asm volatile(
        "mma.sync.aligned.m16n8k8.row.col.f32.tf32.tf32.f32 "
        "{%0,%1,%2,%3}, {%4,%5,%6,%7}, {%8,%9}, {%0,%1,%2,%3};\n"
        : "+f"(d[0]), "+f"(d[1]), "+f"(d[2]), "+f"(d[3])
        : "r"(a[0]), "r"(a[1]), "r"(a[2]), "r"(a[3]), "r"(b0), "r"(b1));
}
__device__ __forceinline__ void cpasync16(void* smem, const void* gmem)
{
    unsigned s = (unsigned)__cvta_generic_to_shared(smem);
    asm volatile("cp.async.cg.shared.global [%0], [%1], 16;" :: "r"(s), "l"(gmem));
}
#define CP_COMMIT() asm volatile("cp.async.commit_group;")
#define CP_WAIT(n)  asm volatile("cp.async.wait_group %0;" :: "n"(n))

// ---------------- weight pre-round (tf32 rna) ----------------
__global__ void wround_kernel(const float* __restrict__ wq, const float* __restrict__ wk,
                              const float* __restrict__ wv, const float* __restrict__ wo,
                              const float* __restrict__ win, const float* __restrict__ wout,
                              float* __restrict__ dst)
{
    int i = blockIdx.x * blockDim.x + threadIdx.x;   // float4 index, 3M total
    const int M1 = 1024 * 1024 / 4;
    const float* src; int off;
    if      (i <     M1) { src = wq;   off = i;          }
    else if (i < 2 * M1) { src = wk;   off = i -     M1; }
    else if (i < 3 * M1) { src = wv;   off = i - 2 * M1; }
    else if (i < 4 * M1) { src = wo;   off = i - 3 * M1; }
    else if (i < 8 * M1) { src = win;  off = i - 4 * M1; }
    else                 { src = wout; off = i - 8 * M1; }
    float4 v = ((const float4*)src)[off];
    ((float4*)dst)[i] = cvt4(v);
}

// ---------------- rmsnorm (rounded output when rnd=1) ----------------
__global__ void rmsnorm_kernel(const float* __restrict__ x, const float* __restrict__ g,
                               float* __restrict__ out, int rnd)
{
    int row = blockIdx.x;
    int tid = threadIdx.x;
    const float4* xr = (const float4*)(x + (size_t)row * DD);
    float4 v = xr[tid];
    float s = v.x*v.x + v.y*v.y + v.z*v.z + v.w*v.w;
    #pragma unroll
    for (int o = 16; o; o >>= 1) s += __shfl_xor_sync(0xffffffffu, s, o);
    __shared__ float red[8];
    if ((tid & 31) == 0) red[tid >> 5] = s;
    __syncthreads();
    float tot = red[0]+red[1]+red[2]+red[3]+red[4]+red[5]+red[6]+red[7];
    float inv = rsqrtf(tot * (1.0f / (float)DD) + 1e-6f);
    const float4* gr = (const float4*)g;
    float4 gv = gr[tid];
    float4 o4;
    o4.x = gv.x * (v.x * inv);
    o4.y = gv.y * (v.y * inv);
    o4.z = gv.z * (v.z * inv);
    o4.w = gv.w * (v.w * inv);
    if (rnd) o4 = cvt4(o4);
    ((float4*)(out + (size_t)row * DD))[tid] = o4;
}

// ---------------- EMA scan (rounded output) ----------------
__global__ void ema_kernel(const float* __restrict__ xn,
                           const float* __restrict__ ap, const float* __restrict__ dp,
                           const float* __restrict__ beta, const float* __restrict__ eta,
                           float* __restrict__ y)
{
    int idx = blockIdx.x * blockDim.x + threadIdx.x;
    int n = idx & 15;
    int d = (idx >> 4) & (DD - 1);
    int b = idx >> 14;
    int dn = d * 16 + n;
    float a   = 1.0f / (1.0f + expf(-ap[dn]));
    float ddv = 1.0f / (1.0f + expf(-dp[dn]));
    float dec = 1.0f - a * ddv;
    float ab  = a * beta[dn];
    float et  = eta[dn];
    const float* xp = xn + (size_t)b * TT * DD + d;
    float* yp       = y  + (size_t)b * TT * DD + d;
    float h = 0.0f;
    for (int t = 0; t < TT; t++) {
        float u = xp[(size_t)t * DD];
        h = fmaf(dec, h, ab * u);
        float s = et * h;
        s += __shfl_xor_sync(0xffffffffu, s, 8, 16);
        s += __shfl_xor_sync(0xffffffffu, s, 4, 16);
        s += __shfl_xor_sync(0xffffffffu, s, 2, 16);
        s += __shfl_xor_sync(0xffffffffu, s, 1, 16);
        if (n == 0) yp[(size_t)t * DD] = f2tf32f(s);
    }
}

// ---------------- RoPE (rounded output) ----------------
__global__ void rope_kernel(float* __restrict__ q, float* __restrict__ k, float* __restrict__ v)
{
    int idx = blockIdx.x * blockDim.x + threadIdx.x;
    int i = idx & 15;
    int h = (idx >> 4) & 15;
    int t = (idx >> 8) & (TT - 1);
    int b = idx >> 19;
    double fd = pow(10000.0, -(double)i / 16.0);
    float freq = (float)fd;
    float ang = (float)t * freq;
    double da = (double)ang;
    float c = (float)cos(da);
    float s = (float)sin(da);
    size_t base = ((size_t)(b * TT + t)) * DD + h * 64;
    {
        float x1 = q[base + i], x2 = q[base + 16 + i];
        q[base + i]      = f2tf32f(x1 * c - x2 * s);
        q[base + 16 + i] = f2tf32f(x2 * c + x1 * s);
    }
    {
        float x1 = k[base + i], x2 = k[base + 16 + i];
        k[base + i]      = f2tf32f(x1 * c - x2 * s);
        k[base + 16 + i] = f2tf32f(x2 * c + x1 * s);
    }
    {
        float x1 = v[base + i], x2 = v[base + 16 + i];
        v[base + i]      = f2tf32f(x1 * c - x2 * s);
        v[base + 16 + i] = f2tf32f(x2 * c + x1 * s);
    }
}

// ---------------- tf32 GEMM core: 128x128x16, cp.async 3-stage ----------------
__device__ __forceinline__ float gelu_tanh(float x)
{
    float x3 = x * x * x;
    float t = tanhf(0.7978845608028654f * (x + 0.044715f * x3));
    return 0.5f * x * (1.0f + t);
}

#define GSTAGES 3
#define AS_STRIDE (128*20)
#define BS_STRIDE (16*132)
#define SMEM_GEMM ((GSTAGES * (AS_STRIDE + BS_STRIDE)) * 4)

// EPI: 0 = none, 1 = +resid, 2 = gelu(acc+bias), 3 = acc+bias+resid
// RND: round output to tf32 (it feeds a later GEMM/attn as an operand)
template<int EPI, bool RND>
__device__ __forceinline__ void gemm_core(const float* __restrict__ A,
                                          const float* __restrict__ B,
                                          float* __restrict__ C,
                                          const float* __restrict__ bias,
                                          const float* __restrict__ resid,
                                          int N, int K, int bx, int by, float* sm)
{
    float* As = sm;                          // [GSTAGES][128][20]
    float* Bs = sm + GSTAGES * AS_STRIDE;    // [GSTAGES][16][132]

    const int tid  = threadIdx.x;
    const int lane = tid & 31;
    const int warp = tid >> 5;
    const int wm = (warp & 1) * 64;
    const int wn = (warp >> 1) * 32;
    const int lr = lane >> 2;
    const int lc = lane & 3;
    const int lrow  = (lane & 7) + (lane & 8);
    const int lkoff = (lane >> 4) * 4;

    const int am = tid >> 2;
    const int ak = (tid & 3) << 2;
    const int bk = tid >> 5;
    const int bn = (tid & 31) << 2;
    const float* Abase = A + (size_t)(by * 128 + am) * K + ak;
    const float* Bbase = B + (size_t)bk * N + bx * 128 + bn;

    const int kt = K >> 4;

    #pragma unroll
    for (int s = 0; s < GSTAGES - 1; s++) {
        const float* Ag = Abase + s * 16;
        const float* Bg = Bbase + (size_t)(s * 16) * N;
        cpasync16(As + s * AS_STRIDE + am * 20 + ak,        Ag);
        cpasync16(As + s * AS_STRIDE + (am + 64) * 20 + ak, Ag + (size_t)64 * K);
        cpasync16(Bs + s * BS_STRIDE + bk * 132 + bn,       Bg);
        cpasync16(Bs + s * BS_STRIDE + (bk + 8) * 132 + bn, Bg + (size_t)8 * N);
        CP_COMMIT();
    }

    float acc[4][4][4];
    #pragma unroll
    for (int mt = 0; mt < 4; mt++)
        #pragma unroll
        for (int nt = 0; nt < 4; nt++)
            #pragma unroll
            for (int r = 0; r < 4; r++) acc[mt][nt][r] = 0.0f;

    int cb = 0, pb = GSTAGES - 1;   // consume-stage, prefetch-stage ring counters
    for (int it = 0; it < kt; it++) {
        CP_WAIT(GSTAGES - 2);
        __syncthreads();

        int nx = it + GSTAGES - 1;
        if (nx < kt) {
            const float* Ag = Abase + nx * 16;
            const float* Bg = Bbase + (size_t)(nx * 16) * N;
            cpasync16(As + pb * AS_STRIDE + am * 20 + ak,        Ag);
            cpasync16(As + pb * AS_STRIDE + (am + 64) * 20 + ak, Ag + (size_t)64 * K);
            cpasync16(Bs + pb * BS_STRIDE + bk * 132 + bn,       Bg);
            cpasync16(Bs + pb * BS_STRIDE + (bk + 8) * 132 + bn, Bg + (size_t)8 * N);
        }
        CP_COMMIT();
        if (++pb == GSTAGES) pb = 0;

        const float* Asc = As + cb * AS_STRIDE;
        const float* Bsc = Bs + cb * BS_STRIDE;
        if (++cb == GSTAGES) cb = 0;

        #pragma unroll
        for (int kb = 0; kb < 2; kb++) {
            unsigned af[4][4];
            #pragma unroll
            for (int mt = 0; mt < 4; mt++) {
                unsigned addr = (unsigned)__cvta_generic_to_shared(
                    Asc + (wm + mt * 16 + lrow) * 20 + kb * 8 + lkoff);
                ldmx4(af[mt][0], af[mt][1], af[mt][2], af[mt][3], addr);
            }
            unsigned bf[4][2];
            #pragma unroll
            for (int nt = 0; nt < 4; nt++) {
                int n = wn + nt * 8 + lr;
                bf[nt][0] = __float_as_uint(Bsc[(kb * 8 + lc) * 132 + n]);
                bf[nt][1] = __float_as_uint(Bsc[(kb * 8 + lc + 4) * 132 + n]);
            }
            #pragma unroll
            for (int mt = 0; mt < 4; mt++)
                #pragma unroll
                for (int nt = 0; nt < 4; nt++)
                    mma_tf32(acc[mt][nt], af[mt], bf[nt][0], bf[nt][1]);
        }
    }

    #pragma unroll
    for (int mt = 0; mt < 4; mt++) {
        #pragma unroll
        for (int nt = 0; nt < 4; nt++) {
            int row = by * 128 + wm + mt * 16 + lr;
            int col = bx * 128 + wn + nt * 8 + 2 * lc;
            #pragma unroll
            for (int half = 0; half < 2; half++) {
                int r = row + half * 8;
                size_t off = (size_t)r * N + col;
                float v0 = acc[mt][nt][half * 2 + 0];
                float v1 = acc[mt][nt][half * 2 + 1];
                if (EPI == 2 || EPI == 3) { v0 += bias[col]; v1 += bias[col + 1]; }
                if (EPI == 2) { v0 = gelu_tanh(v0); v1 = gelu_tanh(v1); }
                if (EPI == 1 || EPI == 3) { v0 += resid[off]; v1 += resid[off + 1]; }
                if (RND) { v0 = f2tf32f(v0); v1 = f2tf32f(v1); }
                *(float2*)(C + off) = make_float2(v0, v1);
            }
        }
    }
}

template<int EPI, bool RND>
__global__ __launch_bounds__(256, 2)
void tgemm_kernel(const float* __restrict__ A, const float* __restrict__ B,
                  float* __restrict__ C, const float* __restrict__ bias,
                  const float* __restrict__ resid, int N, int K)
{
    extern __shared__ float smg[];
    gemm_core<EPI, RND>(A, B, C, bias, resid, N, K, blockIdx.x, blockIdx.y, smg);
}

// merged q/k/v projection: blockIdx.z selects operand set
__global__ __launch_bounds__(256, 2)
void qkv_kernel(const float* __restrict__ y, const float* __restrict__ xn,
                const float* __restrict__ wr,
                float* __restrict__ q, float* __restrict__ k, float* __restrict__ v)
{
    extern __shared__ float smg[];
    int z = blockIdx.z;
    const float* A = (z == 2) ? xn : y;
    const float* B = wr + (size_t)z * 1024 * 1024;
    float*       C = (z == 0) ? q : (z == 1) ? k : v;
    gemm_core<0, true>(A, B, C, nullptr, nullptr, 1024, 1024, blockIdx.x, blockIdx.y, smg);
}

// ---------------- tf32 mma flash attention, BM=128, BN=64 ----------------
#define AT_QS 0
#define AT_KS (128*68)
#define AT_VS (192*68)
#define AT_PS (256*68)
#define ATTN_SMEM_BYTES (384*68*4)

__global__ __launch_bounds__(256, 2)
void attn_kernel(const float* __restrict__ Q, const float* __restrict__ Kk,
                 const float* __restrict__ V, float* __restrict__ O)
{
    extern __shared__ float sm[];

    const int qt = blockIdx.x;
    const int bh = blockIdx.y;
    const int b = bh >> 4, h = bh & 15;
    const size_t ld = DD;
    const float* Qb = Q  + (size_t)b * TT * ld + h * 64;
    const float* Kb = Kk + (size_t)b * TT * ld + h * 64;
    const float* Vb = V  + (size_t)b * TT * ld + h * 64;
    float*       Ob = O  + (size_t)b * TT * ld + h * 64;

    const int tid  = threadIdx.x;
    const int lane = tid & 31;
    const int warp = tid >> 5;
    const int lr = lane >> 2;
    const int lc = lane & 3;
    const int lrow  = (lane & 7) + (lane & 8);
    const int lkoff = (lane >> 4) * 4;

    // Q pre-rounded by producers; *0.125f is exact (power of 2)
    for (int i = tid; i < 128 * 16; i += 256) {
        int r = i >> 4, c4 = (i & 15) << 2;
        float4 qv = *(const float4*)(Qb + (size_t)(qt * 128 + r) * ld + c4);
        qv.x *= 0.125f; qv.y *= 0.125f; qv.z *= 0.125f; qv.w *= 0.125f;
        *(float4*)&sm[AT_QS + r * 68 + c4] = qv;
    }

    float m_i[2] = {-1e30f, -1e30f};
    float l_i[2] = {0.0f, 0.0f};
    float o[8][4];
    #pragma unroll
    for (int nt = 0; nt < 8; nt++)
        #pragma unroll
        for (int r = 0; r < 4; r++) o[nt][r] = 0.0f;

    const int row_min = qt * 128 + warp * 16;
    const int nkt = 2 * qt + 2;

    for (int kt = 0; kt < nkt; kt++) {
        __syncthreads();
        for (int i = tid; i < 64 * 16; i += 256) {
            int r = i >> 4, c4 = (i & 15) << 2;
            float4 kv = *(const float4*)(Kb + (size_t)(kt * 64 + r) * ld + c4);
            *(float4*)&sm[AT_KS + r * 68 + c4] = kv;
        }
        for (int i = tid; i < 64 * 16; i += 256) {
            int r = i & 63;
            int d4 = (i >> 6) << 2;
            float4 vv = *(const float4*)(Vb + (size_t)(kt * 64 + r) * ld + d4);
            sm[AT_VS + (d4 + 0) * 68 + r] = vv.x;
            sm[AT_VS + (d4 + 1) * 68 + r] = vv.y;
            sm[AT_VS + (d4 + 2) * 68 + r] = vv.z;
            sm[AT_VS + (d4 + 3) * 68 + r] = vv.w;
        }
        __syncthreads();

        if (kt * 64 <= row_min + 15) {
            float s[8][4];
            #pragma unroll
            for (int nt = 0; nt < 8; nt++)
                #pragma unroll
                for (int r = 0; r < 4; r++) s[nt][r] = 0.0f;

            #pragma unroll
            for (int kb = 0; kb < 8; kb++) {
                unsigned af[4];
                unsigned qaddr = (unsigned)__cvta_generic_to_shared(
                    &sm[AT_QS + (warp * 16 + lrow) * 68 + kb * 8 + lkoff]);
                ldmx4(af[0], af[1], af[2], af[3], qaddr);
                #pragma unroll
                for (int nt = 0; nt < 8; nt++) {
                    unsigned b0, b1;
                    unsigned kaddr = (unsigned)__cvta_generic_to_shared(
                        &sm[AT_KS + (nt * 8 + (lane & 7)) * 68 + kb * 8 + ((lane >> 3) & 1) * 4]);
                    ldmx2(b0, b1, kaddr);
                    mma_tf32(s[nt], af, b0, b1);
                }
            }

            if (kt * 64 + 63 > row_min) {
                #pragma unroll
                for (int nt = 0; nt < 8; nt++)
                    #pragma unroll
                    for (int r = 0; r < 4; r++) {
                        int col = kt * 64 + nt * 8 + 2 * lc + (r & 1);
                        int row = row_min + lr + 8 * (r >> 1);
                        if (col > row) s[nt][r] = -1e30f;
                    }
            }

            #pragma unroll
            for (int h2 = 0; h2 < 2; h2++) {
                float rm = -1e30f;
                #pragma unroll
                for (int nt = 0; nt < 8; nt++)
                    rm = fmaxf(rm, fmaxf(s[nt][2*h2], s[nt][2*h2+1]));
                rm = fmaxf(rm, __shfl_xor_sync(0xffffffffu, rm, 1));
                rm = fmaxf(rm, __shfl_xor_sync(0xffffffffu, rm, 2));
                float mn = fmaxf(m_i[h2], rm);
                float alpha = __expf(m_i[h2] - mn);
                m_i[h2] = mn;
                float rs = 0.0f;
                #pragma unroll
                for (int nt = 0; nt < 8; nt++) {
                    float p0 = __expf(s[nt][2*h2]   - mn);
                    float p1 = __expf(s[nt][2*h2+1] - mn);
                    s[nt][2*h2]   = p0;
                    s[nt][2*h2+1] = p1;
                    rs += p0 + p1;
                }
                rs += __shfl_xor_sync(0xffffffffu, rs, 1);
                rs += __shfl_xor_sync(0xffffffffu, rs, 2);
                l_i[h2] = l_i[h2] * alpha + rs;
                #pragma unroll
                for (int nt = 0; nt < 8; nt++) {
                    o[nt][2*h2]   *= alpha;
                    o[nt][2*h2+1] *= alpha;
                }
            }

            #pragma unroll
            for (int nt = 0; nt < 8; nt++)
                #pragma unroll
                for (int r = 0; r < 4; r++) {
                    int row = warp * 16 + lr + 8 * (r >> 1);
                    int col = nt * 8 + 2 * lc + (r & 1);
                    sm[AT_PS + row * 68 + col] = f2tf32f(s[nt][r]);
                }
            __syncwarp();

            #pragma unroll
            for (int kb = 0; kb < 8; kb++) {
                unsigned af[4];
                unsigned paddr = (unsigned)__cvta_generic_to_shared(
                    &sm[AT_PS + (warp * 16 + lrow) * 68 + kb * 8 + lkoff]);
                ldmx4(af[0], af[1], af[2], af[3], paddr);
                #pragma unroll
                for (int nt = 0; nt < 8; nt++) {
                    unsigned b0, b1;
                    unsigned vaddr = (unsigned)__cvta_generic_to_shared(
                        &sm[AT_VS + (nt * 8 + (lane & 7)) * 68 + kb * 8 + ((lane >> 3) & 1) * 4]);
                    ldmx2(b0, b1, vaddr);
                    mma_tf32(o[nt], af, b0, b1);
                }
            }
        }
    }

    // output feeds w_o GEMM as A operand -> write tf32-rounded
    #pragma unroll
    for (int h2 = 0; h2 < 2; h2++) {
        float inv = 1.0f / l_i[h2];
        int row = qt * 128 + warp * 16 + lr + 8 * h2;
        #pragma unroll
        for (int nt = 0; nt < 8; nt++) {
            int col = nt * 8 + 2 * lc;
            *(float2*)(Ob + (size_t)row * ld + col) =
                make_float2(f2tf32f(o[nt][2*h2] * inv), f2tf32f(o[nt][2*h2+1] * inv));
        }
    }
}

// ---------------- launch ----------------
extern "C" void kernel_launch(void* const* d_in, const int* in_sizes, int n_in,
                              void* d_out, int out_size)
{
    const float* x       = (const float*)d_in[0];
    const float* w_q     = (const float*)d_in[1];
    const float* w_k     = (const float*)d_in[2];
    const float* w_v     = (const float*)d_in[3];
    const float* w_o     = (const float*)d_in[4];
    const float* alpha_p = (const float*)d_in[5];
    const float* delta_p = (const float*)d_in[6];
    const float* beta    = (const float*)d_in[7];
    const float* eta     = (const float*)d_in[8];
    const float* g1      = (const float*)d_in[9];
    const float* g2      = (const float*)d_in[10];
    const float* w_in    = (const float*)d_in[11];
    const float* b_in    = (const float*)d_in[12];
    const float* w_out   = (const float*)d_in[13];
    const float* b_out   = (const float*)d_in[14];
    float* out = (float*)d_out;

    float *xn, *y, *q, *k, *v, *ao, *x1, *xn2, *hb, *wr;
    cudaGetSymbolAddress((void**)&xn,  g_xn);
    cudaGetSymbolAddress((void**)&y,   g_y);
    cudaGetSymbolAddress((void**)&q,   g_q);
    cudaGetSymbolAddress((void**)&k,   g_k);
    cudaGetSymbolAddress((void**)&v,   g_v);
    cudaGetSymbolAddress((void**)&ao,  g_ao);
    cudaGetSymbolAddress((void**)&x1,  g_x1);
    cudaGetSymbolAddress((void**)&xn2, g_xn2);
    cudaGetSymbolAddress((void**)&hb,  g_hb);
    cudaGetSymbolAddress((void**)&wr,  g_w);

    cudaFuncSetAttribute(attn_kernel, cudaFuncAttributeMaxDynamicSharedMemorySize,
                         ATTN_SMEM_BYTES);
    cudaFuncSetAttribute(qkv_kernel, cudaFuncAttributeMaxDynamicSharedMemorySize, SMEM_GEMM);
    cudaFuncSetAttribute((const void*)tgemm_kernel<1,false>, cudaFuncAttributeMaxDynamicSharedMemorySize, SMEM_GEMM);
    cudaFuncSetAttribute((const void*)tgemm_kernel<2,true>,  cudaFuncAttributeMaxDynamicSharedMemorySize, SMEM_GEMM);
    cudaFuncSetAttribute((const void*)tgemm_kernel<3,false>, cudaFuncAttributeMaxDynamicSharedMemorySize, SMEM_GEMM);

    // pre-round all weights to tf32 (rna) once per replay
    wround_kernel<<<(12 * 1024 * 1024 / 4) / 256, 256>>>(w_q, w_k, w_v, w_o, w_in, w_out, wr);

    rmsnorm_kernel<<<BT, 256>>>(x, g1, xn, 1);
    ema_kernel<<<(BB * DD * 16) / 256, 256>>>(xn, alpha_p, delta_p, beta, eta, y);

    qkv_kernel<<<dim3(1024 / 128, BT / 128, 3), 256, SMEM_GEMM>>>(y, xn, wr, q, k, v);

    rope_kernel<<<(BB * TT * HH * 16) / 256, 256>>>(q, k, v);

    attn_kernel<<<dim3(TT / 128, BB * HH), 256, ATTN_SMEM_BYTES>>>(q, k, v, ao);

    dim3 gN1024(1024 / 128, BT / 128);
    tgemm_kernel<1,false><<<gN1024, 256, SMEM_GEMM>>>(ao, wr + 3 * 1024 * 1024, x1,
                                                      nullptr, x, 1024, 1024);

    rmsnorm_kernel<<<BT, 256>>>(x1, g2, xn2, 1);

    dim3 gN4096(4096 / 128, BT / 128);
    tgemm_kernel<2,true><<<gN4096, 256, SMEM_GEMM>>>(xn2, wr + 4 * 1024 * 1024, hb,
                                                     b_in, nullptr, 4096, 1024);
    tgemm_kernel<3,false><<<gN1024, 256, SMEM_GEMM>>>(hb, wr + 8 * 1024 * 1024, out,
                                                      b_out, x1, 1024, 4096);
}

// round 8
// speedup vs baseline: 1.0425x; 1.0278x over previous
#include <cuda_runtime.h>
#include <math.h>

#define BB 2
#define TT 2048
#define DD 1024
#define HH 16
#define HIDD 4096
#define BT (BB*TT)   // 4096 rows

// ---------------- scratch ----------------
__device__ float g_xn [BB*TT*DD];
__device__ float g_y  [BB*TT*DD];
__device__ float g_q  [BB*TT*DD];
__device__ float g_k  [BB*TT*DD];
__device__ float g_v  [BB*TT*DD];
__device__ float g_ao [BB*TT*DD];
__device__ float g_x1 [BB*TT*DD];
__device__ float g_xn2[BB*TT*DD];
__device__ float g_hb [BB*TT*HIDD];
__device__ float g_w  [12*1024*1024];   // rounded TRANSPOSED weights [n][k]: wq|wk|wv|wo|win|wout

// ---------------- helpers ----------------
__device__ __forceinline__ unsigned f2tf32(float x)
{
    unsigned r;
    asm("cvt.rna.tf32.f32 %0, %1;" : "=r"(r) : "f"(x));
    return r;
}
__device__ __forceinline__ float f2tf32f(float x) { return __uint_as_float(f2tf32(x)); }
__device__ __forceinline__ float4 cvt4(float4 v)
{
    return make_float4(f2tf32f(v.x), f2tf32f(v.y), f2tf32f(v.z), f2tf32f(v.w));
}

__device__ __forceinline__ void ldmx4(unsigned& a0, unsigned& a1, unsigned& a2, unsigned& a3,
                                      unsigned addr)
{
    asm volatile("ldmatrix.sync.aligned.m8n8.x4.shared.b16 {%0,%1,%2,%3}, [%4];"
                 : "=r"(a0), "=r"(a1), "=r"(a2), "=r"(a3) : "r"(addr));
}
__device__ __forceinline__ void ldmx2(unsigned& a0, unsigned& a1, unsigned addr)
{
    asm volatile("ldmatrix.sync.aligned.m8n8.x2.shared.b16 {%0,%1}, [%2];"
                 : "=r"(a0), "=r"(a1) : "r"(addr));
}
__device__ __forceinline__ void mma_tf32(float* d, const unsigned* a, unsigned b0, unsigned b1)
{
    asm volatile(
        "mma.sync.aligned.m16n8k8.row.col.f32.tf32.tf32.f32 "
        "{%0,%1,%2,%3}, {%4,%5,%6,%7}, {%8,%9}, {%0,%1,%2,%3};\n"
        : "+f"(d[0]), "+f"(d[1]), "+f"(d[2]), "+f"(d[3])
        : "r"(a[0]), "r"(a[1]), "r"(a[2]), "r"(a[3]), "r"(b0), "r"(b1));
}
__device__ __forceinline__ void cpasync16(void* smem, const void* gmem)
{
    unsigned s = (unsigned)__cvta_generic_to_shared(smem);
    asm volatile("cp.async.cg.shared.global [%0], [%1], 16;" :: "r"(s), "l"(gmem));
}
#define CP_COMMIT() asm volatile("cp.async.commit_group;")
#define CP_WAIT(n)  asm volatile("cp.async.wait_group %0;" :: "n"(n))

// ---------------- weight transpose + tf32 round ----------------
// dst[n*K + k] = rnd(src[k*N + n]) ; 32x32 tiles, coalesced both sides
__global__ void wtrans_kernel(const float* __restrict__ wq, const float* __restrict__ wk,
                              const float* __restrict__ wv, const float* __restrict__ wo,
                              const float* __restrict__ win, const float* __restrict__ wout,
                              float* __restrict__ dst)
{
    __shared__ float tile[32][33];
    int t = blockIdx.x;
    const float* src; int K, N; size_t doff;
    if (t < 4096) {
        int m = t >> 10; t &= 1023;
        src = (m == 0) ? wq : (m == 1) ? wk : (m == 2) ? wv : wo;
        K = 1024; N = 1024; doff = (size_t)m * 1024 * 1024;
    } else if (t < 8192) {
        t -= 4096; src = win;  K = 1024; N = 4096; doff = (size_t)4 * 1024 * 1024;
    } else {
        t -= 8192; src = wout; K = 4096; N = 1024; doff = (size_t)8 * 1024 * 1024;
    }
    int ktiles = K >> 5;
    int k0 = (t % ktiles) << 5;
    int n0 = (t / ktiles) << 5;
    int tx = threadIdx.x, ty = threadIdx.y;   // (32, 8)
    #pragma unroll
    for (int j = 0; j < 4; j++)
        tile[ty + j * 8][tx] = src[(size_t)(k0 + ty + j * 8) * N + n0 + tx];
    __syncthreads();
    #pragma unroll
    for (int j = 0; j < 4; j++)
        dst[doff + (size_t)(n0 + ty + j * 8) * K + k0 + tx] = f2tf32f(tile[tx][ty + j * 8]);
}

// ---------------- rmsnorm (rounded output when rnd=1) ----------------
__global__ void rmsnorm_kernel(const float* __restrict__ x, const float* __restrict__ g,
                               float* __restrict__ out, int rnd)
{
    int row = blockIdx.x;
    int tid = threadIdx.x;
    const float4* xr = (const float4*)(x + (size_t)row * DD);
    float4 v = xr[tid];
    float s = v.x*v.x + v.y*v.y + v.z*v.z + v.w*v.w;
    #pragma unroll
    for (int o = 16; o; o >>= 1) s += __shfl_xor_sync(0xffffffffu, s, o);
    __shared__ float red[8];
    if ((tid & 31) == 0) red[tid >> 5] = s;
    __syncthreads();
    float tot = red[0]+red[1]+red[2]+red[3]+red[4]+red[5]+red[6]+red[7];
    float inv = rsqrtf(tot * (1.0f / (float)DD) + 1e-6f);
    const float4* gr = (const float4*)g;
    float4 gv = gr[tid];
    float4 o4;
    o4.x = gv.x * (v.x * inv);
    o4.y = gv.y * (v.y * inv);
    o4.z = gv.z * (v.z * inv);
    o4.w = gv.w * (v.w * inv);
    if (rnd) o4 = cvt4(o4);
    ((float4*)(out + (size_t)row * DD))[tid] = o4;
}

// ---------------- EMA scan (rounded output) ----------------
__global__ void ema_kernel(const float* __restrict__ xn,
                           const float* __restrict__ ap, const float* __restrict__ dp,
                           const float* __restrict__ beta, const float* __restrict__ eta,
                           float* __restrict__ y)
{
    int idx = blockIdx.x * blockDim.x + threadIdx.x;
    int n = idx & 15;
    int d = (idx >> 4) & (DD - 1);
    int b = idx >> 14;
    int dn = d * 16 + n;
    float a   = 1.0f / (1.0f + expf(-ap[dn]));
    float ddv = 1.0f / (1.0f + expf(-dp[dn]));
    float dec = 1.0f - a * ddv;
    float ab  = a * beta[dn];
    float et  = eta[dn];
    const float* xp = xn + (size_t)b * TT * DD + d;
    float* yp       = y  + (size_t)b * TT * DD + d;
    float h = 0.0f;
    for (int t = 0; t < TT; t++) {
        float u = xp[(size_t)t * DD];
        h = fmaf(dec, h, ab * u);
        float s = et * h;
        s += __shfl_xor_sync(0xffffffffu, s, 8, 16);
        s += __shfl_xor_sync(0xffffffffu, s, 4, 16);
        s += __shfl_xor_sync(0xffffffffu, s, 2, 16);
        s += __shfl_xor_sync(0xffffffffu, s, 1, 16);
        if (n == 0) yp[(size_t)t * DD] = f2tf32f(s);
    }
}

// ---------------- RoPE (rounded output) ----------------
__global__ void rope_kernel(float* __restrict__ q, float* __restrict__ k, float* __restrict__ v)
{
    int idx = blockIdx.x * blockDim.x + threadIdx.x;
    int i = idx & 15;
    int h = (idx >> 4) & 15;
    int t = (idx >> 8) & (TT - 1);
    int b = idx >> 19;
    double fd = pow(10000.0, -(double)i / 16.0);
    float freq = (float)fd;
    float ang = (float)t * freq;
    double da = (double)ang;
    float c = (float)cos(da);
    float s = (float)sin(da);
    size_t base = ((size_t)(b * TT + t)) * DD + h * 64;
    {
        float x1 = q[base + i], x2 = q[base + 16 + i];
        q[base + i]      = f2tf32f(x1 * c - x2 * s);
        q[base + 16 + i] = f2tf32f(x2 * c + x1 * s);
    }
    {
        float x1 = k[base + i], x2 = k[base + 16 + i];
        k[base + i]      = f2tf32f(x1 * c - x2 * s);
        k[base + 16 + i] = f2tf32f(x2 * c + x1 * s);
    }
    {
        float x1 = v[base + i], x2 = v[base + 16 + i];
        v[base + i]      = f2tf32f(x1 * c - x2 * s);
        v[base + 16 + i] = f2tf32f(x2 * c + x1 * s);
    }
}

// ---------------- tf32 GEMM core: 128x128x16, cp.async 3-stage, all-ldmatrix ----
__device__ __forceinline__ float gelu_tanh(float x)
{
    float x3 = x * x * x;
    float t = tanhf(0.7978845608028654f * (x + 0.044715f * x3));
    return 0.5f * x * (1.0f + t);
}

#define GSTAGES 3
#define TS_STRIDE (128*20)                 // one operand tile [128][20]
#define SMEM_GEMM ((GSTAGES * 2 * TS_STRIDE) * 4)

// EPI: 0 = none, 1 = +resid, 2 = gelu(acc+bias), 3 = acc+bias+resid
// RND: round output to tf32 (it feeds a later GEMM/attn as an operand)
// BT is transposed weight: BT[n][k], row length K
template<int EPI, bool RND>
__device__ __forceinline__ void gemm_core(const float* __restrict__ A,
                                          const float* __restrict__ Bt,
                                          float* __restrict__ C,
                                          const float* __restrict__ bias,
                                          const float* __restrict__ resid,
                                          int N, int K, int bx, int by, float* sm)
{
    float* As = sm;                           // [GSTAGES][128][20]
    float* Bs = sm + GSTAGES * TS_STRIDE;     // [GSTAGES][128][20]

    const int tid  = threadIdx.x;
    const int lane = tid & 31;
    const int warp = tid >> 5;
    const int wm = (warp & 1) * 64;
    const int wn = (warp >> 1) * 32;
    const int lr = lane >> 2;
    const int lc = lane & 3;
    const int lrow  = lane & 15;
    const int lkoff = (lane >> 4) * 4;

    const int am = tid >> 2;                  // 0..63
    const int ak = (tid & 3) << 2;
    const float* Abase = A  + (size_t)(by * 128 + am) * K + ak;
    const float* Bbase = Bt + (size_t)(bx * 128 + am) * K + ak;

    const int kt = K >> 4;

    #pragma unroll
    for (int s = 0; s < GSTAGES - 1; s++) {
        const float* Ag = Abase + s * 16;
        const float* Bg = Bbase + s * 16;
        cpasync16(As + s * TS_STRIDE + am * 20 + ak,        Ag);
        cpasync16(As + s * TS_STRIDE + (am + 64) * 20 + ak, Ag + (size_t)64 * K);
        cpasync16(Bs + s * TS_STRIDE + am * 20 + ak,        Bg);
        cpasync16(Bs + s * TS_STRIDE + (am + 64) * 20 + ak, Bg + (size_t)64 * K);
        CP_COMMIT();
    }

    float acc[4][4][4];
    #pragma unroll
    for (int mt = 0; mt < 4; mt++)
        #pragma unroll
        for (int nt = 0; nt < 4; nt++)
            #pragma unroll
            for (int r = 0; r < 4; r++) acc[mt][nt][r] = 0.0f;

    int cb = 0, pb = GSTAGES - 1;
    for (int it = 0; it < kt; it++) {
        CP_WAIT(GSTAGES - 2);
        __syncthreads();

        int nx = it + GSTAGES - 1;
        if (nx < kt) {
            const float* Ag = Abase + nx * 16;
            const float* Bg = Bbase + nx * 16;
            cpasync16(As + pb * TS_STRIDE + am * 20 + ak,        Ag);
            cpasync16(As + pb * TS_STRIDE + (am + 64) * 20 + ak, Ag + (size_t)64 * K);
            cpasync16(Bs + pb * TS_STRIDE + am * 20 + ak,        Bg);
            cpasync16(Bs + pb * TS_STRIDE + (am + 64) * 20 + ak, Bg + (size_t)64 * K);
        }
        CP_COMMIT();
        if (++pb == GSTAGES) pb = 0;

        const float* Asc = As + cb * TS_STRIDE;
        const float* Bsc = Bs + cb * TS_STRIDE;
        if (++cb == GSTAGES) cb = 0;

        #pragma unroll
        for (int kb = 0; kb < 2; kb++) {
            unsigned af[4][4];
            #pragma unroll
            for (int mt = 0; mt < 4; mt++) {
                unsigned addr = (unsigned)__cvta_generic_to_shared(
                    Asc + (wm + mt * 16 + lrow) * 20 + kb * 8 + lkoff);
                ldmx4(af[mt][0], af[mt][1], af[mt][2], af[mt][3], addr);
            }
            // B fragments: 2 x ldmx4, each covers 16 n (two 8-wide nt tiles)
            // regs: r0 = b0(ntlo), r1 = b0(nthi), r2 = b1(ntlo), r3 = b1(nthi)
            unsigned bf[4][2];
            #pragma unroll
            for (int nt2 = 0; nt2 < 2; nt2++) {
                unsigned r0, r1, r2, r3;
                unsigned addr = (unsigned)__cvta_generic_to_shared(
                    Bsc + (wn + nt2 * 16 + lrow) * 20 + kb * 8 + lkoff);
                ldmx4(r0, r1, r2, r3, addr);
                bf[nt2 * 2 + 0][0] = r0; bf[nt2 * 2 + 0][1] = r2;
                bf[nt2 * 2 + 1][0] = r1; bf[nt2 * 2 + 1][1] = r3;
            }
            #pragma unroll
            for (int mt = 0; mt < 4; mt++)
                #pragma unroll
                for (int nt = 0; nt < 4; nt++)
                    mma_tf32(acc[mt][nt], af[mt], bf[nt][0], bf[nt][1]);
        }
    }

    #pragma unroll
    for (int mt = 0; mt < 4; mt++) {
        #pragma unroll
        for (int nt = 0; nt < 4; nt++) {
            int row = by * 128 + wm + mt * 16 + lr;
            int col = bx * 128 + wn + nt * 8 + 2 * lc;
            #pragma unroll
            for (int half = 0; half < 2; half++) {
                int r = row + half * 8;
                size_t off = (size_t)r * N + col;
                float v0 = acc[mt][nt][half * 2 + 0];
                float v1 = acc[mt][nt][half * 2 + 1];
                if (EPI == 2 || EPI == 3) { v0 += bias[col]; v1 += bias[col + 1]; }
                if (EPI == 2) { v0 = gelu_tanh(v0); v1 = gelu_tanh(v1); }
                if (EPI == 1 || EPI == 3) { v0 += resid[off]; v1 += resid[off + 1]; }
                if (RND) { v0 = f2tf32f(v0); v1 = f2tf32f(v1); }
                *(float2*)(C + off) = make_float2(v0, v1);
            }
        }
    }
}

template<int EPI, bool RND>
__global__ __launch_bounds__(256, 2)
void tgemm_kernel(const float* __restrict__ A, const float* __restrict__ Bt,
                  float* __restrict__ C, const float* __restrict__ bias,
                  const float* __restrict__ resid, int N, int K)
{
    extern __shared__ float smg[];
    gemm_core<EPI, RND>(A, Bt, C, bias, resid, N, K, blockIdx.x, blockIdx.y, smg);
}

// merged q/k/v projection: blockIdx.z selects operand set
__global__ __launch_bounds__(256, 2)
void qkv_kernel(const float* __restrict__ y, const float* __restrict__ xn,
                const float* __restrict__ wr,
                float* __restrict__ q, float* __restrict__ k, float* __restrict__ v)
{
    extern __shared__ float smg[];
    int z = blockIdx.z;
    const float* A = (z == 2) ? xn : y;
    const float* B = wr + (size_t)z * 1024 * 1024;
    float*       C = (z == 0) ? q : (z == 1) ? k : v;
    gemm_core<0, true>(A, B, C, nullptr, nullptr, 1024, 1024, blockIdx.x, blockIdx.y, smg);
}

// ---------------- tf32 mma flash attention, BM=128, BN=64 ----------------
#define AT_QS 0
#define AT_KS (128*68)
#define AT_VS (192*68)
#define AT_PS (256*68)
#define ATTN_SMEM_BYTES (384*68*4)

__global__ __launch_bounds__(256, 2)
void attn_kernel(const float* __restrict__ Q, const float* __restrict__ Kk,
                 const float* __restrict__ V, float* __restrict__ O)
{
    extern __shared__ float sm[];

    const int qt = blockIdx.x;
    const int bh = blockIdx.y;
    const int b = bh >> 4, h = bh & 15;
    const size_t ld = DD;
    const float* Qb = Q  + (size_t)b * TT * ld + h * 64;
    const float* Kb = Kk + (size_t)b * TT * ld + h * 64;
    const float* Vb = V  + (size_t)b * TT * ld + h * 64;
    float*       Ob = O  + (size_t)b * TT * ld + h * 64;

    const int tid  = threadIdx.x;
    const int lane = tid & 31;
    const int warp = tid >> 5;
    const int lr = lane >> 2;
    const int lc = lane & 3;
    const int lrow  = lane & 15;
    const int lkoff = (lane >> 4) * 4;

    for (int i = tid; i < 128 * 16; i += 256) {
        int r = i >> 4, c4 = (i & 15) << 2;
        float4 qv = *(const float4*)(Qb + (size_t)(qt * 128 + r) * ld + c4);
        qv.x *= 0.125f; qv.y *= 0.125f; qv.z *= 0.125f; qv.w *= 0.125f;
        *(float4*)&sm[AT_QS + r * 68 + c4] = qv;
    }

    float m_i[2] = {-1e30f, -1e30f};
    float l_i[2] = {0.0f, 0.0f};
    float o[8][4];
    #pragma unroll
    for (int nt = 0; nt < 8; nt++)
        #pragma unroll
        for (int r = 0; r < 4; r++) o[nt][r] = 0.0f;

    const int row_min = qt * 128 + warp * 16;
    const int nkt = 2 * qt + 2;

    for (int kt = 0; kt < nkt; kt++) {
        __syncthreads();
        for (int i = tid; i < 64 * 16; i += 256) {
            int r = i >> 4, c4 = (i & 15) << 2;
            float4 kv = *(const float4*)(Kb + (size_t)(kt * 64 + r) * ld + c4);
            *(float4*)&sm[AT_KS + r * 68 + c4] = kv;
        }
        for (int i = tid; i < 64 * 16; i += 256) {
            int r = i & 63;
            int d4 = (i >> 6) << 2;
            float4 vv = *(const float4*)(Vb + (size_t)(kt * 64 + r) * ld + d4);
            sm[AT_VS + (d4 + 0) * 68 + r] = vv.x;
            sm[AT_VS + (d4 + 1) * 68 + r] = vv.y;
            sm[AT_VS + (d4 + 2) * 68 + r] = vv.z;
            sm[AT_VS + (d4 + 3) * 68 + r] = vv.w;
        }
        __syncthreads();

        if (kt * 64 <= row_min + 15) {
            float s[8][4];
            #pragma unroll
            for (int nt = 0; nt < 8; nt++)
                #pragma unroll
                for (int r = 0; r < 4; r++) s[nt][r] = 0.0f;

            #pragma unroll
            for (int kb = 0; kb < 8; kb++) {
                unsigned af[4];
                unsigned qaddr = (unsigned)__cvta_generic_to_shared(
                    &sm[AT_QS + (warp * 16 + lrow) * 68 + kb * 8 + lkoff]);
                ldmx4(af[0], af[1], af[2], af[3], qaddr);
                #pragma unroll
                for (int nt = 0; nt < 8; nt++) {
                    unsigned b0, b1;
                    unsigned kaddr = (unsigned)__cvta_generic_to_shared(
                        &sm[AT_KS + (nt * 8 + (lane & 7)) * 68 + kb * 8 + ((lane >> 3) & 1) * 4]);
                    ldmx2(b0, b1, kaddr);
                    mma_tf32(s[nt], af, b0, b1);
                }
            }

            if (kt * 64 + 63 > row_min) {
                #pragma unroll
                for (int nt = 0; nt < 8; nt++)
                    #pragma unroll
                    for (int r = 0; r < 4; r++) {
                        int col = kt * 64 + nt * 8 + 2 * lc + (r & 1);
                        int row = row_min + lr + 8 * (r >> 1);
                        if (col > row) s[nt][r] = -1e30f;
                    }
            }

            #pragma unroll
            for (int h2 = 0; h2 < 2; h2++) {
                float rm = -1e30f;
                #pragma unroll
                for (int nt = 0; nt < 8; nt++)
                    rm = fmaxf(rm, fmaxf(s[nt][2*h2], s[nt][2*h2+1]));
                rm = fmaxf(rm, __shfl_xor_sync(0xffffffffu, rm, 1));
                rm = fmaxf(rm, __shfl_xor_sync(0xffffffffu, rm, 2));
                float mn = fmaxf(m_i[h2], rm);
                float alpha = __expf(m_i[h2] - mn);
                m_i[h2] = mn;
                float rs = 0.0f;
                #pragma unroll
                for (int nt = 0; nt < 8; nt++) {
                    float p0 = __expf(s[nt][2*h2]   - mn);
                    float p1 = __expf(s[nt][2*h2+1] - mn);
                    s[nt][2*h2]   = p0;
                    s[nt][2*h2+1] = p1;
                    rs += p0 + p1;
                }
                rs += __shfl_xor_sync(0xffffffffu, rs, 1);
                rs += __shfl_xor_sync(0xffffffffu, rs, 2);
                l_i[h2] = l_i[h2] * alpha + rs;
                #pragma unroll
                for (int nt = 0; nt < 8; nt++) {
                    o[nt][2*h2]   *= alpha;
                    o[nt][2*h2+1] *= alpha;
                }
            }

            #pragma unroll
            for (int nt = 0; nt < 8; nt++)
                #pragma unroll
                for (int r = 0; r < 4; r++) {
                    int row = warp * 16 + lr + 8 * (r >> 1);
                    int col = nt * 8 + 2 * lc + (r & 1);
                    sm[AT_PS + row * 68 + col] = f2tf32f(s[nt][r]);
                }
            __syncwarp();

            #pragma unroll
            for (int kb = 0; kb < 8; kb++) {
                unsigned af[4];
                unsigned paddr = (unsigned)__cvta_generic_to_shared(
                    &sm[AT_PS + (warp * 16 + lrow) * 68 + kb * 8 + lkoff]);
                ldmx4(af[0], af[1], af[2], af[3], paddr);
                #pragma unroll
                for (int nt = 0; nt < 8; nt++) {
                    unsigned b0, b1;
                    unsigned vaddr = (unsigned)__cvta_generic_to_shared(
                        &sm[AT_VS + (nt * 8 + (lane & 7)) * 68 + kb * 8 + ((lane >> 3) & 1) * 4]);
                    ldmx2(b0, b1, vaddr);
                    mma_tf32(o[nt], af, b0, b1);
                }
            }
        }
    }

    #pragma unroll
    for (int h2 = 0; h2 < 2; h2++) {
        float inv = 1.0f / l_i[h2];
        int row = qt * 128 + warp * 16 + lr + 8 * h2;
        #pragma unroll
        for (int nt = 0; nt < 8; nt++) {
            int col = nt * 8 + 2 * lc;
            *(float2*)(Ob + (size_t)row * ld + col) =
                make_float2(f2tf32f(o[nt][2*h2] * inv), f2tf32f(o[nt][2*h2+1] * inv));
        }
    }
}

// ---------------- launch ----------------
extern "C" void kernel_launch(void* const* d_in, const int* in_sizes, int n_in,
                              void* d_out, int out_size)
{
    const float* x       = (const float*)d_in[0];
    const float* w_q     = (const float*)d_in[1];
    const float* w_k     = (const float*)d_in[2];
    const float* w_v     = (const float*)d_in[3];
    const float* w_o     = (const float*)d_in[4];
    const float* alpha_p = (const float*)d_in[5];
    const float* delta_p = (const float*)d_in[6];
    const float* beta    = (const float*)d_in[7];
    const float* eta     = (const float*)d_in[8];
    const float* g1      = (const float*)d_in[9];
    const float* g2      = (const float*)d_in[10];
    const float* w_in    = (const float*)d_in[11];
    const float* b_in    = (const float*)d_in[12];
    const float* w_out   = (const float*)d_in[13];
    const float* b_out   = (const float*)d_in[14];
    float* out = (float*)d_out;

    float *xn, *y, *q, *k, *v, *ao, *x1, *xn2, *hb, *wr;
    cudaGetSymbolAddress((void**)&xn,  g_xn);
    cudaGetSymbolAddress((void**)&y,   g_y);
    cudaGetSymbolAddress((void**)&q,   g_q);
    cudaGetSymbolAddress((void**)&k,   g_k);
    cudaGetSymbolAddress((void**)&v,   g_v);
    cudaGetSymbolAddress((void**)&ao,  g_ao);
    cudaGetSymbolAddress((void**)&x1,  g_x1);
    cudaGetSymbolAddress((void**)&xn2, g_xn2);
    cudaGetSymbolAddress((void**)&hb,  g_hb);
    cudaGetSymbolAddress((void**)&wr,  g_w);

    cudaFuncSetAttribute(attn_kernel, cudaFuncAttributeMaxDynamicSharedMemorySize,
                         ATTN_SMEM_BYTES);
    cudaFuncSetAttribute(qkv_kernel, cudaFuncAttributeMaxDynamicSharedMemorySize, SMEM_GEMM);
    cudaFuncSetAttribute((const void*)tgemm_kernel<1,false>, cudaFuncAttributeMaxDynamicSharedMemorySize, SMEM_GEMM);
    cudaFuncSetAttribute((const void*)tgemm_kernel<2,true>,  cudaFuncAttributeMaxDynamicSharedMemorySize, SMEM_GEMM);
    cudaFuncSetAttribute((const void*)tgemm_kernel<3,false>, cudaFuncAttributeMaxDynamicSharedMemorySize, SMEM_GEMM);

    // pre-round + transpose all weights to tf32 [n][k] layout
    wtrans_kernel<<<12288, dim3(32, 8)>>>(w_q, w_k, w_v, w_o, w_in, w_out, wr);

    rmsnorm_kernel<<<BT, 256>>>(x, g1, xn, 1);
    ema_kernel<<<(BB * DD * 16) / 256, 256>>>(xn, alpha_p, delta_p, beta, eta, y);

    qkv_kernel<<<dim3(1024 / 128, BT / 128, 3), 256, SMEM_GEMM>>>(y, xn, wr, q, k, v);

    rope_kernel<<<(BB * TT * HH * 16) / 256, 256>>>(q, k, v);

    attn_kernel<<<dim3(TT / 128, BB * HH), 256, ATTN_SMEM_BYTES>>>(q, k, v, ao);

    dim3 gN1024(1024 / 128, BT / 128);
    tgemm_kernel<1,false><<<gN1024, 256, SMEM_GEMM>>>(ao, wr + 3 * 1024 * 1024, x1,
                                                      nullptr, x, 1024, 1024);

    rmsnorm_kernel<<<BT, 256>>>(x1, g2, xn2, 1);

    dim3 gN4096(4096 / 128, BT / 128);
    tgemm_kernel<2,true><<<gN4096, 256, SMEM_GEMM>>>(xn2, wr + 4 * 1024 * 1024, hb,
                                                     b_in, nullptr, 4096, 1024);
    tgemm_kernel<3,false><<<gN1024, 256, SMEM_GEMM>>>(hb, wr + 8 * 1024 * 1024, out,
                                                      b_out, x1, 1024, 4096);
}

// round 9
// speedup vs baseline: 1.1108x; 1.0655x over previous
#include <cuda_runtime.h>
#include <math.h>

#define BB 2
#define TT 2048
#define DD 1024
#define HH 16
#define HIDD 4096
#define BT (BB*TT)   // 4096 rows

// ---------------- scratch ----------------
__device__ float g_xn [BB*TT*DD];
__device__ float g_y  [BB*TT*DD];
__device__ float g_q  [BB*TT*DD];
__device__ float g_k  [BB*TT*DD];
__device__ float g_v  [BB*TT*DD];
__device__ float g_ao [BB*TT*DD];
__device__ float g_x1 [BB*TT*DD];
__device__ float g_xn2[BB*TT*DD];
__device__ float g_hb [BB*TT*HIDD];
__device__ float g_w  [12*1024*1024];   // rounded TRANSPOSED weights [n][k]: wq|wk|wv|wo|win|wout

// ---------------- helpers ----------------
__device__ __forceinline__ unsigned f2tf32(float x)
{
    unsigned r;
    asm("cvt.rna.tf32.f32 %0, %1;" : "=r"(r) : "f"(x));
    return r;
}
__device__ __forceinline__ float f2tf32f(float x) { return __uint_as_float(f2tf32(x)); }
__device__ __forceinline__ float4 cvt4(float4 v)
{
    return make_float4(f2tf32f(v.x), f2tf32f(v.y), f2tf32f(v.z), f2tf32f(v.w));
}

__device__ __forceinline__ void ldmx4(unsigned& a0, unsigned& a1, unsigned& a2, unsigned& a3,
                                      unsigned addr)
{
    asm volatile("ldmatrix.sync.aligned.m8n8.x4.shared.b16 {%0,%1,%2,%3}, [%4];"
                 : "=r"(a0), "=r"(a1), "=r"(a2), "=r"(a3) : "r"(addr));
}
__device__ __forceinline__ void ldmx2(unsigned& a0, unsigned& a1, unsigned addr)
{
    asm volatile("ldmatrix.sync.aligned.m8n8.x2.shared.b16 {%0,%1}, [%2];"
                 : "=r"(a0), "=r"(a1) : "r"(addr));
}
__device__ __forceinline__ void mma_tf32(float* d, const unsigned* a, unsigned b0, unsigned b1)
{
    asm volatile(
        "mma.sync.aligned.m16n8k8.row.col.f32.tf32.tf32.f32 "
        "{%0,%1,%2,%3}, {%4,%5,%6,%7}, {%8,%9}, {%0,%1,%2,%3};\n"
        : "+f"(d[0]), "+f"(d[1]), "+f"(d[2]), "+f"(d[3])
        : "r"(a[0]), "r"(a[1]), "r"(a[2]), "r"(a[3]), "r"(b0), "r"(b1));
}
__device__ __forceinline__ void cpasync16(void* smem, const void* gmem)
{
    unsigned s = (unsigned)__cvta_generic_to_shared(smem);
    asm volatile("cp.async.cg.shared.global [%0], [%1], 16;" :: "r"(s), "l"(gmem));
}
#define CP_COMMIT() asm volatile("cp.async.commit_group;")
#define CP_WAIT(n)  asm volatile("cp.async.wait_group %0;" :: "n"(n))

// ---------------- weight transpose + tf32 round ----------------
__global__ void wtrans_kernel(const float* __restrict__ wq, const float* __restrict__ wk,
                              const float* __restrict__ wv, const float* __restrict__ wo,
                              const float* __restrict__ win, const float* __restrict__ wout,
                              float* __restrict__ dst)
{
    __shared__ float tile[32][33];
    int t = blockIdx.x;
    const float* src; int K, N; size_t doff;
    if (t < 4096) {
        int m = t >> 10; t &= 1023;
        src = (m == 0) ? wq : (m == 1) ? wk : (m == 2) ? wv : wo;
        K = 1024; N = 1024; doff = (size_t)m * 1024 * 1024;
    } else if (t < 8192) {
        t -= 4096; src = win;  K = 1024; N = 4096; doff = (size_t)4 * 1024 * 1024;
    } else {
        t -= 8192; src = wout; K = 4096; N = 1024; doff = (size_t)8 * 1024 * 1024;
    }
    int ktiles = K >> 5;
    int k0 = (t % ktiles) << 5;
    int n0 = (t / ktiles) << 5;
    int tx = threadIdx.x, ty = threadIdx.y;   // (32, 8)
    #pragma unroll
    for (int j = 0; j < 4; j++)
        tile[ty + j * 8][tx] = src[(size_t)(k0 + ty + j * 8) * N + n0 + tx];
    __syncthreads();
    #pragma unroll
    for (int j = 0; j < 4; j++)
        dst[doff + (size_t)(n0 + ty + j * 8) * K + k0 + tx] = f2tf32f(tile[tx][ty + j * 8]);
}

// ---------------- rmsnorm (rounded output when rnd=1) ----------------
__global__ void rmsnorm_kernel(const float* __restrict__ x, const float* __restrict__ g,
                               float* __restrict__ out, int rnd)
{
    int row = blockIdx.x;
    int tid = threadIdx.x;
    const float4* xr = (const float4*)(x + (size_t)row * DD);
    float4 v = xr[tid];
    float s = v.x*v.x + v.y*v.y + v.z*v.z + v.w*v.w;
    #pragma unroll
    for (int o = 16; o; o >>= 1) s += __shfl_xor_sync(0xffffffffu, s, o);
    __shared__ float red[8];
    if ((tid & 31) == 0) red[tid >> 5] = s;
    __syncthreads();
    float tot = red[0]+red[1]+red[2]+red[3]+red[4]+red[5]+red[6]+red[7];
    float inv = rsqrtf(tot * (1.0f / (float)DD) + 1e-6f);
    const float4* gr = (const float4*)g;
    float4 gv = gr[tid];
    float4 o4;
    o4.x = gv.x * (v.x * inv);
    o4.y = gv.y * (v.y * inv);
    o4.z = gv.z * (v.z * inv);
    o4.w = gv.w * (v.w * inv);
    if (rnd) o4 = cvt4(o4);
    ((float4*)(out + (size_t)row * DD))[tid] = o4;
}

// ---------------- EMA scan (rounded output) ----------------
__global__ void ema_kernel(const float* __restrict__ xn,
                           const float* __restrict__ ap, const float* __restrict__ dp,
                           const float* __restrict__ beta, const float* __restrict__ eta,
                           float* __restrict__ y)
{
    int idx = blockIdx.x * blockDim.x + threadIdx.x;
    int n = idx & 15;
    int d = (idx >> 4) & (DD - 1);
    int b = idx >> 14;
    int dn = d * 16 + n;
    float a   = 1.0f / (1.0f + expf(-ap[dn]));
    float ddv = 1.0f / (1.0f + expf(-dp[dn]));
    float dec = 1.0f - a * ddv;
    float ab  = a * beta[dn];
    float et  = eta[dn];
    const float* xp = xn + (size_t)b * TT * DD + d;
    float* yp       = y  + (size_t)b * TT * DD + d;
    float h = 0.0f;
    for (int t = 0; t < TT; t++) {
        float u = xp[(size_t)t * DD];
        h = fmaf(dec, h, ab * u);
        float s = et * h;
        s += __shfl_xor_sync(0xffffffffu, s, 8, 16);
        s += __shfl_xor_sync(0xffffffffu, s, 4, 16);
        s += __shfl_xor_sync(0xffffffffu, s, 2, 16);
        s += __shfl_xor_sync(0xffffffffu, s, 1, 16);
        if (n == 0) yp[(size_t)t * DD] = f2tf32f(s);
    }
}

// ---------------- RoPE (rounded output) ----------------
__global__ void rope_kernel(float* __restrict__ q, float* __restrict__ k, float* __restrict__ v)
{
    int idx = blockIdx.x * blockDim.x + threadIdx.x;
    int i = idx & 15;
    int h = (idx >> 4) & 15;
    int t = (idx >> 8) & (TT - 1);
    int b = idx >> 19;
    double fd = pow(10000.0, -(double)i / 16.0);
    float freq = (float)fd;
    float ang = (float)t * freq;
    double da = (double)ang;
    float c = (float)cos(da);
    float s = (float)sin(da);
    size_t base = ((size_t)(b * TT + t)) * DD + h * 64;
    {
        float x1 = q[base + i], x2 = q[base + 16 + i];
        q[base + i]      = f2tf32f(x1 * c - x2 * s);
        q[base + 16 + i] = f2tf32f(x2 * c + x1 * s);
    }
    {
        float x1 = k[base + i], x2 = k[base + 16 + i];
        k[base + i]      = f2tf32f(x1 * c - x2 * s);
        k[base + 16 + i] = f2tf32f(x2 * c + x1 * s);
    }
    {
        float x1 = v[base + i], x2 = v[base + 16 + i];
        v[base + i]      = f2tf32f(x1 * c - x2 * s);
        v[base + 16 + i] = f2tf32f(x2 * c + x1 * s);
    }
}

// ---------------- tf32 GEMM core: 128x128x16, cp.async 4-stage, all-ldmatrix ----
__device__ __forceinline__ float gelu_tanh(float x)
{
    float x3 = x * x * x;
    float t = tanhf(0.7978845608028654f * (x + 0.044715f * x3));
    return 0.5f * x * (1.0f + t);
}

#define GSTAGES 4
#define TS_STRIDE (128*20)                 // one operand tile [128][20]
#define SMEM_GEMM ((GSTAGES * 2 * TS_STRIDE) * 4)

template<int EPI, bool RND>
__device__ __forceinline__ void gemm_core(const float* __restrict__ A,
                                          const float* __restrict__ Bt,
                                          float* __restrict__ C,
                                          const float* __restrict__ bias,
                                          const float* __restrict__ resid,
                                          int N, int K, int bx, int by, float* sm)
{
    float* As = sm;                           // [GSTAGES][128][20]
    float* Bs = sm + GSTAGES * TS_STRIDE;     // [GSTAGES][128][20]

    const int tid  = threadIdx.x;
    const int lane = tid & 31;
    const int warp = tid >> 5;
    const int wm = (warp & 1) * 64;
    const int wn = (warp >> 1) * 32;
    const int lr = lane >> 2;
    const int lc = lane & 3;
    const int lrow  = lane & 15;
    const int lkoff = (lane >> 4) * 4;

    const int am = tid >> 2;                  // 0..63
    const int ak = (tid & 3) << 2;
    const float* Abase = A  + (size_t)(by * 128 + am) * K + ak;
    const float* Bbase = Bt + (size_t)(bx * 128 + am) * K + ak;

    const int kt = K >> 4;

    #pragma unroll
    for (int s = 0; s < GSTAGES - 1; s++) {
        const float* Ag = Abase + s * 16;
        const float* Bg = Bbase + s * 16;
        cpasync16(As + s * TS_STRIDE + am * 20 + ak,        Ag);
        cpasync16(As + s * TS_STRIDE + (am + 64) * 20 + ak, Ag + (size_t)64 * K);
        cpasync16(Bs + s * TS_STRIDE + am * 20 + ak,        Bg);
        cpasync16(Bs + s * TS_STRIDE + (am + 64) * 20 + ak, Bg + (size_t)64 * K);
        CP_COMMIT();
    }

    float acc[4][4][4];
    #pragma unroll
    for (int mt = 0; mt < 4; mt++)
        #pragma unroll
        for (int nt = 0; nt < 4; nt++)
            #pragma unroll
            for (int r = 0; r < 4; r++) acc[mt][nt][r] = 0.0f;

    int cb = 0, pb = GSTAGES - 1;
    for (int it = 0; it < kt; it++) {
        CP_WAIT(GSTAGES - 2);
        __syncthreads();

        int nx = it + GSTAGES - 1;
        if (nx < kt) {
            const float* Ag = Abase + nx * 16;
            const float* Bg = Bbase + nx * 16;
            cpasync16(As + pb * TS_STRIDE + am * 20 + ak,        Ag);
            cpasync16(As + pb * TS_STRIDE + (am + 64) * 20 + ak, Ag + (size_t)64 * K);
            cpasync16(Bs + pb * TS_STRIDE + am * 20 + ak,        Bg);
            cpasync16(Bs + pb * TS_STRIDE + (am + 64) * 20 + ak, Bg + (size_t)64 * K);
        }
        CP_COMMIT();
        if (++pb == GSTAGES) pb = 0;

        const float* Asc = As + cb * TS_STRIDE;
        const float* Bsc = Bs + cb * TS_STRIDE;
        if (++cb == GSTAGES) cb = 0;

        #pragma unroll
        for (int kb = 0; kb < 2; kb++) {
            unsigned af[4][4];
            #pragma unroll
            for (int mt = 0; mt < 4; mt++) {
                unsigned addr = (unsigned)__cvta_generic_to_shared(
                    Asc + (wm + mt * 16 + lrow) * 20 + kb * 8 + lkoff);
                ldmx4(af[mt][0], af[mt][1], af[mt][2], af[mt][3], addr);
            }
            unsigned bf[4][2];
            #pragma unroll
            for (int nt2 = 0; nt2 < 2; nt2++) {
                unsigned r0, r1, r2, r3;
                unsigned addr = (unsigned)__cvta_generic_to_shared(
                    Bsc + (wn + nt2 * 16 + lrow) * 20 + kb * 8 + lkoff);
                ldmx4(r0, r1, r2, r3, addr);
                bf[nt2 * 2 + 0][0] = r0; bf[nt2 * 2 + 0][1] = r2;
                bf[nt2 * 2 + 1][0] = r1; bf[nt2 * 2 + 1][1] = r3;
            }
            #pragma unroll
            for (int mt = 0; mt < 4; mt++)
                #pragma unroll
                for (int nt = 0; nt < 4; nt++)
                    mma_tf32(acc[mt][nt], af[mt], bf[nt][0], bf[nt][1]);
        }
    }

    #pragma unroll
    for (int mt = 0; mt < 4; mt++) {
        #pragma unroll
        for (int nt = 0; nt < 4; nt++) {
            int row = by * 128 + wm + mt * 16 + lr;
            int col = bx * 128 + wn + nt * 8 + 2 * lc;
            #pragma unroll
            for (int half = 0; half < 2; half++) {
                int r = row + half * 8;
                size_t off = (size_t)r * N + col;
                float v0 = acc[mt][nt][half * 2 + 0];
                float v1 = acc[mt][nt][half * 2 + 1];
                if (EPI == 2 || EPI == 3) { v0 += bias[col]; v1 += bias[col + 1]; }
                if (EPI == 2) { v0 = gelu_tanh(v0); v1 = gelu_tanh(v1); }
                if (EPI == 1 || EPI == 3) { v0 += resid[off]; v1 += resid[off + 1]; }
                if (RND) { v0 = f2tf32f(v0); v1 = f2tf32f(v1); }
                *(float2*)(C + off) = make_float2(v0, v1);
            }
        }
    }
}

template<int EPI, bool RND>
__global__ __launch_bounds__(256, 2)
void tgemm_kernel(const float* __restrict__ A, const float* __restrict__ Bt,
                  float* __restrict__ C, const float* __restrict__ bias,
                  const float* __restrict__ resid, int N, int K)
{
    extern __shared__ float smg[];
    gemm_core<EPI, RND>(A, Bt, C, bias, resid, N, K, blockIdx.x, blockIdx.y, smg);
}

__global__ __launch_bounds__(256, 2)
void qkv_kernel(const float* __restrict__ y, const float* __restrict__ xn,
                const float* __restrict__ wr,
                float* __restrict__ q, float* __restrict__ k, float* __restrict__ v)
{
    extern __shared__ float smg[];
    int z = blockIdx.z;
    const float* A = (z == 2) ? xn : y;
    const float* B = wr + (size_t)z * 1024 * 1024;
    float*       C = (z == 0) ? q : (z == 1) ? k : v;
    gemm_core<0, true>(A, B, C, nullptr, nullptr, 1024, 1024, blockIdx.x, blockIdx.y, smg);
}

// ---------------- tf32 mma flash attention, BM=128, BN=64, cp.async split pipe --
// smem floats: Qs[128][68] | Ks[64][68] | Vs[64][72] natural | Ps[128][68]
#define AT_QS 0
#define AT_KS (128*68)
#define AT_VS (AT_KS + 64*68)
#define AT_PS (AT_VS + 64*72)
#define ATTN_SMEM_FLOATS (AT_PS + 128*68)
#define ATTN_SMEM_BYTES (ATTN_SMEM_FLOATS*4)

__global__ __launch_bounds__(256, 2)
void attn_kernel(const float* __restrict__ Q, const float* __restrict__ Kk,
                 const float* __restrict__ V, float* __restrict__ O)
{
    extern __shared__ float sm[];

    const int qt = blockIdx.x;
    const int bh = blockIdx.y;
    const int b = bh >> 4, h = bh & 15;
    const size_t ld = DD;
    const float* Qb = Q  + (size_t)b * TT * ld + h * 64;
    const float* Kb = Kk + (size_t)b * TT * ld + h * 64;
    const float* Vb = V  + (size_t)b * TT * ld + h * 64;
    float*       Ob = O  + (size_t)b * TT * ld + h * 64;

    const int tid  = threadIdx.x;
    const int lane = tid & 31;
    const int warp = tid >> 5;
    const int lr = lane >> 2;
    const int lc = lane & 3;
    const int lrow  = lane & 15;
    const int lkoff = (lane >> 4) * 4;

    const int nkt = 2 * qt + 2;
    const int row_min = qt * 128 + warp * 16;

    // per-thread load slots (4 rows x 1 float4 each over the 64x16-float4 tile)
    const int ldr0 = tid >> 4;        // rows ldr0, every +16
    const int ldc4 = (tid & 15) << 2;

    // prime: K(0), then V(0)
    #pragma unroll
    for (int j = 0; j < 4; j++) {
        int r = ldr0 + j * 16;
        cpasync16(&sm[AT_KS + r * 68 + ldc4], Kb + (size_t)r * ld + ldc4);
    }
    CP_COMMIT();
    #pragma unroll
    for (int j = 0; j < 4; j++) {
        int r = ldr0 + j * 16;
        cpasync16(&sm[AT_VS + r * 72 + ldc4], Vb + (size_t)r * ld + ldc4);
    }
    CP_COMMIT();

    // Q (once, scaled; already tf32-rounded by producers, *0.125f exact)
    for (int i = tid; i < 128 * 16; i += 256) {
        int r = i >> 4, c4 = (i & 15) << 2;
        float4 qv = *(const float4*)(Qb + (size_t)(qt * 128 + r) * ld + c4);
        qv.x *= 0.125f; qv.y *= 0.125f; qv.z *= 0.125f; qv.w *= 0.125f;
        *(float4*)&sm[AT_QS + r * 68 + c4] = qv;
    }

    float m_i[2] = {-1e30f, -1e30f};
    float l_i[2] = {0.0f, 0.0f};
    float o[8][4];
    #pragma unroll
    for (int nt = 0; nt < 8; nt++)
        #pragma unroll
        for (int r = 0; r < 4; r++) o[nt][r] = 0.0f;

    for (int kt = 0; kt < nkt; kt++) {
        const bool active = (kt * 64 <= row_min + 15);
        float s[8][4];

        CP_WAIT(1);            // K(kt) ready (V(kt) may still be in flight)
        __syncthreads();

        if (active) {
            #pragma unroll
            for (int nt = 0; nt < 8; nt++)
                #pragma unroll
                for (int r = 0; r < 4; r++) s[nt][r] = 0.0f;

            #pragma unroll
            for (int kb = 0; kb < 8; kb++) {
                unsigned af[4];
                unsigned qaddr = (unsigned)__cvta_generic_to_shared(
                    &sm[AT_QS + (warp * 16 + lrow) * 68 + kb * 8 + lkoff]);
                ldmx4(af[0], af[1], af[2], af[3], qaddr);
                #pragma unroll
                for (int nt = 0; nt < 8; nt++) {
                    unsigned b0, b1;
                    unsigned kaddr = (unsigned)__cvta_generic_to_shared(
                        &sm[AT_KS + (nt * 8 + (lane & 7)) * 68 + kb * 8 + ((lane >> 3) & 1) * 4]);
                    ldmx2(b0, b1, kaddr);
                    mma_tf32(s[nt], af, b0, b1);
                }
            }

            if (kt * 64 + 63 > row_min) {
                #pragma unroll
                for (int nt = 0; nt < 8; nt++)
                    #pragma unroll
                    for (int r = 0; r < 4; r++) {
                        int col = kt * 64 + nt * 8 + 2 * lc + (r & 1);
                        int row = row_min + lr + 8 * (r >> 1);
                        if (col > row) s[nt][r] = -1e30f;
                    }
            }

            #pragma unroll
            for (int h2 = 0; h2 < 2; h2++) {
                float rm = -1e30f;
                #pragma unroll
                for (int nt = 0; nt < 8; nt++)
                    rm = fmaxf(rm, fmaxf(s[nt][2*h2], s[nt][2*h2+1]));
                rm = fmaxf(rm, __shfl_xor_sync(0xffffffffu, rm, 1));
                rm = fmaxf(rm, __shfl_xor_sync(0xffffffffu, rm, 2));
                float mn = fmaxf(m_i[h2], rm);
                float alpha = __expf(m_i[h2] - mn);
                m_i[h2] = mn;
                float rs = 0.0f;
                #pragma unroll
                for (int nt = 0; nt < 8; nt++) {
                    float p0 = __expf(s[nt][2*h2]   - mn);
                    float p1 = __expf(s[nt][2*h2+1] - mn);
                    s[nt][2*h2]   = p0;
                    s[nt][2*h2+1] = p1;
                    rs += p0 + p1;
                }
                rs += __shfl_xor_sync(0xffffffffu, rs, 1);
                rs += __shfl_xor_sync(0xffffffffu, rs, 2);
                l_i[h2] = l_i[h2] * alpha + rs;
                #pragma unroll
                for (int nt = 0; nt < 8; nt++) {
                    o[nt][2*h2]   *= alpha;
                    o[nt][2*h2+1] *= alpha;
                }
            }
        }

        __syncthreads();       // everyone done reading K(kt)
        if (kt + 1 < nkt) {    // prefetch K(kt+1)
            #pragma unroll
            for (int j = 0; j < 4; j++) {
                int r = ldr0 + j * 16;
                cpasync16(&sm[AT_KS + r * 68 + ldc4],
                          Kb + (size_t)((kt + 1) * 64 + r) * ld + ldc4);
            }
        }
        CP_COMMIT();

        CP_WAIT(1);            // V(kt) ready (K(kt+1) may still be in flight)
        __syncthreads();

        if (active) {
            #pragma unroll
            for (int nt = 0; nt < 8; nt++)
                #pragma unroll
                for (int r = 0; r < 4; r++) {
                    int row = warp * 16 + lr + 8 * (r >> 1);
                    int col = nt * 8 + 2 * lc + (r & 1);
                    sm[AT_PS + row * 68 + col] = f2tf32f(s[nt][r]);
                }
            __syncwarp();

            #pragma unroll
            for (int kb = 0; kb < 8; kb++) {
                unsigned af[4];
                unsigned paddr = (unsigned)__cvta_generic_to_shared(
                    &sm[AT_PS + (warp * 16 + lrow) * 68 + kb * 8 + lkoff]);
                ldmx4(af[0], af[1], af[2], af[3], paddr);
                #pragma unroll
                for (int nt = 0; nt < 8; nt++) {
                    unsigned b0 = __float_as_uint(sm[AT_VS + (kb * 8 + lc)     * 72 + nt * 8 + lr]);
                    unsigned b1 = __float_as_uint(sm[AT_VS + (kb * 8 + lc + 4) * 72 + nt * 8 + lr]);
                    mma_tf32(o[nt], af, b0, b1);
                }
            }
        }

        __syncthreads();       // everyone done reading V(kt)
        if (kt + 1 < nkt) {    // prefetch V(kt+1)
            #pragma unroll
            for (int j = 0; j < 4; j++) {
                int r = ldr0 + j * 16;
                cpasync16(&sm[AT_VS + r * 72 + ldc4],
                          Vb + (size_t)((kt + 1) * 64 + r) * ld + ldc4);
            }
        }
        CP_COMMIT();
    }

    #pragma unroll
    for (int h2 = 0; h2 < 2; h2++) {
        float inv = 1.0f / l_i[h2];
        int row = qt * 128 + warp * 16 + lr + 8 * h2;
        #pragma unroll
        for (int nt = 0; nt < 8; nt++) {
            int col = nt * 8 + 2 * lc;
            *(float2*)(Ob + (size_t)row * ld + col) =
                make_float2(f2tf32f(o[nt][2*h2] * inv), f2tf32f(o[nt][2*h2+1] * inv));
        }
    }
}

// ---------------- launch ----------------
extern "C" void kernel_launch(void* const* d_in, const int* in_sizes, int n_in,
                              void* d_out, int out_size)
{
    const float* x       = (const float*)d_in[0];
    const float* w_q     = (const float*)d_in[1];
    const float* w_k     = (const float*)d_in[2];
    const float* w_v     = (const float*)d_in[3];
    const float* w_o     = (const float*)d_in[4];
    const float* alpha_p = (const float*)d_in[5];
    const float* delta_p = (const float*)d_in[6];
    const float* beta    = (const float*)d_in[7];
    const float* eta     = (const float*)d_in[8];
    const float* g1      = (const float*)d_in[9];
    const float* g2      = (const float*)d_in[10];
    const float* w_in    = (const float*)d_in[11];
    const float* b_in    = (const float*)d_in[12];
    const float* w_out   = (const float*)d_in[13];
    const float* b_out   = (const float*)d_in[14];
    float* out = (float*)d_out;

    float *xn, *y, *q, *k, *v, *ao, *x1, *xn2, *hb, *wr;
    cudaGetSymbolAddress((void**)&xn,  g_xn);
    cudaGetSymbolAddress((void**)&y,   g_y);
    cudaGetSymbolAddress((void**)&q,   g_q);
    cudaGetSymbolAddress((void**)&k,   g_k);
    cudaGetSymbolAddress((void**)&v,   g_v);
    cudaGetSymbolAddress((void**)&ao,  g_ao);
    cudaGetSymbolAddress((void**)&x1,  g_x1);
    cudaGetSymbolAddress((void**)&xn2, g_xn2);
    cudaGetSymbolAddress((void**)&hb,  g_hb);
    cudaGetSymbolAddress((void**)&wr,  g_w);

    cudaFuncSetAttribute(attn_kernel, cudaFuncAttributeMaxDynamicSharedMemorySize,
                         ATTN_SMEM_BYTES);
    cudaFuncSetAttribute(qkv_kernel, cudaFuncAttributeMaxDynamicSharedMemorySize, SMEM_GEMM);
    cudaFuncSetAttribute((const void*)tgemm_kernel<1,false>, cudaFuncAttributeMaxDynamicSharedMemorySize, SMEM_GEMM);
    cudaFuncSetAttribute((const void*)tgemm_kernel<2,true>,  cudaFuncAttributeMaxDynamicSharedMemorySize, SMEM_GEMM);
    cudaFuncSetAttribute((const void*)tgemm_kernel<3,false>, cudaFuncAttributeMaxDynamicSharedMemorySize, SMEM_GEMM);

    wtrans_kernel<<<12288, dim3(32, 8)>>>(w_q, w_k, w_v, w_o, w_in, w_out, wr);

    rmsnorm_kernel<<<BT, 256>>>(x, g1, xn, 1);
    ema_kernel<<<(BB * DD * 16) / 256, 256>>>(xn, alpha_p, delta_p, beta, eta, y);

    qkv_kernel<<<dim3(1024 / 128, BT / 128, 3), 256, SMEM_GEMM>>>(y, xn, wr, q, k, v);

    rope_kernel<<<(BB * TT * HH * 16) / 256, 256>>>(q, k, v);

    attn_kernel<<<dim3(TT / 128, BB * HH), 256, ATTN_SMEM_BYTES>>>(q, k, v, ao);

    dim3 gN1024(1024 / 128, BT / 128);
    tgemm_kernel<1,false><<<gN1024, 256, SMEM_GEMM>>>(ao, wr + 3 * 1024 * 1024, x1,
                                                      nullptr, x, 1024, 1024);

    rmsnorm_kernel<<<BT, 256>>>(x1, g2, xn2, 1);

    dim3 gN4096(4096 / 128, BT / 128);
    tgemm_kernel<2,true><<<gN4096, 256, SMEM_GEMM>>>(xn2, wr + 4 * 1024 * 1024, hb,
                                                     b_in, nullptr, 4096, 1024);
    tgemm_kernel<3,false><<<gN1024, 256, SMEM_GEMM>>>(hb, wr + 8 * 1024 * 1024, out,
                                                      b_out, x1, 1024, 4096);
}

// round 10
// speedup vs baseline: 1.3333x; 1.2004x over previous
#include <cuda_runtime.h>
#include <math.h>

#define BB 2
#define TT 2048
#define DD 1024
#define HH 16
#define HIDD 4096
#define BT (BB*TT)   // 4096 rows

// ---------------- scratch ----------------
__device__ float g_xn [BB*TT*DD];
__device__ float g_y  [BB*TT*DD];
__device__ float g_q  [BB*TT*DD];
__device__ float g_k  [BB*TT*DD];
__device__ float g_v  [BB*TT*DD];
__device__ float g_ao [BB*TT*DD];
__device__ float g_x1 [BB*TT*DD];
__device__ float g_xn2[BB*TT*DD];
__device__ float g_hb [BB*TT*HIDD];
__device__ float g_w  [12*1024*1024];   // rounded TRANSPOSED weights [n][k]
__device__ float g_e1 [BB*16*16*DD];    // ema chunk h_end   [b][g][n][d]
__device__ float g_e2 [BB*16*16*DD];    // ema chunk h_start [b][g][n][d]

// ---------------- helpers ----------------
__device__ __forceinline__ unsigned f2tf32(float x)
{
    unsigned r;
    asm("cvt.rna.tf32.f32 %0, %1;" : "=r"(r) : "f"(x));
    return r;
}
__device__ __forceinline__ float f2tf32f(float x) { return __uint_as_float(f2tf32(x)); }
__device__ __forceinline__ float4 cvt4(float4 v)
{
    return make_float4(f2tf32f(v.x), f2tf32f(v.y), f2tf32f(v.z), f2tf32f(v.w));
}

__device__ __forceinline__ void ldmx4(unsigned& a0, unsigned& a1, unsigned& a2, unsigned& a3,
                                      unsigned addr)
{
    asm volatile("ldmatrix.sync.aligned.m8n8.x4.shared.b16 {%0,%1,%2,%3}, [%4];"
                 : "=r"(a0), "=r"(a1), "=r"(a2), "=r"(a3) : "r"(addr));
}
__device__ __forceinline__ void ldmx2(unsigned& a0, unsigned& a1, unsigned addr)
{
    asm volatile("ldmatrix.sync.aligned.m8n8.x2.shared.b16 {%0,%1}, [%2];"
                 : "=r"(a0), "=r"(a1) : "r"(addr));
}
__device__ __forceinline__ void mma_tf32(float* d, const unsigned* a, unsigned b0, unsigned b1)
{
    asm volatile(
        "mma.sync.aligned.m16n8k8.row.col.f32.tf32.tf32.f32 "
        "{%0,%1,%2,%3}, {%4,%5,%6,%7}, {%8,%9}, {%0,%1,%2,%3};\n"
        : "+f"(d[0]), "+f"(d[1]), "+f"(d[2]), "+f"(d[3])
        : "r"(a[0]), "r"(a[1]), "r"(a[2]), "r"(a[3]), "r"(b0), "r"(b1));
}
__device__ __forceinline__ void cpasync16(void* smem, const void* gmem)
{
    unsigned s = (unsigned)__cvta_generic_to_shared(smem);
    asm volatile("cp.async.cg.shared.global [%0], [%1], 16;" :: "r"(s), "l"(gmem));
}
#define CP_COMMIT() asm volatile("cp.async.commit_group;")
#define CP_WAIT(n)  asm volatile("cp.async.wait_group %0;" :: "n"(n))

// ---------------- weight transpose + tf32 round ----------------
__global__ void wtrans_kernel(const float* __restrict__ wq, const float* __restrict__ wk,
                              const float* __restrict__ wv, const float* __restrict__ wo,
                              const float* __restrict__ win, const float* __restrict__ wout,
                              float* __restrict__ dst)
{
    __shared__ float tile[32][33];
    int t = blockIdx.x;
    const float* src; int K, N; size_t doff;
    if (t < 4096) {
        int m = t >> 10; t &= 1023;
        src = (m == 0) ? wq : (m == 1) ? wk : (m == 2) ? wv : wo;
        K = 1024; N = 1024; doff = (size_t)m * 1024 * 1024;
    } else if (t < 8192) {
        t -= 4096; src = win;  K = 1024; N = 4096; doff = (size_t)4 * 1024 * 1024;
    } else {
        t -= 8192; src = wout; K = 4096; N = 1024; doff = (size_t)8 * 1024 * 1024;
    }
    int ktiles = K >> 5;
    int k0 = (t % ktiles) << 5;
    int n0 = (t / ktiles) << 5;
    int tx = threadIdx.x, ty = threadIdx.y;   // (32, 8)
    #pragma unroll
    for (int j = 0; j < 4; j++)
        tile[ty + j * 8][tx] = src[(size_t)(k0 + ty + j * 8) * N + n0 + tx];
    __syncthreads();
    #pragma unroll
    for (int j = 0; j < 4; j++)
        dst[doff + (size_t)(n0 + ty + j * 8) * K + k0 + tx] = f2tf32f(tile[tx][ty + j * 8]);
}

// ---------------- rmsnorm ----------------
__global__ void rmsnorm_kernel(const float* __restrict__ x, const float* __restrict__ g,
                               float* __restrict__ out, int rnd)
{
    int row = blockIdx.x;
    int tid = threadIdx.x;
    const float4* xr = (const float4*)(x + (size_t)row * DD);
    float4 v = xr[tid];
    float s = v.x*v.x + v.y*v.y + v.z*v.z + v.w*v.w;
    #pragma unroll
    for (int o = 16; o; o >>= 1) s += __shfl_xor_sync(0xffffffffu, s, o);
    __shared__ float red[8];
    if ((tid & 31) == 0) red[tid >> 5] = s;
    __syncthreads();
    float tot = red[0]+red[1]+red[2]+red[3]+red[4]+red[5]+red[6]+red[7];
    float inv = rsqrtf(tot * (1.0f / (float)DD) + 1e-6f);
    const float4* gr = (const float4*)g;
    float4 gv = gr[tid];
    float4 o4;
    o4.x = gv.x * (v.x * inv);
    o4.y = gv.y * (v.y * inv);
    o4.z = gv.z * (v.z * inv);
    o4.w = gv.w * (v.w * inv);
    if (rnd) o4 = cvt4(o4);
    ((float4*)(out + (size_t)row * DD))[tid] = o4;
}

// ---------------- EMA chunked scan (G=16 chunks of 128 steps) ----------------
#define EG 16
#define ECH 128

// phase 1: per (b,g,n,d) partial state over chunk with h0=0
__global__ void ema1_kernel(const float* __restrict__ xn,
                            const float* __restrict__ ap, const float* __restrict__ dp,
                            const float* __restrict__ beta,
                            float* __restrict__ hend)
{
    int idx = blockIdx.x * blockDim.x + threadIdx.x;   // 2^19
    int d = idx & 1023;
    int n = (idx >> 10) & 15;
    int g = (idx >> 14) & 15;
    int b = idx >> 18;
    int dn = d * 16 + n;
    float a   = 1.0f / (1.0f + expf(-ap[dn]));
    float ddv = 1.0f / (1.0f + expf(-dp[dn]));
    float dec = 1.0f - a * ddv;
    float ab  = a * beta[dn];
    const float* xp = xn + ((size_t)b * TT + g * ECH) * DD + d;
    float h = 0.0f;
    #pragma unroll 4
    for (int t = 0; t < ECH; t++)
        h = fmaf(dec, h, ab * xp[(size_t)t * DD]);
    hend[idx] = h;   // layout [b][g][n][d]
}

// phase 2: propagate chunk-boundary states per (b,n,d)
__global__ void ema2_kernel(const float* __restrict__ hend,
                            const float* __restrict__ ap, const float* __restrict__ dp,
                            float* __restrict__ hstart)
{
    int idx = blockIdx.x * blockDim.x + threadIdx.x;   // 2^15
    int d = idx & 1023;
    int n = (idx >> 10) & 15;
    int b = idx >> 14;
    int dn = d * 16 + n;
    float a   = 1.0f / (1.0f + expf(-ap[dn]));
    float ddv = 1.0f / (1.0f + expf(-dp[dn]));
    float dec = 1.0f - a * ddv;
    float d128 = dec;
    #pragma unroll
    for (int j = 0; j < 7; j++) d128 *= d128;          // dec^128
    size_t base = ((size_t)b * EG * 16 + n) * DD + d;  // + g*16*DD steps
    float H = 0.0f;
    #pragma unroll
    for (int g = 0; g < EG; g++) {
        hstart[base + (size_t)g * 16 * DD] = H;
        H = fmaf(d128, H, hend[base + (size_t)g * 16 * DD]);
    }
}

// phase 3: per (b,g,d) thread owns all 16 n; no shfl, pipelined chains
__global__ void ema3_kernel(const float* __restrict__ xn,
                            const float* __restrict__ ap, const float* __restrict__ dp,
                            const float* __restrict__ beta, const float* __restrict__ eta,
                            const float* __restrict__ hstart,
                            float* __restrict__ y)
{
    int idx = blockIdx.x * blockDim.x + threadIdx.x;   // 2^15
    int d = idx & 1023;
    int g = (idx >> 10) & 15;
    int b = idx >> 14;
    float dec[16], ab[16], et[16], h[16];
    #pragma unroll
    for (int n = 0; n < 16; n++) {
        int dn = d * 16 + n;
        float a   = 1.0f / (1.0f + expf(-ap[dn]));
        float ddv = 1.0f / (1.0f + expf(-dp[dn]));
        dec[n] = 1.0f - a * ddv;
        ab[n]  = a * beta[dn];
        et[n]  = eta[dn];
        h[n]   = hstart[(((size_t)b * EG + g) * 16 + n) * DD + d];
    }
    const float* xp = xn + ((size_t)b * TT + g * ECH) * DD + d;
    float*       yp = y  + ((size_t)b * TT + g * ECH) * DD + d;
    #pragma unroll 2
    for (int t = 0; t < ECH; t++) {
        float u = xp[(size_t)t * DD];
        float s0 = 0.f, s1 = 0.f, s2 = 0.f, s3 = 0.f;
        #pragma unroll
        for (int n = 0; n < 16; n += 4) {
            h[n]   = fmaf(dec[n],   h[n],   ab[n]   * u);
            h[n+1] = fmaf(dec[n+1], h[n+1], ab[n+1] * u);
            h[n+2] = fmaf(dec[n+2], h[n+2], ab[n+2] * u);
            h[n+3] = fmaf(dec[n+3], h[n+3], ab[n+3] * u);
            s0 = fmaf(et[n],   h[n],   s0);
            s1 = fmaf(et[n+1], h[n+1], s1);
            s2 = fmaf(et[n+2], h[n+2], s2);
            s3 = fmaf(et[n+3], h[n+3], s3);
        }
        yp[(size_t)t * DD] = f2tf32f((s0 + s1) + (s2 + s3));
    }
}

// ---------------- RoPE (rounded output) ----------------
__global__ void rope_kernel(float* __restrict__ q, float* __restrict__ k, float* __restrict__ v)
{
    int idx = blockIdx.x * blockDim.x + threadIdx.x;
    int i = idx & 15;
    int h = (idx >> 4) & 15;
    int t = (idx >> 8) & (TT - 1);
    int b = idx >> 19;
    double fd = pow(10000.0, -(double)i / 16.0);
    float freq = (float)fd;
    float ang = (float)t * freq;
    double da = (double)ang;
    float c = (float)cos(da);
    float s = (float)sin(da);
    size_t base = ((size_t)(b * TT + t)) * DD + h * 64;
    {
        float x1 = q[base + i], x2 = q[base + 16 + i];
        q[base + i]      = f2tf32f(x1 * c - x2 * s);
        q[base + 16 + i] = f2tf32f(x2 * c + x1 * s);
    }
    {
        float x1 = k[base + i], x2 = k[base + 16 + i];
        k[base + i]      = f2tf32f(x1 * c - x2 * s);
        k[base + 16 + i] = f2tf32f(x2 * c + x1 * s);
    }
    {
        float x1 = v[base + i], x2 = v[base + 16 + i];
        v[base + i]      = f2tf32f(x1 * c - x2 * s);
        v[base + 16 + i] = f2tf32f(x2 * c + x1 * s);
    }
}

// ---------------- tf32 GEMM core: 128x128xK32, cp.async 3-stage, all-ldmatrix ---
__device__ __forceinline__ float gelu_tanh(float x)
{
    float x3 = x * x * x;
    float t = tanhf(0.7978845608028654f * (x + 0.044715f * x3));
    return 0.5f * x * (1.0f + t);
}

#define GSTAGES 3
#define TS_STRIDE (128*36)                 // one operand tile [128][36] (K=32 + pad)
#define SMEM_GEMM ((GSTAGES * 2 * TS_STRIDE) * 4)

template<int EPI, bool RND>
__device__ __forceinline__ void gemm_core(const float* __restrict__ A,
                                          const float* __restrict__ Bt,
                                          float* __restrict__ C,
                                          const float* __restrict__ bias,
                                          const float* __restrict__ resid,
                                          int N, int K, int bx, int by, float* sm)
{
    float* As = sm;                           // [GSTAGES][128][36]
    float* Bs = sm + GSTAGES * TS_STRIDE;     // [GSTAGES][128][36]

    const int tid  = threadIdx.x;
    const int lane = tid & 31;
    const int warp = tid >> 5;
    const int wm = (warp & 1) * 64;
    const int wn = (warp >> 1) * 32;
    const int lr = lane >> 2;
    const int lc = lane & 3;
    const int lrow  = lane & 15;
    const int lkoff = (lane >> 4) * 4;

    // load slots: each thread covers rows r0, r0+32, r0+64, r0+96 at col c4
    const int r0 = tid >> 3;                  // 0..31
    const int c4 = (tid & 7) << 2;            // 0..28
    const float* Abase = A  + (size_t)(by * 128 + r0) * K + c4;
    const float* Bbase = Bt + (size_t)(bx * 128 + r0) * K + c4;

    const int kt = K >> 5;

    #pragma unroll
    for (int s = 0; s < GSTAGES - 1; s++) {
        #pragma unroll
        for (int j = 0; j < 4; j++) {
            cpasync16(As + s * TS_STRIDE + (r0 + 32 * j) * 36 + c4,
                      Abase + (size_t)(32 * j) * K + s * 32);
            cpasync16(Bs + s * TS_STRIDE + (r0 + 32 * j) * 36 + c4,
                      Bbase + (size_t)(32 * j) * K + s * 32);
        }
        CP_COMMIT();
    }

    float acc[4][4][4];
    #pragma unroll
    for (int mt = 0; mt < 4; mt++)
        #pragma unroll
        for (int nt = 0; nt < 4; nt++)
            #pragma unroll
            for (int r = 0; r < 4; r++) acc[mt][nt][r] = 0.0f;

    int cb = 0, pb = GSTAGES - 1;
    for (int it = 0; it < kt; it++) {
        CP_WAIT(GSTAGES - 2);
        __syncthreads();

        int nx = it + GSTAGES - 1;
        if (nx < kt) {
            #pragma unroll
            for (int j = 0; j < 4; j++) {
                cpasync16(As + pb * TS_STRIDE + (r0 + 32 * j) * 36 + c4,
                          Abase + (size_t)(32 * j) * K + nx * 32);
                cpasync16(Bs + pb * TS_STRIDE + (r0 + 32 * j) * 36 + c4,
                          Bbase + (size_t)(32 * j) * K + nx * 32);
            }
        }
        CP_COMMIT();
        if (++pb == GSTAGES) pb = 0;

        const float* Asc = As + cb * TS_STRIDE;
        const float* Bsc = Bs + cb * TS_STRIDE;
        if (++cb == GSTAGES) cb = 0;

        #pragma unroll
        for (int kb = 0; kb < 4; kb++) {
            unsigned af[4][4];
            #pragma unroll
            for (int mt = 0; mt < 4; mt++) {
                unsigned addr = (unsigned)__cvta_generic_to_shared(
                    Asc + (wm + mt * 16 + lrow) * 36 + kb * 8 + lkoff);
                ldmx4(af[mt][0], af[mt][1], af[mt][2], af[mt][3], addr);
            }
            unsigned bf[4][2];
            #pragma unroll
            for (int nt2 = 0; nt2 < 2; nt2++) {
                unsigned q0, q1, q2, q3;
                unsigned addr = (unsigned)__cvta_generic_to_shared(
                    Bsc + (wn + nt2 * 16 + lrow) * 36 + kb * 8 + lkoff);
                ldmx4(q0, q1, q2, q3, addr);
                bf[nt2 * 2 + 0][0] = q0; bf[nt2 * 2 + 0][1] = q2;
                bf[nt2 * 2 + 1][0] = q1; bf[nt2 * 2 + 1][1] = q3;
            }
            #pragma unroll
            for (int mt = 0; mt < 4; mt++)
                #pragma unroll
                for (int nt = 0; nt < 4; nt++)
                    mma_tf32(acc[mt][nt], af[mt], bf[nt][0], bf[nt][1]);
        }
    }

    #pragma unroll
    for (int mt = 0; mt < 4; mt++) {
        #pragma unroll
        for (int nt = 0; nt < 4; nt++) {
            int row = by * 128 + wm + mt * 16 + lr;
            int col = bx * 128 + wn + nt * 8 + 2 * lc;
            #pragma unroll
            for (int half = 0; half < 2; half++) {
                int r = row + half * 8;
                size_t off = (size_t)r * N + col;
                float v0 = acc[mt][nt][half * 2 + 0];
                float v1 = acc[mt][nt][half * 2 + 1];
                if (EPI == 2 || EPI == 3) { v0 += bias[col]; v1 += bias[col + 1]; }
                if (EPI == 2) { v0 = gelu_tanh(v0); v1 = gelu_tanh(v1); }
                if (EPI == 1 || EPI == 3) { v0 += resid[off]; v1 += resid[off + 1]; }
                if (RND) { v0 = f2tf32f(v0); v1 = f2tf32f(v1); }
                *(float2*)(C + off) = make_float2(v0, v1);
            }
        }
    }
}

template<int EPI, bool RND>
__global__ __launch_bounds__(256, 2)
void tgemm_kernel(const float* __restrict__ A, const float* __restrict__ Bt,
                  float* __restrict__ C, const float* __restrict__ bias,
                  const float* __restrict__ resid, int N, int K)
{
    extern __shared__ float smg[];
    gemm_core<EPI, RND>(A, Bt, C, bias, resid, N, K, blockIdx.x, blockIdx.y, smg);
}

__global__ __launch_bounds__(256, 2)
void qkv_kernel(const float* __restrict__ y, const float* __restrict__ xn,
                const float* __restrict__ wr,
                float* __restrict__ q, float* __restrict__ k, float* __restrict__ v)
{
    extern __shared__ float smg[];
    int z = blockIdx.z;
    const float* A = (z == 2) ? xn : y;
    const float* B = wr + (size_t)z * 1024 * 1024;
    float*       C = (z == 0) ? q : (z == 1) ? k : v;
    gemm_core<0, true>(A, B, C, nullptr, nullptr, 1024, 1024, blockIdx.x, blockIdx.y, smg);
}

// ---------------- tf32 mma flash attention, BM=128, BN=64, cp.async split pipe --
#define AT_QS 0
#define AT_KS (128*68)
#define AT_VS (AT_KS + 64*68)
#define AT_PS (AT_VS + 64*72)
#define ATTN_SMEM_FLOATS (AT_PS + 128*68)
#define ATTN_SMEM_BYTES (ATTN_SMEM_FLOATS*4)

__global__ __launch_bounds__(256, 2)
void attn_kernel(const float* __restrict__ Q, const float* __restrict__ Kk,
                 const float* __restrict__ V, float* __restrict__ O)
{
    extern __shared__ float sm[];

    const int qt = blockIdx.x;
    const int bh = blockIdx.y;
    const int b = bh >> 4, h = bh & 15;
    const size_t ld = DD;
    const float* Qb = Q  + (size_t)b * TT * ld + h * 64;
    const float* Kb = Kk + (size_t)b * TT * ld + h * 64;
    const float* Vb = V  + (size_t)b * TT * ld + h * 64;
    float*       Ob = O  + (size_t)b * TT * ld + h * 64;

    const int tid  = threadIdx.x;
    const int lane = tid & 31;
    const int warp = tid >> 5;
    const int lr = lane >> 2;
    const int lc = lane & 3;
    const int lrow  = lane & 15;
    const int lkoff = (lane >> 4) * 4;

    const int nkt = 2 * qt + 2;
    const int row_min = qt * 128 + warp * 16;

    const int ldr0 = tid >> 4;
    const int ldc4 = (tid & 15) << 2;

    #pragma unroll
    for (int j = 0; j < 4; j++) {
        int r = ldr0 + j * 16;
        cpasync16(&sm[AT_KS + r * 68 + ldc4], Kb + (size_t)r * ld + ldc4);
    }
    CP_COMMIT();
    #pragma unroll
    for (int j = 0; j < 4; j++) {
        int r = ldr0 + j * 16;
        cpasync16(&sm[AT_VS + r * 72 + ldc4], Vb + (size_t)r * ld + ldc4);
    }
    CP_COMMIT();

    for (int i = tid; i < 128 * 16; i += 256) {
        int r = i >> 4, c4 = (i & 15) << 2;
        float4 qv = *(const float4*)(Qb + (size_t)(qt * 128 + r) * ld + c4);
        qv.x *= 0.125f; qv.y *= 0.125f; qv.z *= 0.125f; qv.w *= 0.125f;
        *(float4*)&sm[AT_QS + r * 68 + c4] = qv;
    }

    float m_i[2] = {-1e30f, -1e30f};
    float l_i[2] = {0.0f, 0.0f};
    float o[8][4];
    #pragma unroll
    for (int nt = 0; nt < 8; nt++)
        #pragma unroll
        for (int r = 0; r < 4; r++) o[nt][r] = 0.0f;

    for (int kt = 0; kt < nkt; kt++) {
        const bool active = (kt * 64 <= row_min + 15);
        float s[8][4];

        CP_WAIT(1);
        __syncthreads();

        if (active) {
            #pragma unroll
            for (int nt = 0; nt < 8; nt++)
                #pragma unroll
                for (int r = 0; r < 4; r++) s[nt][r] = 0.0f;

            #pragma unroll
            for (int kb = 0; kb < 8; kb++) {
                unsigned af[4];
                unsigned qaddr = (unsigned)__cvta_generic_to_shared(
                    &sm[AT_QS + (warp * 16 + lrow) * 68 + kb * 8 + lkoff]);
                ldmx4(af[0], af[1], af[2], af[3], qaddr);
                #pragma unroll
                for (int nt = 0; nt < 8; nt++) {
                    unsigned b0, b1;
                    unsigned kaddr = (unsigned)__cvta_generic_to_shared(
                        &sm[AT_KS + (nt * 8 + (lane & 7)) * 68 + kb * 8 + ((lane >> 3) & 1) * 4]);
                    ldmx2(b0, b1, kaddr);
                    mma_tf32(s[nt], af, b0, b1);
                }
            }

            if (kt * 64 + 63 > row_min) {
                #pragma unroll
                for (int nt = 0; nt < 8; nt++)
                    #pragma unroll
                    for (int r = 0; r < 4; r++) {
                        int col = kt * 64 + nt * 8 + 2 * lc + (r & 1);
                        int row = row_min + lr + 8 * (r >> 1);
                        if (col > row) s[nt][r] = -1e30f;
                    }
            }

            #pragma unroll
            for (int h2 = 0; h2 < 2; h2++) {
                float rm = -1e30f;
                #pragma unroll
                for (int nt = 0; nt < 8; nt++)
                    rm = fmaxf(rm, fmaxf(s[nt][2*h2], s[nt][2*h2+1]));
                rm = fmaxf(rm, __shfl_xor_sync(0xffffffffu, rm, 1));
                rm = fmaxf(rm, __shfl_xor_sync(0xffffffffu, rm, 2));
                float mn = fmaxf(m_i[h2], rm);
                float alpha = __expf(m_i[h2] - mn);
                m_i[h2] = mn;
                float rs = 0.0f;
                #pragma unroll
                for (int nt = 0; nt < 8; nt++) {
                    float p0 = __expf(s[nt][2*h2]   - mn);
                    float p1 = __expf(s[nt][2*h2+1] - mn);
                    s[nt][2*h2]   = p0;
                    s[nt][2*h2+1] = p1;
                    rs += p0 + p1;
                }
                rs += __shfl_xor_sync(0xffffffffu, rs, 1);
                rs += __shfl_xor_sync(0xffffffffu, rs, 2);
                l_i[h2] = l_i[h2] * alpha + rs;
                #pragma unroll
                for (int nt = 0; nt < 8; nt++) {
                    o[nt][2*h2]   *= alpha;
                    o[nt][2*h2+1] *= alpha;
                }
            }
        }

        __syncthreads();
        if (kt + 1 < nkt) {
            #pragma unroll
            for (int j = 0; j < 4; j++) {
                int r = ldr0 + j * 16;
                cpasync16(&sm[AT_KS + r * 68 + ldc4],
                          Kb + (size_t)((kt + 1) * 64 + r) * ld + ldc4);
            }
        }
        CP_COMMIT();

        CP_WAIT(1);
        __syncthreads();

        if (active) {
            #pragma unroll
            for (int nt = 0; nt < 8; nt++)
                #pragma unroll
                for (int r = 0; r < 4; r++) {
                    int row = warp * 16 + lr + 8 * (r >> 1);
                    int col = nt * 8 + 2 * lc + (r & 1);
                    sm[AT_PS + row * 68 + col] = f2tf32f(s[nt][r]);
                }
            __syncwarp();

            #pragma unroll
            for (int kb = 0; kb < 8; kb++) {
                unsigned af[4];
                unsigned paddr = (unsigned)__cvta_generic_to_shared(
                    &sm[AT_PS + (warp * 16 + lrow) * 68 + kb * 8 + lkoff]);
                ldmx4(af[0], af[1], af[2], af[3], paddr);
                #pragma unroll
                for (int nt = 0; nt < 8; nt++) {
                    unsigned b0 = __float_as_uint(sm[AT_VS + (kb * 8 + lc)     * 72 + nt * 8 + lr]);
                    unsigned b1 = __float_as_uint(sm[AT_VS + (kb * 8 + lc + 4) * 72 + nt * 8 + lr]);
                    mma_tf32(o[nt], af, b0, b1);
                }
            }
        }

        __syncthreads();
        if (kt + 1 < nkt) {
            #pragma unroll
            for (int j = 0; j < 4; j++) {
                int r = ldr0 + j * 16;
                cpasync16(&sm[AT_VS + r * 72 + ldc4],
                          Vb + (size_t)((kt + 1) * 64 + r) * ld + ldc4);
            }
        }
        CP_COMMIT();
    }

    #pragma unroll
    for (int h2 = 0; h2 < 2; h2++) {
        float inv = 1.0f / l_i[h2];
        int row = qt * 128 + warp * 16 + lr + 8 * h2;
        #pragma unroll
        for (int nt = 0; nt < 8; nt++) {
            int col = nt * 8 + 2 * lc;
            *(float2*)(Ob + (size_t)row * ld + col) =
                make_float2(f2tf32f(o[nt][2*h2] * inv), f2tf32f(o[nt][2*h2+1] * inv));
        }
    }
}

// ---------------- launch ----------------
extern "C" void kernel_launch(void* const* d_in, const int* in_sizes, int n_in,
                              void* d_out, int out_size)
{
    const float* x       = (const float*)d_in[0];
    const float* w_q     = (const float*)d_in[1];
    const float* w_k     = (const float*)d_in[2];
    const float* w_v     = (const float*)d_in[3];
    const float* w_o     = (const float*)d_in[4];
    const float* alpha_p = (const float*)d_in[5];
    const float* delta_p = (const float*)d_in[6];
    const float* beta    = (const float*)d_in[7];
    const float* eta     = (const float*)d_in[8];
    const float* g1      = (const float*)d_in[9];
    const float* g2      = (const float*)d_in[10];
    const float* w_in    = (const float*)d_in[11];
    const float* b_in    = (const float*)d_in[12];
    const float* w_out   = (const float*)d_in[13];
    const float* b_out   = (const float*)d_in[14];
    float* out = (float*)d_out;

    float *xn, *y, *q, *k, *v, *ao, *x1, *xn2, *hb, *wr, *e1, *e2;
    cudaGetSymbolAddress((void**)&xn,  g_xn);
    cudaGetSymbolAddress((void**)&y,   g_y);
    cudaGetSymbolAddress((void**)&q,   g_q);
    cudaGetSymbolAddress((void**)&k,   g_k);
    cudaGetSymbolAddress((void**)&v,   g_v);
    cudaGetSymbolAddress((void**)&ao,  g_ao);
    cudaGetSymbolAddress((void**)&x1,  g_x1);
    cudaGetSymbolAddress((void**)&xn2, g_xn2);
    cudaGetSymbolAddress((void**)&hb,  g_hb);
    cudaGetSymbolAddress((void**)&wr,  g_w);
    cudaGetSymbolAddress((void**)&e1,  g_e1);
    cudaGetSymbolAddress((void**)&e2,  g_e2);

    cudaFuncSetAttribute(attn_kernel, cudaFuncAttributeMaxDynamicSharedMemorySize,
                         ATTN_SMEM_BYTES);
    cudaFuncSetAttribute(qkv_kernel, cudaFuncAttributeMaxDynamicSharedMemorySize, SMEM_GEMM);
    cudaFuncSetAttribute((const void*)tgemm_kernel<1,false>, cudaFuncAttributeMaxDynamicSharedMemorySize, SMEM_GEMM);
    cudaFuncSetAttribute((const void*)tgemm_kernel<2,true>,  cudaFuncAttributeMaxDynamicSharedMemorySize, SMEM_GEMM);
    cudaFuncSetAttribute((const void*)tgemm_kernel<3,false>, cudaFuncAttributeMaxDynamicSharedMemorySize, SMEM_GEMM);

    wtrans_kernel<<<12288, dim3(32, 8)>>>(w_q, w_k, w_v, w_o, w_in, w_out, wr);

    rmsnorm_kernel<<<BT, 256>>>(x, g1, xn, 1);

    ema1_kernel<<<(BB * EG * 16 * DD) / 256, 256>>>(xn, alpha_p, delta_p, beta, e1);
    ema2_kernel<<<(BB * 16 * DD) / 256, 256>>>(e1, alpha_p, delta_p, e2);
    ema3_kernel<<<(BB * EG * DD) / 256, 256>>>(xn, alpha_p, delta_p, beta, eta, e2, y);

    qkv_kernel<<<dim3(1024 / 128, BT / 128, 3), 256, SMEM_GEMM>>>(y, xn, wr, q, k, v);

    rope_kernel<<<(BB * TT * HH * 16) / 256, 256>>>(q, k, v);

    attn_kernel<<<dim3(TT / 128, BB * HH), 256, ATTN_SMEM_BYTES>>>(q, k, v, ao);

    dim3 gN1024(1024 / 128, BT / 128);
    tgemm_kernel<1,false><<<gN1024, 256, SMEM_GEMM>>>(ao, wr + 3 * 1024 * 1024, x1,
                                                      nullptr, x, 1024, 1024);

    rmsnorm_kernel<<<BT, 256>>>(x1, g2, xn2, 1);

    dim3 gN4096(4096 / 128, BT / 128);
    tgemm_kernel<2,true><<<gN4096, 256, SMEM_GEMM>>>(xn2, wr + 4 * 1024 * 1024, hb,
                                                     b_in, nullptr, 4096, 1024);
    tgemm_kernel<3,false><<<gN1024, 256, SMEM_GEMM>>>(hb, wr + 8 * 1024 * 1024, out,
                                                      b_out, x1, 1024, 4096);
}

// round 11
// speedup vs baseline: 1.3900x; 1.0425x over previous
#include <cuda_runtime.h>
#include <math.h>

#define BB 2
#define TT 2048
#define DD 1024
#define HH 16
#define HIDD 4096
#define BT (BB*TT)   // 4096 rows

// ---------------- scratch ----------------
__device__ float g_xn [BB*TT*DD];
__device__ float g_y  [BB*TT*DD];
__device__ float g_q  [BB*TT*DD];
__device__ float g_k  [BB*TT*DD];
__device__ float g_v  [BB*TT*DD];
__device__ float g_ao [BB*TT*DD];
__device__ float g_x1 [BB*TT*DD];
__device__ float g_xn2[BB*TT*DD];
__device__ float g_hb [BB*TT*HIDD];
__device__ float g_w  [12*1024*1024];   // rounded TRANSPOSED weights [n][k]
__device__ float g_e1 [BB*16*16*DD];    // ema chunk h_end   [b][g][n][d]
__device__ float g_e2 [BB*16*16*DD];    // ema chunk h_start [b][g][n][d]

// ---------------- helpers ----------------
__device__ __forceinline__ unsigned f2tf32(float x)
{
    unsigned r;
    asm("cvt.rna.tf32.f32 %0, %1;" : "=r"(r) : "f"(x));
    return r;
}
__device__ __forceinline__ float f2tf32f(float x) { return __uint_as_float(f2tf32(x)); }
__device__ __forceinline__ float4 cvt4(float4 v)
{
    return make_float4(f2tf32f(v.x), f2tf32f(v.y), f2tf32f(v.z), f2tf32f(v.w));
}

__device__ __forceinline__ void ldmx4(unsigned& a0, unsigned& a1, unsigned& a2, unsigned& a3,
                                      unsigned addr)
{
    asm volatile("ldmatrix.sync.aligned.m8n8.x4.shared.b16 {%0,%1,%2,%3}, [%4];"
                 : "=r"(a0), "=r"(a1), "=r"(a2), "=r"(a3) : "r"(addr));
}
__device__ __forceinline__ void ldmx2(unsigned& a0, unsigned& a1, unsigned addr)
{
    asm volatile("ldmatrix.sync.aligned.m8n8.x2.shared.b16 {%0,%1}, [%2];"
                 : "=r"(a0), "=r"(a1) : "r"(addr));
}
__device__ __forceinline__ void mma_tf32(float* d, const unsigned* a, unsigned b0, unsigned b1)
{
    asm volatile(
        "mma.sync.aligned.m16n8k8.row.col.f32.tf32.tf32.f32 "
        "{%0,%1,%2,%3}, {%4,%5,%6,%7}, {%8,%9}, {%0,%1,%2,%3};\n"
        : "+f"(d[0]), "+f"(d[1]), "+f"(d[2]), "+f"(d[3])
        : "r"(a[0]), "r"(a[1]), "r"(a[2]), "r"(a[3]), "r"(b0), "r"(b1));
}
__device__ __forceinline__ void cpasync16(void* smem, const void* gmem)
{
    unsigned s = (unsigned)__cvta_generic_to_shared(smem);
    asm volatile("cp.async.cg.shared.global [%0], [%1], 16;" :: "r"(s), "l"(gmem));
}
#define CP_COMMIT() asm volatile("cp.async.commit_group;")
#define CP_WAIT(n)  asm volatile("cp.async.wait_group %0;" :: "n"(n))

// ---------------- weight transpose + tf32 round ----------------
__global__ void wtrans_kernel(const float* __restrict__ wq, const float* __restrict__ wk,
                              const float* __restrict__ wv, const float* __restrict__ wo,
                              const float* __restrict__ win, const float* __restrict__ wout,
                              float* __restrict__ dst)
{
    __shared__ float tile[32][33];
    int t = blockIdx.x;
    const float* src; int K, N; size_t doff;
    if (t < 4096) {
        int m = t >> 10; t &= 1023;
        src = (m == 0) ? wq : (m == 1) ? wk : (m == 2) ? wv : wo;
        K = 1024; N = 1024; doff = (size_t)m * 1024 * 1024;
    } else if (t < 8192) {
        t -= 4096; src = win;  K = 1024; N = 4096; doff = (size_t)4 * 1024 * 1024;
    } else {
        t -= 8192; src = wout; K = 4096; N = 1024; doff = (size_t)8 * 1024 * 1024;
    }
    int ktiles = K >> 5;
    int k0 = (t % ktiles) << 5;
    int n0 = (t / ktiles) << 5;
    int tx = threadIdx.x, ty = threadIdx.y;   // (32, 8)
    #pragma unroll
    for (int j = 0; j < 4; j++)
        tile[ty + j * 8][tx] = src[(size_t)(k0 + ty + j * 8) * N + n0 + tx];
    __syncthreads();
    #pragma unroll
    for (int j = 0; j < 4; j++)
        dst[doff + (size_t)(n0 + ty + j * 8) * K + k0 + tx] = f2tf32f(tile[tx][ty + j * 8]);
}

// ---------------- rmsnorm ----------------
__global__ void rmsnorm_kernel(const float* __restrict__ x, const float* __restrict__ g,
                               float* __restrict__ out, int rnd)
{
    int row = blockIdx.x;
    int tid = threadIdx.x;
    const float4* xr = (const float4*)(x + (size_t)row * DD);
    float4 v = xr[tid];
    float s = v.x*v.x + v.y*v.y + v.z*v.z + v.w*v.w;
    #pragma unroll
    for (int o = 16; o; o >>= 1) s += __shfl_xor_sync(0xffffffffu, s, o);
    __shared__ float red[8];
    if ((tid & 31) == 0) red[tid >> 5] = s;
    __syncthreads();
    float tot = red[0]+red[1]+red[2]+red[3]+red[4]+red[5]+red[6]+red[7];
    float inv = rsqrtf(tot * (1.0f / (float)DD) + 1e-6f);
    const float4* gr = (const float4*)g;
    float4 gv = gr[tid];
    float4 o4;
    o4.x = gv.x * (v.x * inv);
    o4.y = gv.y * (v.y * inv);
    o4.z = gv.z * (v.z * inv);
    o4.w = gv.w * (v.w * inv);
    if (rnd) o4 = cvt4(o4);
    ((float4*)(out + (size_t)row * DD))[tid] = o4;
}

// ---------------- EMA chunked scan (G=16 chunks of 128 steps) ----------------
#define EG 16
#define ECH 128

// phase 1: per (b,g,d) thread, all 16 n chains; h0=0; write h_end[b][g][n][d]
__global__ void ema1_kernel(const float* __restrict__ xn,
                            const float* __restrict__ ap, const float* __restrict__ dp,
                            const float* __restrict__ beta,
                            float* __restrict__ hend)
{
    int idx = blockIdx.x * blockDim.x + threadIdx.x;   // 2^15
    int d = idx & 1023;
    int g = (idx >> 10) & 15;
    int b = idx >> 14;
    float dec[16], ab[16], h[16];
    #pragma unroll
    for (int n = 0; n < 16; n++) {
        int dn = d * 16 + n;
        float a   = 1.0f / (1.0f + expf(-ap[dn]));
        float ddv = 1.0f / (1.0f + expf(-dp[dn]));
        dec[n] = 1.0f - a * ddv;
        ab[n]  = a * beta[dn];
        h[n]   = 0.0f;
    }
    const float* xp = xn + ((size_t)b * TT + g * ECH) * DD + d;
    #pragma unroll 2
    for (int t = 0; t < ECH; t++) {
        float u = xp[(size_t)t * DD];
        #pragma unroll
        for (int n = 0; n < 16; n++)
            h[n] = fmaf(dec[n], h[n], ab[n] * u);
    }
    size_t base = ((size_t)b * EG + g) * 16 * DD + d;
    #pragma unroll
    for (int n = 0; n < 16; n++)
        hend[base + (size_t)n * DD] = h[n];
}

// phase 2: propagate chunk-boundary states per (b,n,d)
__global__ void ema2_kernel(const float* __restrict__ hend,
                            const float* __restrict__ ap, const float* __restrict__ dp,
                            float* __restrict__ hstart)
{
    int idx = blockIdx.x * blockDim.x + threadIdx.x;   // 2^15
    int d = idx & 1023;
    int n = (idx >> 10) & 15;
    int b = idx >> 14;
    int dn = d * 16 + n;
    float a   = 1.0f / (1.0f + expf(-ap[dn]));
    float ddv = 1.0f / (1.0f + expf(-dp[dn]));
    float dec = 1.0f - a * ddv;
    float d128 = dec;
    #pragma unroll
    for (int j = 0; j < 7; j++) d128 *= d128;          // dec^128
    size_t base = ((size_t)b * EG * 16 + n) * DD + d;  // + g*16*DD steps
    float H = 0.0f;
    #pragma unroll
    for (int g = 0; g < EG; g++) {
        hstart[base + (size_t)g * 16 * DD] = H;
        H = fmaf(d128, H, hend[base + (size_t)g * 16 * DD]);
    }
}

// phase 3: per (b,g,d) thread owns all 16 n; no shfl, pipelined chains
__global__ void ema3_kernel(const float* __restrict__ xn,
                            const float* __restrict__ ap, const float* __restrict__ dp,
                            const float* __restrict__ beta, const float* __restrict__ eta,
                            const float* __restrict__ hstart,
                            float* __restrict__ y)
{
    int idx = blockIdx.x * blockDim.x + threadIdx.x;   // 2^15
    int d = idx & 1023;
    int g = (idx >> 10) & 15;
    int b = idx >> 14;
    float dec[16], ab[16], et[16], h[16];
    #pragma unroll
    for (int n = 0; n < 16; n++) {
        int dn = d * 16 + n;
        float a   = 1.0f / (1.0f + expf(-ap[dn]));
        float ddv = 1.0f / (1.0f + expf(-dp[dn]));
        dec[n] = 1.0f - a * ddv;
        ab[n]  = a * beta[dn];
        et[n]  = eta[dn];
        h[n]   = hstart[(((size_t)b * EG + g) * 16 + n) * DD + d];
    }
    const float* xp = xn + ((size_t)b * TT + g * ECH) * DD + d;
    float*       yp = y  + ((size_t)b * TT + g * ECH) * DD + d;
    #pragma unroll 2
    for (int t = 0; t < ECH; t++) {
        float u = xp[(size_t)t * DD];
        float s0 = 0.f, s1 = 0.f, s2 = 0.f, s3 = 0.f;
        #pragma unroll
        for (int n = 0; n < 16; n += 4) {
            h[n]   = fmaf(dec[n],   h[n],   ab[n]   * u);
            h[n+1] = fmaf(dec[n+1], h[n+1], ab[n+1] * u);
            h[n+2] = fmaf(dec[n+2], h[n+2], ab[n+2] * u);
            h[n+3] = fmaf(dec[n+3], h[n+3], ab[n+3] * u);
            s0 = fmaf(et[n],   h[n],   s0);
            s1 = fmaf(et[n+1], h[n+1], s1);
            s2 = fmaf(et[n+2], h[n+2], s2);
            s3 = fmaf(et[n+3], h[n+3], s3);
        }
        yp[(size_t)t * DD] = f2tf32f((s0 + s1) + (s2 + s3));
    }
}

// ---------------- RoPE (rounded output) ----------------
__global__ void rope_kernel(float* __restrict__ q, float* __restrict__ k, float* __restrict__ v)
{
    int idx = blockIdx.x * blockDim.x + threadIdx.x;
    int i = idx & 15;
    int h = (idx >> 4) & 15;
    int t = (idx >> 8) & (TT - 1);
    int b = idx >> 19;
    double fd = pow(10000.0, -(double)i / 16.0);
    float freq = (float)fd;
    float ang = (float)t * freq;
    double da = (double)ang;
    float c = (float)cos(da);
    float s = (float)sin(da);
    size_t base = ((size_t)(b * TT + t)) * DD + h * 64;
    {
        float x1 = q[base + i], x2 = q[base + 16 + i];
        q[base + i]      = f2tf32f(x1 * c - x2 * s);
        q[base + 16 + i] = f2tf32f(x2 * c + x1 * s);
    }
    {
        float x1 = k[base + i], x2 = k[base + 16 + i];
        k[base + i]      = f2tf32f(x1 * c - x2 * s);
        k[base + 16 + i] = f2tf32f(x2 * c + x1 * s);
    }
    {
        float x1 = v[base + i], x2 = v[base + 16 + i];
        v[base + i]      = f2tf32f(x1 * c - x2 * s);
        v[base + 16 + i] = f2tf32f(x2 * c + x1 * s);
    }
}

// ---------------- tf32 GEMM core: 128x128xK32, cp.async 3-stage, all-ldmatrix ---
__device__ __forceinline__ float gelu_tanh(float x)
{
    // tanh(z) = 1 - 2/(e^{2z}+1); exact limits at +-inf
    float z = 0.7978845608028654f * (x + 0.044715f * x * x * x);
    float e = __expf(2.0f * z);
    float t = 1.0f - 2.0f / (e + 1.0f);
    return 0.5f * x * (1.0f + t);
}

#define GSTAGES 3
#define TS_STRIDE (128*36)                 // one operand tile [128][36] (K=32 + pad)
#define SMEM_GEMM ((GSTAGES * 2 * TS_STRIDE) * 4)

template<int EPI, bool RND>
__device__ __forceinline__ void gemm_core(const float* __restrict__ A,
                                          const float* __restrict__ Bt,
                                          float* __restrict__ C,
                                          const float* __restrict__ bias,
                                          const float* __restrict__ resid,
                                          int N, int K, int bx, int by, float* sm)
{
    float* As = sm;                           // [GSTAGES][128][36]
    float* Bs = sm + GSTAGES * TS_STRIDE;     // [GSTAGES][128][36]

    const int tid  = threadIdx.x;
    const int lane = tid & 31;
    const int warp = tid >> 5;
    const int wm = (warp & 1) * 64;
    const int wn = (warp >> 1) * 32;
    const int lr = lane >> 2;
    const int lc = lane & 3;
    const int lrow  = lane & 15;
    const int lkoff = (lane >> 4) * 4;

    const int r0 = tid >> 3;                  // 0..31
    const int c4 = (tid & 7) << 2;            // 0..28
    const float* Abase = A  + (size_t)(by * 128 + r0) * K + c4;
    const float* Bbase = Bt + (size_t)(bx * 128 + r0) * K + c4;

    const int kt = K >> 5;

    #pragma unroll
    for (int s = 0; s < GSTAGES - 1; s++) {
        #pragma unroll
        for (int j = 0; j < 4; j++) {
            cpasync16(As + s * TS_STRIDE + (r0 + 32 * j) * 36 + c4,
                      Abase + (size_t)(32 * j) * K + s * 32);
            cpasync16(Bs + s * TS_STRIDE + (r0 + 32 * j) * 36 + c4,
                      Bbase + (size_t)(32 * j) * K + s * 32);
        }
        CP_COMMIT();
    }

    float acc[4][4][4];
    #pragma unroll
    for (int mt = 0; mt < 4; mt++)
        #pragma unroll
        for (int nt = 0; nt < 4; nt++)
            #pragma unroll
            for (int r = 0; r < 4; r++) acc[mt][nt][r] = 0.0f;

    int cb = 0, pb = GSTAGES - 1;
    for (int it = 0; it < kt; it++) {
        CP_WAIT(GSTAGES - 2);
        __syncthreads();

        int nx = it + GSTAGES - 1;
        if (nx < kt) {
            #pragma unroll
            for (int j = 0; j < 4; j++) {
                cpasync16(As + pb * TS_STRIDE + (r0 + 32 * j) * 36 + c4,
                          Abase + (size_t)(32 * j) * K + nx * 32);
                cpasync16(Bs + pb * TS_STRIDE + (r0 + 32 * j) * 36 + c4,
                          Bbase + (size_t)(32 * j) * K + nx * 32);
            }
        }
        CP_COMMIT();
        if (++pb == GSTAGES) pb = 0;

        const float* Asc = As + cb * TS_STRIDE;
        const float* Bsc = Bs + cb * TS_STRIDE;
        if (++cb == GSTAGES) cb = 0;

        #pragma unroll
        for (int kb = 0; kb < 4; kb++) {
            unsigned af[4][4];
            #pragma unroll
            for (int mt = 0; mt < 4; mt++) {
                unsigned addr = (unsigned)__cvta_generic_to_shared(
                    Asc + (wm + mt * 16 + lrow) * 36 + kb * 8 + lkoff);
                ldmx4(af[mt][0], af[mt][1], af[mt][2], af[mt][3], addr);
            }
            unsigned bf[4][2];
            #pragma unroll
            for (int nt2 = 0; nt2 < 2; nt2++) {
                unsigned q0, q1, q2, q3;
                unsigned addr = (unsigned)__cvta_generic_to_shared(
                    Bsc + (wn + nt2 * 16 + lrow) * 36 + kb * 8 + lkoff);
                ldmx4(q0, q1, q2, q3, addr);
                bf[nt2 * 2 + 0][0] = q0; bf[nt2 * 2 + 0][1] = q2;
                bf[nt2 * 2 + 1][0] = q1; bf[nt2 * 2 + 1][1] = q3;
            }
            #pragma unroll
            for (int mt = 0; mt < 4; mt++)
                #pragma unroll
                for (int nt = 0; nt < 4; nt++)
                    mma_tf32(acc[mt][nt], af[mt], bf[nt][0], bf[nt][1]);
        }
    }

    #pragma unroll
    for (int mt = 0; mt < 4; mt++) {
        #pragma unroll
        for (int nt = 0; nt < 4; nt++) {
            int row = by * 128 + wm + mt * 16 + lr;
            int col = bx * 128 + wn + nt * 8 + 2 * lc;
            #pragma unroll
            for (int half = 0; half < 2; half++) {
                int r = row + half * 8;
                size_t off = (size_t)r * N + col;
                float v0 = acc[mt][nt][half * 2 + 0];
                float v1 = acc[mt][nt][half * 2 + 1];
                if (EPI == 2 || EPI == 3) { v0 += bias[col]; v1 += bias[col + 1]; }
                if (EPI == 2) { v0 = gelu_tanh(v0); v1 = gelu_tanh(v1); }
                if (EPI == 1 || EPI == 3) { v0 += resid[off]; v1 += resid[off + 1]; }
                if (RND) { v0 = f2tf32f(v0); v1 = f2tf32f(v1); }
                *(float2*)(C + off) = make_float2(v0, v1);
            }
        }
    }
}

template<int EPI, bool RND>
__global__ __launch_bounds__(256, 2)
void tgemm_kernel(const float* __restrict__ A, const float* __restrict__ Bt,
                  float* __restrict__ C, const float* __restrict__ bias,
                  const float* __restrict__ resid, int N, int K)
{
    extern __shared__ float smg[];
    gemm_core<EPI, RND>(A, Bt, C, bias, resid, N, K, blockIdx.x, blockIdx.y, smg);
}

__global__ __launch_bounds__(256, 2)
void qkv_kernel(const float* __restrict__ y, const float* __restrict__ xn,
                const float* __restrict__ wr,
                float* __restrict__ q, float* __restrict__ k, float* __restrict__ v)
{
    extern __shared__ float smg[];
    int z = blockIdx.z;
    const float* A = (z == 2) ? xn : y;
    const float* B = wr + (size_t)z * 1024 * 1024;
    float*       C = (z == 0) ? q : (z == 1) ? k : v;
    gemm_core<0, true>(A, B, C, nullptr, nullptr, 1024, 1024, blockIdx.x, blockIdx.y, smg);
}

// ---------------- tf32 mma flash attention, BM=128, BN=64, paired q-tiles ------
#define AT_QS 0
#define AT_KS (128*68)
#define AT_VS (AT_KS + 64*68)
#define AT_PS (AT_VS + 64*72)
#define ATTN_SMEM_FLOATS (AT_PS + 128*68)
#define ATTN_SMEM_BYTES (ATTN_SMEM_FLOATS*4)
#define NQT (TT/128)   // 16

__global__ __launch_bounds__(256, 2)
void attn_kernel(const float* __restrict__ Q, const float* __restrict__ Kk,
                 const float* __restrict__ V, float* __restrict__ O)
{
    extern __shared__ float sm[];

    const int bh = blockIdx.y;
    const int b = bh >> 4, h = bh & 15;
    const size_t ld = DD;
    const float* Qb = Q  + (size_t)b * TT * ld + h * 64;
    const float* Kb = Kk + (size_t)b * TT * ld + h * 64;
    const float* Vb = V  + (size_t)b * TT * ld + h * 64;
    float*       Ob = O  + (size_t)b * TT * ld + h * 64;

    const int tid  = threadIdx.x;
    const int lane = tid & 31;
    const int warp = tid >> 5;
    const int lr = lane >> 2;
    const int lc = lane & 3;
    const int lrow  = lane & 15;
    const int lkoff = (lane >> 4) * 4;

    const int ldr0 = tid >> 4;
    const int ldc4 = (tid & 15) << 2;

    // two complementary q tiles: equal total work (34 inner iterations) per block
    #pragma unroll 1
    for (int pass = 0; pass < 2; pass++) {
        const int qt = pass ? (NQT - 1 - blockIdx.x) : blockIdx.x;
        const int nkt = 2 * qt + 2;
        const int row_min = qt * 128 + warp * 16;

        __syncthreads();   // previous pass fully done with smem

        // prime K(0), V(0)
        #pragma unroll
        for (int j = 0; j < 4; j++) {
            int r = ldr0 + j * 16;
            cpasync16(&sm[AT_KS + r * 68 + ldc4], Kb + (size_t)(qt * 0 + r) * ld + ldc4);
        }
        CP_COMMIT();
        #pragma unroll
        for (int j = 0; j < 4; j++) {
            int r = ldr0 + j * 16;
            cpasync16(&sm[AT_VS + r * 72 + ldc4], Vb + (size_t)r * ld + ldc4);
        }
        CP_COMMIT();

        // Q tile (scaled; already tf32-rounded, *0.125f exact)
        for (int i = tid; i < 128 * 16; i += 256) {
            int r = i >> 4, c4 = (i & 15) << 2;
            float4 qv = *(const float4*)(Qb + (size_t)(qt * 128 + r) * ld + c4);
            qv.x *= 0.125f; qv.y *= 0.125f; qv.z *= 0.125f; qv.w *= 0.125f;
            *(float4*)&sm[AT_QS + r * 68 + c4] = qv;
        }

        float m_i[2] = {-1e30f, -1e30f};
        float l_i[2] = {0.0f, 0.0f};
        float o[8][4];
        #pragma unroll
        for (int nt = 0; nt < 8; nt++)
            #pragma unroll
            for (int r = 0; r < 4; r++) o[nt][r] = 0.0f;

        for (int kt = 0; kt < nkt; kt++) {
            const bool active = (kt * 64 <= row_min + 15);
            float s[8][4];

            CP_WAIT(1);
            __syncthreads();

            if (active) {
                #pragma unroll
                for (int nt = 0; nt < 8; nt++)
                    #pragma unroll
                    for (int r = 0; r < 4; r++) s[nt][r] = 0.0f;

                #pragma unroll
                for (int kb = 0; kb < 8; kb++) {
                    unsigned af[4];
                    unsigned qaddr = (unsigned)__cvta_generic_to_shared(
                        &sm[AT_QS + (warp * 16 + lrow) * 68 + kb * 8 + lkoff]);
                    ldmx4(af[0], af[1], af[2], af[3], qaddr);
                    #pragma unroll
                    for (int nt = 0; nt < 8; nt++) {
                        unsigned b0, b1;
                        unsigned kaddr = (unsigned)__cvta_generic_to_shared(
                            &sm[AT_KS + (nt * 8 + (lane & 7)) * 68 + kb * 8 + ((lane >> 3) & 1) * 4]);
                        ldmx2(b0, b1, kaddr);
                        mma_tf32(s[nt], af, b0, b1);
                    }
                }

                if (kt * 64 + 63 > row_min) {
                    #pragma unroll
                    for (int nt = 0; nt < 8; nt++)
                        #pragma unroll
                        for (int r = 0; r < 4; r++) {
                            int col = kt * 64 + nt * 8 + 2 * lc + (r & 1);
                            int row = row_min + lr + 8 * (r >> 1);
                            if (col > row) s[nt][r] = -1e30f;
                        }
                }

                #pragma unroll
                for (int h2 = 0; h2 < 2; h2++) {
                    float rm = -1e30f;
                    #pragma unroll
                    for (int nt = 0; nt < 8; nt++)
                        rm = fmaxf(rm, fmaxf(s[nt][2*h2], s[nt][2*h2+1]));
                    rm = fmaxf(rm, __shfl_xor_sync(0xffffffffu, rm, 1));
                    rm = fmaxf(rm, __shfl_xor_sync(0xffffffffu, rm, 2));
                    float mn = fmaxf(m_i[h2], rm);
                    float alpha = __expf(m_i[h2] - mn);
                    m_i[h2] = mn;
                    float rs = 0.0f;
                    #pragma unroll
                    for (int nt = 0; nt < 8; nt++) {
                        float p0 = __expf(s[nt][2*h2]   - mn);
                        float p1 = __expf(s[nt][2*h2+1] - mn);
                        s[nt][2*h2]   = p0;
                        s[nt][2*h2+1] = p1;
                        rs += p0 + p1;
                    }
                    rs += __shfl_xor_sync(0xffffffffu, rs, 1);
                    rs += __shfl_xor_sync(0xffffffffu, rs, 2);
                    l_i[h2] = l_i[h2] * alpha + rs;
                    #pragma unroll
                    for (int nt = 0; nt < 8; nt++) {
                        o[nt][2*h2]   *= alpha;
                        o[nt][2*h2+1] *= alpha;
                    }
                }
            }

            __syncthreads();
            if (kt + 1 < nkt) {
                #pragma unroll
                for (int j = 0; j < 4; j++) {
                    int r = ldr0 + j * 16;
                    cpasync16(&sm[AT_KS + r * 68 + ldc4],
                              Kb + (size_t)((kt + 1) * 64 + r) * ld + ldc4);
                }
            }
            CP_COMMIT();

            CP_WAIT(1);
            __syncthreads();

            if (active) {
                #pragma unroll
                for (int nt = 0; nt < 8; nt++)
                    #pragma unroll
                    for (int r = 0; r < 4; r++) {
                        int row = warp * 16 + lr + 8 * (r >> 1);
                        int col = nt * 8 + 2 * lc + (r & 1);
                        sm[AT_PS + row * 68 + col] = f2tf32f(s[nt][r]);
                    }
                __syncwarp();

                #pragma unroll
                for (int kb = 0; kb < 8; kb++) {
                    unsigned af[4];
                    unsigned paddr = (unsigned)__cvta_generic_to_shared(
                        &sm[AT_PS + (warp * 16 + lrow) * 68 + kb * 8 + lkoff]);
                    ldmx4(af[0], af[1], af[2], af[3], paddr);
                    #pragma unroll
                    for (int nt = 0; nt < 8; nt++) {
                        unsigned b0 = __float_as_uint(sm[AT_VS + (kb * 8 + lc)     * 72 + nt * 8 + lr]);
                        unsigned b1 = __float_as_uint(sm[AT_VS + (kb * 8 + lc + 4) * 72 + nt * 8 + lr]);
                        mma_tf32(o[nt], af, b0, b1);
                    }
                }
            }

            __syncthreads();
            if (kt + 1 < nkt) {
                #pragma unroll
                for (int j = 0; j < 4; j++) {
                    int r = ldr0 + j * 16;
                    cpasync16(&sm[AT_VS + r * 72 + ldc4],
                              Vb + (size_t)((kt + 1) * 64 + r) * ld + ldc4);
                }
            }
            CP_COMMIT();
        }

        #pragma unroll
        for (int h2 = 0; h2 < 2; h2++) {
            float inv = 1.0f / l_i[h2];
            int row = qt * 128 + warp * 16 + lr + 8 * h2;
            #pragma unroll
            for (int nt = 0; nt < 8; nt++) {
                int col = nt * 8 + 2 * lc;
                *(float2*)(Ob + (size_t)row * ld + col) =
                    make_float2(f2tf32f(o[nt][2*h2] * inv), f2tf32f(o[nt][2*h2+1] * inv));
            }
        }
    }
}

// ---------------- launch ----------------
extern "C" void kernel_launch(void* const* d_in, const int* in_sizes, int n_in,
                              void* d_out, int out_size)
{
    const float* x       = (const float*)d_in[0];
    const float* w_q     = (const float*)d_in[1];
    const float* w_k     = (const float*)d_in[2];
    const float* w_v     = (const float*)d_in[3];
    const float* w_o     = (const float*)d_in[4];
    const float* alpha_p = (const float*)d_in[5];
    const float* delta_p = (const float*)d_in[6];
    const float* beta    = (const float*)d_in[7];
    const float* eta     = (const float*)d_in[8];
    const float* g1      = (const float*)d_in[9];
    const float* g2      = (const float*)d_in[10];
    const float* w_in    = (const float*)d_in[11];
    const float* b_in    = (const float*)d_in[12];
    const float* w_out   = (const float*)d_in[13];
    const float* b_out   = (const float*)d_in[14];
    float* out = (float*)d_out;

    float *xn, *y, *q, *k, *v, *ao, *x1, *xn2, *hb, *wr, *e1, *e2;
    cudaGetSymbolAddress((void**)&xn,  g_xn);
    cudaGetSymbolAddress((void**)&y,   g_y);
    cudaGetSymbolAddress((void**)&q,   g_q);
    cudaGetSymbolAddress((void**)&k,   g_k);
    cudaGetSymbolAddress((void**)&v,   g_v);
    cudaGetSymbolAddress((void**)&ao,  g_ao);
    cudaGetSymbolAddress((void**)&x1,  g_x1);
    cudaGetSymbolAddress((void**)&xn2, g_xn2);
    cudaGetSymbolAddress((void**)&hb,  g_hb);
    cudaGetSymbolAddress((void**)&wr,  g_w);
    cudaGetSymbolAddress((void**)&e1,  g_e1);
    cudaGetSymbolAddress((void**)&e2,  g_e2);

    cudaFuncSetAttribute(attn_kernel, cudaFuncAttributeMaxDynamicSharedMemorySize,
                         ATTN_SMEM_BYTES);
    cudaFuncSetAttribute(qkv_kernel, cudaFuncAttributeMaxDynamicSharedMemorySize, SMEM_GEMM);
    cudaFuncSetAttribute((const void*)tgemm_kernel<1,false>, cudaFuncAttributeMaxDynamicSharedMemorySize, SMEM_GEMM);
    cudaFuncSetAttribute((const void*)tgemm_kernel<2,true>,  cudaFuncAttributeMaxDynamicSharedMemorySize, SMEM_GEMM);
    cudaFuncSetAttribute((const void*)tgemm_kernel<3,false>, cudaFuncAttributeMaxDynamicSharedMemorySize, SMEM_GEMM);

    wtrans_kernel<<<12288, dim3(32, 8)>>>(w_q, w_k, w_v, w_o, w_in, w_out, wr);

    rmsnorm_kernel<<<BT, 256>>>(x, g1, xn, 1);

    ema1_kernel<<<(BB * EG * DD) / 256, 256>>>(xn, alpha_p, delta_p, beta, e1);
    ema2_kernel<<<(BB * 16 * DD) / 256, 256>>>(e1, alpha_p, delta_p, e2);
    ema3_kernel<<<(BB * EG * DD) / 256, 256>>>(xn, alpha_p, delta_p, beta, eta, e2, y);

    qkv_kernel<<<dim3(1024 / 128, BT / 128, 3), 256, SMEM_GEMM>>>(y, xn, wr, q, k, v);

    rope_kernel<<<(BB * TT * HH * 16) / 256, 256>>>(q, k, v);

    attn_kernel<<<dim3(NQT / 2, BB * HH), 256, ATTN_SMEM_BYTES>>>(q, k, v, ao);

    dim3 gN1024(1024 / 128, BT / 128);
    tgemm_kernel<1,false><<<gN1024, 256, SMEM_GEMM>>>(ao, wr + 3 * 1024 * 1024, x1,
                                                      nullptr, x, 1024, 1024);

    rmsnorm_kernel<<<BT, 256>>>(x1, g2, xn2, 1);

    dim3 gN4096(4096 / 128, BT / 128);
    tgemm_kernel<2,true><<<gN4096, 256, SMEM_GEMM>>>(xn2, wr + 4 * 1024 * 1024, hb,
                                                     b_in, nullptr, 4096, 1024);
    tgemm_kernel<3,false><<<gN1024, 256, SMEM_GEMM>>>(hb, wr + 8 * 1024 * 1024, out,
                                                      b_out, x1, 1024, 4096);
}

// round 12
// speedup vs baseline: 1.3933x; 1.0024x over previous
#include <cuda_runtime.h>
#include <math.h>

#define BB 2
#define TT 2048
#define DD 1024
#define HH 16
#define HIDD 4096
#define BT (BB*TT)   // 4096 rows

// ---------------- scratch ----------------
__device__ float g_xn [BB*TT*DD];
__device__ float g_y  [BB*TT*DD];
__device__ float g_q  [BB*TT*DD];
__device__ float g_k  [BB*TT*DD];
__device__ float g_v  [BB*TT*DD];
__device__ float g_ao [BB*TT*DD];
__device__ float g_x1 [BB*TT*DD];
__device__ float g_xn2[BB*TT*DD];
__device__ float g_hb [BB*TT*HIDD];
__device__ float g_w  [12*1024*1024];   // rounded TRANSPOSED weights [n][k]
__device__ float g_e1 [BB*16*16*DD];    // ema chunk h_end   [b][g][n][d]
__device__ float g_e2 [BB*16*16*DD];    // ema chunk h_start [b][g][n][d]
__device__ float2 g_cs[TT*16];          // rope cos/sin table [t][i]

// ---------------- helpers ----------------
__device__ __forceinline__ unsigned f2tf32(float x)
{
    unsigned r;
    asm("cvt.rna.tf32.f32 %0, %1;" : "=r"(r) : "f"(x));
    return r;
}
__device__ __forceinline__ float f2tf32f(float x) { return __uint_as_float(f2tf32(x)); }
__device__ __forceinline__ float4 cvt4(float4 v)
{
    return make_float4(f2tf32f(v.x), f2tf32f(v.y), f2tf32f(v.z), f2tf32f(v.w));
}

__device__ __forceinline__ void ldmx4(unsigned& a0, unsigned& a1, unsigned& a2, unsigned& a3,
                                      unsigned addr)
{
    asm volatile("ldmatrix.sync.aligned.m8n8.x4.shared.b16 {%0,%1,%2,%3}, [%4];"
                 : "=r"(a0), "=r"(a1), "=r"(a2), "=r"(a3) : "r"(addr));
}
__device__ __forceinline__ void ldmx2(unsigned& a0, unsigned& a1, unsigned addr)
{
    asm volatile("ldmatrix.sync.aligned.m8n8.x2.shared.b16 {%0,%1}, [%2];"
                 : "=r"(a0), "=r"(a1) : "r"(addr));
}
__device__ __forceinline__ void mma_tf32(float* d, const unsigned* a, unsigned b0, unsigned b1)
{
    asm volatile(
        "mma.sync.aligned.m16n8k8.row.col.f32.tf32.tf32.f32 "
        "{%0,%1,%2,%3}, {%4,%5,%6,%7}, {%8,%9}, {%0,%1,%2,%3};\n"
        : "+f"(d[0]), "+f"(d[1]), "+f"(d[2]), "+f"(d[3])
        : "r"(a[0]), "r"(a[1]), "r"(a[2]), "r"(a[3]), "r"(b0), "r"(b1));
}
__device__ __forceinline__ void cpasync16(void* smem, const void* gmem)
{
    unsigned s = (unsigned)__cvta_generic_to_shared(smem);
    asm volatile("cp.async.cg.shared.global [%0], [%1], 16;" :: "r"(s), "l"(gmem));
}
#define CP_COMMIT() asm volatile("cp.async.commit_group;")
#define CP_WAIT(n)  asm volatile("cp.async.wait_group %0;" :: "n"(n))

// ---------------- rope cos/sin table (exact match of prior rope math) ----------
__global__ void cstab_kernel(float2* __restrict__ cs)
{
    int idx = blockIdx.x * blockDim.x + threadIdx.x;   // TT*16
    int i = idx & 15;
    int t = idx >> 4;
    double fd = pow(10000.0, -(double)i / 16.0);
    float freq = (float)fd;
    float ang = (float)t * freq;
    double da = (double)ang;
    cs[idx] = make_float2((float)cos(da), (float)sin(da));
}

// ---------------- weight transpose + tf32 round ----------------
__global__ void wtrans_kernel(const float* __restrict__ wq, const float* __restrict__ wk,
                              const float* __restrict__ wv, const float* __restrict__ wo,
                              const float* __restrict__ win, const float* __restrict__ wout,
                              float* __restrict__ dst)
{
    __shared__ float tile[32][33];
    int t = blockIdx.x;
    const float* src; int K, N; size_t doff;
    if (t < 4096) {
        int m = t >> 10; t &= 1023;
        src = (m == 0) ? wq : (m == 1) ? wk : (m == 2) ? wv : wo;
        K = 1024; N = 1024; doff = (size_t)m * 1024 * 1024;
    } else if (t < 8192) {
        t -= 4096; src = win;  K = 1024; N = 4096; doff = (size_t)4 * 1024 * 1024;
    } else {
        t -= 8192; src = wout; K = 4096; N = 1024; doff = (size_t)8 * 1024 * 1024;
    }
    int ktiles = K >> 5;
    int k0 = (t % ktiles) << 5;
    int n0 = (t / ktiles) << 5;
    int tx = threadIdx.x, ty = threadIdx.y;   // (32, 8)
    #pragma unroll
    for (int j = 0; j < 4; j++)
        tile[ty + j * 8][tx] = src[(size_t)(k0 + ty + j * 8) * N + n0 + tx];
    __syncthreads();
    #pragma unroll
    for (int j = 0; j < 4; j++)
        dst[doff + (size_t)(n0 + ty + j * 8) * K + k0 + tx] = f2tf32f(tile[tx][ty + j * 8]);
}

// ---------------- rmsnorm ----------------
__global__ void rmsnorm_kernel(const float* __restrict__ x, const float* __restrict__ g,
                               float* __restrict__ out, int rnd)
{
    int row = blockIdx.x;
    int tid = threadIdx.x;
    const float4* xr = (const float4*)(x + (size_t)row * DD);
    float4 v = xr[tid];
    float s = v.x*v.x + v.y*v.y + v.z*v.z + v.w*v.w;
    #pragma unroll
    for (int o = 16; o; o >>= 1) s += __shfl_xor_sync(0xffffffffu, s, o);
    __shared__ float red[8];
    if ((tid & 31) == 0) red[tid >> 5] = s;
    __syncthreads();
    float tot = red[0]+red[1]+red[2]+red[3]+red[4]+red[5]+red[6]+red[7];
    float inv = rsqrtf(tot * (1.0f / (float)DD) + 1e-6f);
    const float4* gr = (const float4*)g;
    float4 gv = gr[tid];
    float4 o4;
    o4.x = gv.x * (v.x * inv);
    o4.y = gv.y * (v.y * inv);
    o4.z = gv.z * (v.z * inv);
    o4.w = gv.w * (v.w * inv);
    if (rnd) o4 = cvt4(o4);
    ((float4*)(out + (size_t)row * DD))[tid] = o4;
}

// ---------------- EMA chunked scan (G=16 chunks of 128 steps) ----------------
#define EG 16
#define ECH 128

__global__ void ema1_kernel(const float* __restrict__ xn,
                            const float* __restrict__ ap, const float* __restrict__ dp,
                            const float* __restrict__ beta,
                            float* __restrict__ hend)
{
    int idx = blockIdx.x * blockDim.x + threadIdx.x;   // 2^15
    int d = idx & 1023;
    int g = (idx >> 10) & 15;
    int b = idx >> 14;
    float dec[16], ab[16], h[16];
    #pragma unroll
    for (int n = 0; n < 16; n++) {
        int dn = d * 16 + n;
        float a   = 1.0f / (1.0f + expf(-ap[dn]));
        float ddv = 1.0f / (1.0f + expf(-dp[dn]));
        dec[n] = 1.0f - a * ddv;
        ab[n]  = a * beta[dn];
        h[n]   = 0.0f;
    }
    const float* xp = xn + ((size_t)b * TT + g * ECH) * DD + d;
    #pragma unroll 2
    for (int t = 0; t < ECH; t++) {
        float u = xp[(size_t)t * DD];
        #pragma unroll
        for (int n = 0; n < 16; n++)
            h[n] = fmaf(dec[n], h[n], ab[n] * u);
    }
    size_t base = ((size_t)b * EG + g) * 16 * DD + d;
    #pragma unroll
    for (int n = 0; n < 16; n++)
        hend[base + (size_t)n * DD] = h[n];
}

// phase 2: preload all chunk states (MLP=16), then register chain
__global__ void ema2_kernel(const float* __restrict__ hend,
                            const float* __restrict__ ap, const float* __restrict__ dp,
                            float* __restrict__ hstart)
{
    int idx = blockIdx.x * blockDim.x + threadIdx.x;   // 2^15
    int d = idx & 1023;
    int n = (idx >> 10) & 15;
    int b = idx >> 14;
    int dn = d * 16 + n;
    float a   = 1.0f / (1.0f + expf(-ap[dn]));
    float ddv = 1.0f / (1.0f + expf(-dp[dn]));
    float dec = 1.0f - a * ddv;
    float d128 = dec;
    #pragma unroll
    for (int j = 0; j < 7; j++) d128 *= d128;          // dec^128
    size_t base = ((size_t)b * EG * 16 + n) * DD + d;
    float hv[EG];
    #pragma unroll
    for (int g = 0; g < EG; g++)
        hv[g] = hend[base + (size_t)g * 16 * DD];      // independent loads
    float H = 0.0f;
    #pragma unroll
    for (int g = 0; g < EG; g++) {
        hstart[base + (size_t)g * 16 * DD] = H;
        H = fmaf(d128, H, hv[g]);
    }
}

__global__ void ema3_kernel(const float* __restrict__ xn,
                            const float* __restrict__ ap, const float* __restrict__ dp,
                            const float* __restrict__ beta, const float* __restrict__ eta,
                            const float* __restrict__ hstart,
                            float* __restrict__ y)
{
    int idx = blockIdx.x * blockDim.x + threadIdx.x;   // 2^15
    int d = idx & 1023;
    int g = (idx >> 10) & 15;
    int b = idx >> 14;
    float dec[16], ab[16], et[16], h[16];
    #pragma unroll
    for (int n = 0; n < 16; n++) {
        int dn = d * 16 + n;
        float a   = 1.0f / (1.0f + expf(-ap[dn]));
        float ddv = 1.0f / (1.0f + expf(-dp[dn]));
        dec[n] = 1.0f - a * ddv;
        ab[n]  = a * beta[dn];
        et[n]  = eta[dn];
        h[n]   = hstart[(((size_t)b * EG + g) * 16 + n) * DD + d];
    }
    const float* xp = xn + ((size_t)b * TT + g * ECH) * DD + d;
    float*       yp = y  + ((size_t)b * TT + g * ECH) * DD + d;
    #pragma unroll 2
    for (int t = 0; t < ECH; t++) {
        float u = xp[(size_t)t * DD];
        float s0 = 0.f, s1 = 0.f, s2 = 0.f, s3 = 0.f;
        #pragma unroll
        for (int n = 0; n < 16; n += 4) {
            h[n]   = fmaf(dec[n],   h[n],   ab[n]   * u);
            h[n+1] = fmaf(dec[n+1], h[n+1], ab[n+1] * u);
            h[n+2] = fmaf(dec[n+2], h[n+2], ab[n+2] * u);
            h[n+3] = fmaf(dec[n+3], h[n+3], ab[n+3] * u);
            s0 = fmaf(et[n],   h[n],   s0);
            s1 = fmaf(et[n+1], h[n+1], s1);
            s2 = fmaf(et[n+2], h[n+2], s2);
            s3 = fmaf(et[n+3], h[n+3], s3);
        }
        yp[(size_t)t * DD] = f2tf32f((s0 + s1) + (s2 + s3));
    }
}

// ---------------- tf32 GEMM core: 128x128xK32, cp.async 3-stage, all-ldmatrix ---
__device__ __forceinline__ float gelu_tanh(float x)
{
    float z = 0.7978845608028654f * (x + 0.044715f * x * x * x);
    float e = __expf(2.0f * z);
    float t = 1.0f - 2.0f / (e + 1.0f);
    return 0.5f * x * (1.0f + t);
}

#define GSTAGES 3
#define TS_STRIDE (128*36)
#define SMEM_GEMM ((GSTAGES * 2 * TS_STRIDE) * 4)

// EPI: 0 none, 1 +resid, 2 gelu(acc+bias), 3 acc+bias+resid
// RND: round output to tf32 ; ROPE: apply rope rotation in-register before write
template<int EPI, bool RND, bool ROPE>
__device__ __forceinline__ void gemm_core(const float* __restrict__ A,
                                          const float* __restrict__ Bt,
                                          float* __restrict__ C,
                                          const float* __restrict__ bias,
                                          const float* __restrict__ resid,
                                          const float2* __restrict__ cs,
                                          int N, int K, int bx, int by, float* sm)
{
    float* As = sm;
    float* Bs = sm + GSTAGES * TS_STRIDE;

    const int tid  = threadIdx.x;
    const int lane = tid & 31;
    const int warp = tid >> 5;
    const int wm = (warp & 1) * 64;
    const int wn = (warp >> 1) * 32;
    const int lr = lane >> 2;
    const int lc = lane & 3;
    const int lrow  = lane & 15;
    const int lkoff = (lane >> 4) * 4;

    const int r0 = tid >> 3;
    const int c4 = (tid & 7) << 2;
    const float* Abase = A  + (size_t)(by * 128 + r0) * K + c4;
    const float* Bbase = Bt + (size_t)(bx * 128 + r0) * K + c4;

    const int kt = K >> 5;

    #pragma unroll
    for (int s = 0; s < GSTAGES - 1; s++) {
        #pragma unroll
        for (int j = 0; j < 4; j++) {
            cpasync16(As + s * TS_STRIDE + (r0 + 32 * j) * 36 + c4,
                      Abase + (size_t)(32 * j) * K + s * 32);
            cpasync16(Bs + s * TS_STRIDE + (r0 + 32 * j) * 36 + c4,
                      Bbase + (size_t)(32 * j) * K + s * 32);
        }
        CP_COMMIT();
    }

    float acc[4][4][4];
    #pragma unroll
    for (int mt = 0; mt < 4; mt++)
        #pragma unroll
        for (int nt = 0; nt < 4; nt++)
            #pragma unroll
            for (int r = 0; r < 4; r++) acc[mt][nt][r] = 0.0f;

    int cb = 0, pb = GSTAGES - 1;
    for (int it = 0; it < kt; it++) {
        CP_WAIT(GSTAGES - 2);
        __syncthreads();

        int nx = it + GSTAGES - 1;
        if (nx < kt) {
            #pragma unroll
            for (int j = 0; j < 4; j++) {
                cpasync16(As + pb * TS_STRIDE + (r0 + 32 * j) * 36 + c4,
                          Abase + (size_t)(32 * j) * K + nx * 32);
                cpasync16(Bs + pb * TS_STRIDE + (r0 + 32 * j) * 36 + c4,
                          Bbase + (size_t)(32 * j) * K + nx * 32);
            }
        }
        CP_COMMIT();
        if (++pb == GSTAGES) pb = 0;

        const float* Asc = As + cb * TS_STRIDE;
        const float* Bsc = Bs + cb * TS_STRIDE;
        if (++cb == GSTAGES) cb = 0;

        #pragma unroll
        for (int kb = 0; kb < 4; kb++) {
            unsigned af[4][4];
            #pragma unroll
            for (int mt = 0; mt < 4; mt++) {
                unsigned addr = (unsigned)__cvta_generic_to_shared(
                    Asc + (wm + mt * 16 + lrow) * 36 + kb * 8 + lkoff);
                ldmx4(af[mt][0], af[mt][1], af[mt][2], af[mt][3], addr);
            }
            unsigned bf[4][2];
            #pragma unroll
            for (int nt2 = 0; nt2 < 2; nt2++) {
                unsigned q0, q1, q2, q3;
                unsigned addr = (unsigned)__cvta_generic_to_shared(
                    Bsc + (wn + nt2 * 16 + lrow) * 36 + kb * 8 + lkoff);
                ldmx4(q0, q1, q2, q3, addr);
                bf[nt2 * 2 + 0][0] = q0; bf[nt2 * 2 + 0][1] = q2;
                bf[nt2 * 2 + 1][0] = q1; bf[nt2 * 2 + 1][1] = q3;
            }
            #pragma unroll
            for (int mt = 0; mt < 4; mt++)
                #pragma unroll
                for (int nt = 0; nt < 4; nt++)
                    mma_tf32(acc[mt][nt], af[mt], bf[nt][0], bf[nt][1]);
        }
    }

    // rope pre-pass: rotate (nt, nt+2) pairs in-register for low half of each head
    if (ROPE && (wn & 32) == 0) {
        #pragma unroll
        for (int mt = 0; mt < 4; mt++) {
            #pragma unroll
            for (int half = 0; half < 2; half++) {
                int rr = by * 128 + wm + mt * 16 + lr + half * 8;
                int t = rr & (TT - 1);
                #pragma unroll
                for (int nt2 = 0; nt2 < 2; nt2++) {
                    #pragma unroll
                    for (int j = 0; j < 2; j++) {
                        int i = nt2 * 8 + 2 * lc + j;
                        float2 cv = cs[t * 16 + i];
                        float x1 = acc[mt][nt2][half * 2 + j];
                        float x2 = acc[mt][nt2 + 2][half * 2 + j];
                        acc[mt][nt2][half * 2 + j]     = x1 * cv.x - x2 * cv.y;
                        acc[mt][nt2 + 2][half * 2 + j] = x2 * cv.x + x1 * cv.y;
                    }
                }
            }
        }
    }

    #pragma unroll
    for (int mt = 0; mt < 4; mt++) {
        #pragma unroll
        for (int nt = 0; nt < 4; nt++) {
            int row = by * 128 + wm + mt * 16 + lr;
            int col = bx * 128 + wn + nt * 8 + 2 * lc;
            #pragma unroll
            for (int half = 0; half < 2; half++) {
                int r = row + half * 8;
                size_t off = (size_t)r * N + col;
                float v0 = acc[mt][nt][half * 2 + 0];
                float v1 = acc[mt][nt][half * 2 + 1];
                if (EPI == 2 || EPI == 3) { v0 += bias[col]; v1 += bias[col + 1]; }
                if (EPI == 2) { v0 = gelu_tanh(v0); v1 = gelu_tanh(v1); }
                if (EPI == 1 || EPI == 3) { v0 += resid[off]; v1 += resid[off + 1]; }
                if (RND) { v0 = f2tf32f(v0); v1 = f2tf32f(v1); }
                *(float2*)(C + off) = make_float2(v0, v1);
            }
        }
    }
}

template<int EPI, bool RND>
__global__ __launch_bounds__(256, 2)
void tgemm_kernel(const float* __restrict__ A, const float* __restrict__ Bt,
                  float* __restrict__ C, const float* __restrict__ bias,
                  const float* __restrict__ resid, int N, int K)
{
    extern __shared__ float smg[];
    gemm_core<EPI, RND, false>(A, Bt, C, bias, resid, nullptr, N, K,
                               blockIdx.x, blockIdx.y, smg);
}

// merged q/k/v projection with fused rope
__global__ __launch_bounds__(256, 2)
void qkv_kernel(const float* __restrict__ y, const float* __restrict__ xn,
                const float* __restrict__ wr, const float2* __restrict__ cs,
                float* __restrict__ q, float* __restrict__ k, float* __restrict__ v)
{
    extern __shared__ float smg[];
    int z = blockIdx.z;
    const float* A = (z == 2) ? xn : y;
    const float* B = wr + (size_t)z * 1024 * 1024;
    float*       C = (z == 0) ? q : (z == 1) ? k : v;
    gemm_core<0, true, true>(A, B, C, nullptr, nullptr, cs, 1024, 1024,
                             blockIdx.x, blockIdx.y, smg);
}

// ---------------- tf32 mma flash attention, BM=128, BN=64, paired q-tiles ------
#define AT_QS 0
#define AT_KS (128*68)
#define AT_VS (AT_KS + 64*68)
#define AT_PS (AT_VS + 64*72)
#define ATTN_SMEM_FLOATS (AT_PS + 128*68)
#define ATTN_SMEM_BYTES (ATTN_SMEM_FLOATS*4)
#define NQT (TT/128)   // 16

__global__ __launch_bounds__(256, 2)
void attn_kernel(const float* __restrict__ Q, const float* __restrict__ Kk,
                 const float* __restrict__ V, float* __restrict__ O)
{
    extern __shared__ float sm[];

    const int bh = blockIdx.y;
    const int b = bh >> 4, h = bh & 15;
    const size_t ld = DD;
    const float* Qb = Q  + (size_t)b * TT * ld + h * 64;
    const float* Kb = Kk + (size_t)b * TT * ld + h * 64;
    const float* Vb = V  + (size_t)b * TT * ld + h * 64;
    float*       Ob = O  + (size_t)b * TT * ld + h * 64;

    const int tid  = threadIdx.x;
    const int lane = tid & 31;
    const int warp = tid >> 5;
    const int lr = lane >> 2;
    const int lc = lane & 3;
    const int lrow  = lane & 15;
    const int lkoff = (lane >> 4) * 4;

    const int ldr0 = tid >> 4;
    const int ldc4 = (tid & 15) << 2;

    #pragma unroll 1
    for (int pass = 0; pass < 2; pass++) {
        const int qt = pass ? (NQT - 1 - blockIdx.x) : blockIdx.x;
        const int nkt = 2 * qt + 2;
        const int row_min = qt * 128 + warp * 16;

        __syncthreads();

        #pragma unroll
        for (int j = 0; j < 4; j++) {
            int r = ldr0 + j * 16;
            cpasync16(&sm[AT_KS + r * 68 + ldc4], Kb + (size_t)r * ld + ldc4);
        }
        CP_COMMIT();
        #pragma unroll
        for (int j = 0; j < 4; j++) {
            int r = ldr0 + j * 16;
            cpasync16(&sm[AT_VS + r * 72 + ldc4], Vb + (size_t)r * ld + ldc4);
        }
        CP_COMMIT();

        for (int i = tid; i < 128 * 16; i += 256) {
            int r = i >> 4, c4 = (i & 15) << 2;
            float4 qv = *(const float4*)(Qb + (size_t)(qt * 128 + r) * ld + c4);
            qv.x *= 0.125f; qv.y *= 0.125f; qv.z *= 0.125f; qv.w *= 0.125f;
            *(float4*)&sm[AT_QS + r * 68 + c4] = qv;
        }

        float m_i[2] = {-1e30f, -1e30f};
        float l_i[2] = {0.0f, 0.0f};
        float o[8][4];
        #pragma unroll
        for (int nt = 0; nt < 8; nt++)
            #pragma unroll
            for (int r = 0; r < 4; r++) o[nt][r] = 0.0f;

        for (int kt = 0; kt < nkt; kt++) {
            const bool active = (kt * 64 <= row_min + 15);
            float s[8][4];

            CP_WAIT(1);
            __syncthreads();

            if (active) {
                #pragma unroll
                for (int nt = 0; nt < 8; nt++)
                    #pragma unroll
                    for (int r = 0; r < 4; r++) s[nt][r] = 0.0f;

                #pragma unroll
                for (int kb = 0; kb < 8; kb++) {
                    unsigned af[4];
                    unsigned qaddr = (unsigned)__cvta_generic_to_shared(
                        &sm[AT_QS + (warp * 16 + lrow) * 68 + kb * 8 + lkoff]);
                    ldmx4(af[0], af[1], af[2], af[3], qaddr);
                    #pragma unroll
                    for (int nt = 0; nt < 8; nt++) {
                        unsigned b0, b1;
                        unsigned kaddr = (unsigned)__cvta_generic_to_shared(
                            &sm[AT_KS + (nt * 8 + (lane & 7)) * 68 + kb * 8 + ((lane >> 3) & 1) * 4]);
                        ldmx2(b0, b1, kaddr);
                        mma_tf32(s[nt], af, b0, b1);
                    }
                }

                if (kt * 64 + 63 > row_min) {
                    #pragma unroll
                    for (int nt = 0; nt < 8; nt++)
                        #pragma unroll
                        for (int r = 0; r < 4; r++) {
                            int col = kt * 64 + nt * 8 + 2 * lc + (r & 1);
                            int row = row_min + lr + 8 * (r >> 1);
                            if (col > row) s[nt][r] = -1e30f;
                        }
                }

                #pragma unroll
                for (int h2 = 0; h2 < 2; h2++) {
                    float rm = -1e30f;
                    #pragma unroll
                    for (int nt = 0; nt < 8; nt++)
                        rm = fmaxf(rm, fmaxf(s[nt][2*h2], s[nt][2*h2+1]));
                    rm = fmaxf(rm, __shfl_xor_sync(0xffffffffu, rm, 1));
                    rm = fmaxf(rm, __shfl_xor_sync(0xffffffffu, rm, 2));
                    float mn = fmaxf(m_i[h2], rm);
                    float alpha = __expf(m_i[h2] - mn);
                    m_i[h2] = mn;
                    float rs = 0.0f;
                    #pragma unroll
                    for (int nt = 0; nt < 8; nt++) {
                        float p0 = __expf(s[nt][2*h2]   - mn);
                        float p1 = __expf(s[nt][2*h2+1] - mn);
                        s[nt][2*h2]   = p0;
                        s[nt][2*h2+1] = p1;
                        rs += p0 + p1;
                    }
                    rs += __shfl_xor_sync(0xffffffffu, rs, 1);
                    rs += __shfl_xor_sync(0xffffffffu, rs, 2);
                    l_i[h2] = l_i[h2] * alpha + rs;
                    #pragma unroll
                    for (int nt = 0; nt < 8; nt++) {
                        o[nt][2*h2]   *= alpha;
                        o[nt][2*h2+1] *= alpha;
                    }
                }
            }

            __syncthreads();
            if (kt + 1 < nkt) {
                #pragma unroll
                for (int j = 0; j < 4; j++) {
                    int r = ldr0 + j * 16;
                    cpasync16(&sm[AT_KS + r * 68 + ldc4],
                              Kb + (size_t)((kt + 1) * 64 + r) * ld + ldc4);
                }
            }
            CP_COMMIT();

            CP_WAIT(1);
            __syncthreads();

            if (active) {
                #pragma unroll
                for (int nt = 0; nt < 8; nt++)
                    #pragma unroll
                    for (int r = 0; r < 4; r++) {
                        int row = warp * 16 + lr + 8 * (r >> 1);
                        int col = nt * 8 + 2 * lc + (r & 1);
                        sm[AT_PS + row * 68 + col] = f2tf32f(s[nt][r]);
                    }
                __syncwarp();

                #pragma unroll
                for (int kb = 0; kb < 8; kb++) {
                    unsigned af[4];
                    unsigned paddr = (unsigned)__cvta_generic_to_shared(
                        &sm[AT_PS + (warp * 16 + lrow) * 68 + kb * 8 + lkoff]);
                    ldmx4(af[0], af[1], af[2], af[3], paddr);
                    #pragma unroll
                    for (int nt = 0; nt < 8; nt++) {
                        unsigned b0 = __float_as_uint(sm[AT_VS + (kb * 8 + lc)     * 72 + nt * 8 + lr]);
                        unsigned b1 = __float_as_uint(sm[AT_VS + (kb * 8 + lc + 4) * 72 + nt * 8 + lr]);
                        mma_tf32(o[nt], af, b0, b1);
                    }
                }
            }

            __syncthreads();
            if (kt + 1 < nkt) {
                #pragma unroll
                for (int j = 0; j < 4; j++) {
                    int r = ldr0 + j * 16;
                    cpasync16(&sm[AT_VS + r * 72 + ldc4],
                              Vb + (size_t)((kt + 1) * 64 + r) * ld + ldc4);
                }
            }
            CP_COMMIT();
        }

        #pragma unroll
        for (int h2 = 0; h2 < 2; h2++) {
            float inv = 1.0f / l_i[h2];
            int row = qt * 128 + warp * 16 + lr + 8 * h2;
            #pragma unroll
            for (int nt = 0; nt < 8; nt++) {
                int col = nt * 8 + 2 * lc;
                *(float2*)(Ob + (size_t)row * ld + col) =
                    make_float2(f2tf32f(o[nt][2*h2] * inv), f2tf32f(o[nt][2*h2+1] * inv));
            }
        }
    }
}

// ---------------- launch ----------------
extern "C" void kernel_launch(void* const* d_in, const int* in_sizes, int n_in,
                              void* d_out, int out_size)
{
    const float* x       = (const float*)d_in[0];
    const float* w_q     = (const float*)d_in[1];
    const float* w_k     = (const float*)d_in[2];
    const float* w_v     = (const float*)d_in[3];
    const float* w_o     = (const float*)d_in[4];
    const float* alpha_p = (const float*)d_in[5];
    const float* delta_p = (const float*)d_in[6];
    const float* beta    = (const float*)d_in[7];
    const float* eta     = (const float*)d_in[8];
    const float* g1      = (const float*)d_in[9];
    const float* g2      = (const float*)d_in[10];
    const float* w_in    = (const float*)d_in[11];
    const float* b_in    = (const float*)d_in[12];
    const float* w_out   = (const float*)d_in[13];
    const float* b_out   = (const float*)d_in[14];
    float* out = (float*)d_out;

    float *xn, *y, *q, *k, *v, *ao, *x1, *xn2, *hb, *wr, *e1, *e2;
    float2* cs;
    cudaGetSymbolAddress((void**)&xn,  g_xn);
    cudaGetSymbolAddress((void**)&y,   g_y);
    cudaGetSymbolAddress((void**)&q,   g_q);
    cudaGetSymbolAddress((void**)&k,   g_k);
    cudaGetSymbolAddress((void**)&v,   g_v);
    cudaGetSymbolAddress((void**)&ao,  g_ao);
    cudaGetSymbolAddress((void**)&x1,  g_x1);
    cudaGetSymbolAddress((void**)&xn2, g_xn2);
    cudaGetSymbolAddress((void**)&hb,  g_hb);
    cudaGetSymbolAddress((void**)&wr,  g_w);
    cudaGetSymbolAddress((void**)&e1,  g_e1);
    cudaGetSymbolAddress((void**)&e2,  g_e2);
    cudaGetSymbolAddress((void**)&cs,  g_cs);

    cudaFuncSetAttribute(attn_kernel, cudaFuncAttributeMaxDynamicSharedMemorySize,
                         ATTN_SMEM_BYTES);
    cudaFuncSetAttribute(qkv_kernel, cudaFuncAttributeMaxDynamicSharedMemorySize, SMEM_GEMM);
    cudaFuncSetAttribute((const void*)tgemm_kernel<1,false>, cudaFuncAttributeMaxDynamicSharedMemorySize, SMEM_GEMM);
    cudaFuncSetAttribute((const void*)tgemm_kernel<2,true>,  cudaFuncAttributeMaxDynamicSharedMemorySize, SMEM_GEMM);
    cudaFuncSetAttribute((const void*)tgemm_kernel<3,false>, cudaFuncAttributeMaxDynamicSharedMemorySize, SMEM_GEMM);

    wtrans_kernel<<<12288, dim3(32, 8)>>>(w_q, w_k, w_v, w_o, w_in, w_out, wr);
    cstab_kernel<<<(TT * 16) / 256, 256>>>(cs);

    rmsnorm_kernel<<<BT, 256>>>(x, g1, xn, 1);

    ema1_kernel<<<(BB * EG * DD) / 256, 256>>>(xn, alpha_p, delta_p, beta, e1);
    ema2_kernel<<<(BB * 16 * DD) / 256, 256>>>(e1, alpha_p, delta_p, e2);
    ema3_kernel<<<(BB * EG * DD) / 256, 256>>>(xn, alpha_p, delta_p, beta, eta, e2, y);

    qkv_kernel<<<dim3(1024 / 128, BT / 128, 3), 256, SMEM_GEMM>>>(y, xn, wr, cs, q, k, v);

    attn_kernel<<<dim3(NQT / 2, BB * HH), 256, ATTN_SMEM_BYTES>>>(q, k, v, ao);

    dim3 gN1024(1024 / 128, BT / 128);
    tgemm_kernel<1,false><<<gN1024, 256, SMEM_GEMM>>>(ao, wr + 3 * 1024 * 1024, x1,
                                                      nullptr, x, 1024, 1024);

    rmsnorm_kernel<<<BT, 256>>>(x1, g2, xn2, 1);

    dim3 gN4096(4096 / 128, BT / 128);
    tgemm_kernel<2,true><<<gN4096, 256, SMEM_GEMM>>>(xn2, wr + 4 * 1024 * 1024, hb,
                                                     b_in, nullptr, 4096, 1024);
    tgemm_kernel<3,false><<<gN1024, 256, SMEM_GEMM>>>(hb, wr + 8 * 1024 * 1024, out,
                                                      b_out, x1, 1024, 4096);
}

// round 13
// speedup vs baseline: 1.3942x; 1.0006x over previous
#include <cuda_runtime.h>
#include <math.h>

#define BB 2
#define TT 2048
#define DD 1024
#define HH 16
#define HIDD 4096
#define BT (BB*TT)   // 4096 rows

// ---------------- scratch ----------------
__device__ float g_xn [BB*TT*DD];
__device__ float g_y  [BB*TT*DD];
__device__ float g_q  [BB*TT*DD];
__device__ float g_k  [BB*TT*DD];
__device__ float g_v  [BB*TT*DD];
__device__ float g_ao [BB*TT*DD];
__device__ float g_x1 [BB*TT*DD];
__device__ float g_xn2[BB*TT*DD];
__device__ float g_hb [BB*TT*HIDD];
__device__ float g_w  [12*1024*1024];   // rounded TRANSPOSED weights [n][k]
__device__ float g_e1 [BB*64*16*DD];    // ema chunk h_end   [b][g][n][d]
__device__ float g_e2 [BB*64*16*DD];    // ema chunk h_start [b][g][n][d]
__device__ float2 g_cs[TT*16];          // rope cos/sin table [t][i]

// ---------------- helpers ----------------
__device__ __forceinline__ unsigned f2tf32(float x)
{
    unsigned r;
    asm("cvt.rna.tf32.f32 %0, %1;" : "=r"(r) : "f"(x));
    return r;
}
__device__ __forceinline__ float f2tf32f(float x) { return __uint_as_float(f2tf32(x)); }
__device__ __forceinline__ float4 cvt4(float4 v)
{
    return make_float4(f2tf32f(v.x), f2tf32f(v.y), f2tf32f(v.z), f2tf32f(v.w));
}

__device__ __forceinline__ void ldmx4(unsigned& a0, unsigned& a1, unsigned& a2, unsigned& a3,
                                      unsigned addr)
{
    asm volatile("ldmatrix.sync.aligned.m8n8.x4.shared.b16 {%0,%1,%2,%3}, [%4];"
                 : "=r"(a0), "=r"(a1), "=r"(a2), "=r"(a3) : "r"(addr));
}
__device__ __forceinline__ void ldmx2(unsigned& a0, unsigned& a1, unsigned addr)
{
    asm volatile("ldmatrix.sync.aligned.m8n8.x2.shared.b16 {%0,%1}, [%2];"
                 : "=r"(a0), "=r"(a1) : "r"(addr));
}
__device__ __forceinline__ void mma_tf32(float* d, const unsigned* a, unsigned b0, unsigned b1)
{
    asm volatile(
        "mma.sync.aligned.m16n8k8.row.col.f32.tf32.tf32.f32 "
        "{%0,%1,%2,%3}, {%4,%5,%6,%7}, {%8,%9}, {%0,%1,%2,%3};\n"
        : "+f"(d[0]), "+f"(d[1]), "+f"(d[2]), "+f"(d[3])
        : "r"(a[0]), "r"(a[1]), "r"(a[2]), "r"(a[3]), "r"(b0), "r"(b1));
}
__device__ __forceinline__ void cpasync16(void* smem, const void* gmem)
{
    unsigned s = (unsigned)__cvta_generic_to_shared(smem);
    asm volatile("cp.async.cg.shared.global [%0], [%1], 16;" :: "r"(s), "l"(gmem));
}
#define CP_COMMIT() asm volatile("cp.async.commit_group;")
#define CP_WAIT(n)  asm volatile("cp.async.wait_group %0;" :: "n"(n))

// ---------------- rope cos/sin table ----------------
__global__ void cstab_kernel(float2* __restrict__ cs)
{
    int idx = blockIdx.x * blockDim.x + threadIdx.x;   // TT*16
    int i = idx & 15;
    int t = idx >> 4;
    double fd = pow(10000.0, -(double)i / 16.0);
    float freq = (float)fd;
    float ang = (float)t * freq;
    double da = (double)ang;
    cs[idx] = make_float2((float)cos(da), (float)sin(da));
}

// ---------------- weight transpose + tf32 round ----------------
__global__ void wtrans_kernel(const float* __restrict__ wq, const float* __restrict__ wk,
                              const float* __restrict__ wv, const float* __restrict__ wo,
                              const float* __restrict__ win, const float* __restrict__ wout,
                              float* __restrict__ dst)
{
    __shared__ float tile[32][33];
    int t = blockIdx.x;
    const float* src; int K, N; size_t doff;
    if (t < 4096) {
        int m = t >> 10; t &= 1023;
        src = (m == 0) ? wq : (m == 1) ? wk : (m == 2) ? wv : wo;
        K = 1024; N = 1024; doff = (size_t)m * 1024 * 1024;
    } else if (t < 8192) {
        t -= 4096; src = win;  K = 1024; N = 4096; doff = (size_t)4 * 1024 * 1024;
    } else {
        t -= 8192; src = wout; K = 4096; N = 1024; doff = (size_t)8 * 1024 * 1024;
    }
    int ktiles = K >> 5;
    int k0 = (t % ktiles) << 5;
    int n0 = (t / ktiles) << 5;
    int tx = threadIdx.x, ty = threadIdx.y;   // (32, 8)
    #pragma unroll
    for (int j = 0; j < 4; j++)
        tile[ty + j * 8][tx] = src[(size_t)(k0 + ty + j * 8) * N + n0 + tx];
    __syncthreads();
    #pragma unroll
    for (int j = 0; j < 4; j++)
        dst[doff + (size_t)(n0 + ty + j * 8) * K + k0 + tx] = f2tf32f(tile[tx][ty + j * 8]);
}

// ---------------- rmsnorm ----------------
__global__ void rmsnorm_kernel(const float* __restrict__ x, const float* __restrict__ g,
                               float* __restrict__ out, int rnd)
{
    int row = blockIdx.x;
    int tid = threadIdx.x;
    const float4* xr = (const float4*)(x + (size_t)row * DD);
    float4 v = xr[tid];
    float s = v.x*v.x + v.y*v.y + v.z*v.z + v.w*v.w;
    #pragma unroll
    for (int o = 16; o; o >>= 1) s += __shfl_xor_sync(0xffffffffu, s, o);
    __shared__ float red[8];
    if ((tid & 31) == 0) red[tid >> 5] = s;
    __syncthreads();
    float tot = red[0]+red[1]+red[2]+red[3]+red[4]+red[5]+red[6]+red[7];
    float inv = rsqrtf(tot * (1.0f / (float)DD) + 1e-6f);
    const float4* gr = (const float4*)g;
    float4 gv = gr[tid];
    float4 o4;
    o4.x = gv.x * (v.x * inv);
    o4.y = gv.y * (v.y * inv);
    o4.z = gv.z * (v.z * inv);
    o4.w = gv.w * (v.w * inv);
    if (rnd) o4 = cvt4(o4);
    ((float4*)(out + (size_t)row * DD))[tid] = o4;
}

// ---------------- EMA chunked scan (G=64 chunks of 32 steps) ----------------
#define EG 64
#define ECH 32

// phase 1: per (b,g,d) thread, all 16 n chains; h0=0; write h_end[b][g][n][d]
__global__ void ema1_kernel(const float* __restrict__ xn,
                            const float* __restrict__ ap, const float* __restrict__ dp,
                            const float* __restrict__ beta,
                            float* __restrict__ hend)
{
    int idx = blockIdx.x * blockDim.x + threadIdx.x;   // 2^17
    int d = idx & 1023;
    int g = (idx >> 10) & (EG - 1);
    int b = idx >> 16;
    float dec[16], ab[16], h[16];
    #pragma unroll
    for (int n = 0; n < 16; n++) {
        int dn = d * 16 + n;
        float a   = 1.0f / (1.0f + expf(-ap[dn]));
        float ddv = 1.0f / (1.0f + expf(-dp[dn]));
        dec[n] = 1.0f - a * ddv;
        ab[n]  = a * beta[dn];
        h[n]   = 0.0f;
    }
    const float* xp = xn + ((size_t)b * TT + g * ECH) * DD + d;
    #pragma unroll 4
    for (int t = 0; t < ECH; t++) {
        float u = xp[(size_t)t * DD];
        #pragma unroll
        for (int n = 0; n < 16; n++)
            h[n] = fmaf(dec[n], h[n], ab[n] * u);
    }
    size_t base = ((size_t)b * EG + g) * 16 * DD + d;
    #pragma unroll
    for (int n = 0; n < 16; n++)
        hend[base + (size_t)n * DD] = h[n];
}

// phase 2: propagate chunk-boundary states per (b,n,d); preload groups of 16
__global__ void ema2_kernel(const float* __restrict__ hend,
                            const float* __restrict__ ap, const float* __restrict__ dp,
                            float* __restrict__ hstart)
{
    int idx = blockIdx.x * blockDim.x + threadIdx.x;   // 2^15
    int d = idx & 1023;
    int n = (idx >> 10) & 15;
    int b = idx >> 14;
    int dn = d * 16 + n;
    float a   = 1.0f / (1.0f + expf(-ap[dn]));
    float ddv = 1.0f / (1.0f + expf(-dp[dn]));
    float dec = 1.0f - a * ddv;
    float dch = dec;
    #pragma unroll
    for (int j = 0; j < 5; j++) dch *= dch;            // dec^32
    size_t base = ((size_t)b * EG * 16 + n) * DD + d;  // + g*16*DD steps
    float H = 0.0f;
    #pragma unroll
    for (int gg = 0; gg < EG; gg += 16) {
        float hv[16];
        #pragma unroll
        for (int j = 0; j < 16; j++)
            hv[j] = hend[base + (size_t)(gg + j) * 16 * DD];   // MLP=16
        #pragma unroll
        for (int j = 0; j < 16; j++) {
            hstart[base + (size_t)(gg + j) * 16 * DD] = H;
            H = fmaf(dch, H, hv[j]);
        }
    }
}

// phase 3: per (b,g,d) thread owns all 16 n
__global__ void ema3_kernel(const float* __restrict__ xn,
                            const float* __restrict__ ap, const float* __restrict__ dp,
                            const float* __restrict__ beta, const float* __restrict__ eta,
                            const float* __restrict__ hstart,
                            float* __restrict__ y)
{
    int idx = blockIdx.x * blockDim.x + threadIdx.x;   // 2^17
    int d = idx & 1023;
    int g = (idx >> 10) & (EG - 1);
    int b = idx >> 16;
    float dec[16], ab[16], et[16], h[16];
    #pragma unroll
    for (int n = 0; n < 16; n++) {
        int dn = d * 16 + n;
        float a   = 1.0f / (1.0f + expf(-ap[dn]));
        float ddv = 1.0f / (1.0f + expf(-dp[dn]));
        dec[n] = 1.0f - a * ddv;
        ab[n]  = a * beta[dn];
        et[n]  = eta[dn];
        h[n]   = hstart[(((size_t)b * EG + g) * 16 + n) * DD + d];
    }
    const float* xp = xn + ((size_t)b * TT + g * ECH) * DD + d;
    float*       yp = y  + ((size_t)b * TT + g * ECH) * DD + d;
    #pragma unroll 4
    for (int t = 0; t < ECH; t++) {
        float u = xp[(size_t)t * DD];
        float s0 = 0.f, s1 = 0.f, s2 = 0.f, s3 = 0.f;
        #pragma unroll
        for (int n = 0; n < 16; n += 4) {
            h[n]   = fmaf(dec[n],   h[n],   ab[n]   * u);
            h[n+1] = fmaf(dec[n+1], h[n+1], ab[n+1] * u);
            h[n+2] = fmaf(dec[n+2], h[n+2], ab[n+2] * u);
            h[n+3] = fmaf(dec[n+3], h[n+3], ab[n+3] * u);
            s0 = fmaf(et[n],   h[n],   s0);
            s1 = fmaf(et[n+1], h[n+1], s1);
            s2 = fmaf(et[n+2], h[n+2], s2);
            s3 = fmaf(et[n+3], h[n+3], s3);
        }
        yp[(size_t)t * DD] = f2tf32f((s0 + s1) + (s2 + s3));
    }
}

// ---------------- tf32 GEMM core: 128x128xK32, cp.async 3-stage, all-ldmatrix ---
__device__ __forceinline__ float gelu_tanh(float x)
{
    float z = 0.7978845608028654f * (x + 0.044715f * x * x * x);
    float e = __expf(2.0f * z);
    float t = 1.0f - 2.0f / (e + 1.0f);
    return 0.5f * x * (1.0f + t);
}

#define GSTAGES 3
#define TS_STRIDE (128*36)
#define SMEM_GEMM ((GSTAGES * 2 * TS_STRIDE) * 4)

template<int EPI, bool RND, bool ROPE>
__device__ __forceinline__ void gemm_core(const float* __restrict__ A,
                                          const float* __restrict__ Bt,
                                          float* __restrict__ C,
                                          const float* __restrict__ bias,
                                          const float* __restrict__ resid,
                                          const float2* __restrict__ cs,
                                          int N, int K, int bx, int by, float* sm)
{
    float* As = sm;
    float* Bs = sm + GSTAGES * TS_STRIDE;

    const int tid  = threadIdx.x;
    const int lane = tid & 31;
    const int warp = tid >> 5;
    const int wm = (warp & 1) * 64;
    const int wn = (warp >> 1) * 32;
    const int lr = lane >> 2;
    const int lc = lane & 3;
    const int lrow  = lane & 15;
    const int lkoff = (lane >> 4) * 4;

    const int r0 = tid >> 3;
    const int c4 = (tid & 7) << 2;
    const float* Abase = A  + (size_t)(by * 128 + r0) * K + c4;
    const float* Bbase = Bt + (size_t)(bx * 128 + r0) * K + c4;

    const int kt = K >> 5;

    #pragma unroll
    for (int s = 0; s < GSTAGES - 1; s++) {
        #pragma unroll
        for (int j = 0; j < 4; j++) {
            cpasync16(As + s * TS_STRIDE + (r0 + 32 * j) * 36 + c4,
                      Abase + (size_t)(32 * j) * K + s * 32);
            cpasync16(Bs + s * TS_STRIDE + (r0 + 32 * j) * 36 + c4,
                      Bbase + (size_t)(32 * j) * K + s * 32);
        }
        CP_COMMIT();
    }

    float acc[4][4][4];
    #pragma unroll
    for (int mt = 0; mt < 4; mt++)
        #pragma unroll
        for (int nt = 0; nt < 4; nt++)
            #pragma unroll
            for (int r = 0; r < 4; r++) acc[mt][nt][r] = 0.0f;

    int cb = 0, pb = GSTAGES - 1;
    for (int it = 0; it < kt; it++) {
        CP_WAIT(GSTAGES - 2);
        __syncthreads();

        int nx = it + GSTAGES - 1;
        if (nx < kt) {
            #pragma unroll
            for (int j = 0; j < 4; j++) {
                cpasync16(As + pb * TS_STRIDE + (r0 + 32 * j) * 36 + c4,
                          Abase + (size_t)(32 * j) * K + nx * 32);
                cpasync16(Bs + pb * TS_STRIDE + (r0 + 32 * j) * 36 + c4,
                          Bbase + (size_t)(32 * j) * K + nx * 32);
            }
        }
        CP_COMMIT();
        if (++pb == GSTAGES) pb = 0;

        const float* Asc = As + cb * TS_STRIDE;
        const float* Bsc = Bs + cb * TS_STRIDE;
        if (++cb == GSTAGES) cb = 0;

        #pragma unroll
        for (int kb = 0; kb < 4; kb++) {
            unsigned af[4][4];
            #pragma unroll
            for (int mt = 0; mt < 4; mt++) {
                unsigned addr = (unsigned)__cvta_generic_to_shared(
                    Asc + (wm + mt * 16 + lrow) * 36 + kb * 8 + lkoff);
                ldmx4(af[mt][0], af[mt][1], af[mt][2], af[mt][3], addr);
            }
            unsigned bf[4][2];
            #pragma unroll
            for (int nt2 = 0; nt2 < 2; nt2++) {
                unsigned q0, q1, q2, q3;
                unsigned addr = (unsigned)__cvta_generic_to_shared(
                    Bsc + (wn + nt2 * 16 + lrow) * 36 + kb * 8 + lkoff);
                ldmx4(q0, q1, q2, q3, addr);
                bf[nt2 * 2 + 0][0] = q0; bf[nt2 * 2 + 0][1] = q2;
                bf[nt2 * 2 + 1][0] = q1; bf[nt2 * 2 + 1][1] = q3;
            }
            #pragma unroll
            for (int mt = 0; mt < 4; mt++)
                #pragma unroll
                for (int nt = 0; nt < 4; nt++)
                    mma_tf32(acc[mt][nt], af[mt], bf[nt][0], bf[nt][1]);
        }
    }

    if (ROPE && (wn & 32) == 0) {
        #pragma unroll
        for (int mt = 0; mt < 4; mt++) {
            #pragma unroll
            for (int half = 0; half < 2; half++) {
                int rr = by * 128 + wm + mt * 16 + lr + half * 8;
                int t = rr & (TT - 1);
                #pragma unroll
                for (int nt2 = 0; nt2 < 2; nt2++) {
                    #pragma unroll
                    for (int j = 0; j < 2; j++) {
                        int i = nt2 * 8 + 2 * lc + j;
                        float2 cv = cs[t * 16 + i];
                        float x1 = acc[mt][nt2][half * 2 + j];
                        float x2 = acc[mt][nt2 + 2][half * 2 + j];
                        acc[mt][nt2][half * 2 + j]     = x1 * cv.x - x2 * cv.y;
                        acc[mt][nt2 + 2][half * 2 + j] = x2 * cv.x + x1 * cv.y;
                    }
                }
            }
        }
    }

    #pragma unroll
    for (int mt = 0; mt < 4; mt++) {
        #pragma unroll
        for (int nt = 0; nt < 4; nt++) {
            int row = by * 128 + wm + mt * 16 + lr;
            int col = bx * 128 + wn + nt * 8 + 2 * lc;
            #pragma unroll
            for (int half = 0; half < 2; half++) {
                int r = row + half * 8;
                size_t off = (size_t)r * N + col;
                float v0 = acc[mt][nt][half * 2 + 0];
                float v1 = acc[mt][nt][half * 2 + 1];
                if (EPI == 2 || EPI == 3) { v0 += bias[col]; v1 += bias[col + 1]; }
                if (EPI == 2) { v0 = gelu_tanh(v0); v1 = gelu_tanh(v1); }
                if (EPI == 1 || EPI == 3) { v0 += resid[off]; v1 += resid[off + 1]; }
                if (RND) { v0 = f2tf32f(v0); v1 = f2tf32f(v1); }
                *(float2*)(C + off) = make_float2(v0, v1);
            }
        }
    }
}

template<int EPI, bool RND>
__global__ __launch_bounds__(256, 2)
void tgemm_kernel(const float* __restrict__ A, const float* __restrict__ Bt,
                  float* __restrict__ C, const float* __restrict__ bias,
                  const float* __restrict__ resid, int N, int K)
{
    extern __shared__ float smg[];
    gemm_core<EPI, RND, false>(A, Bt, C, bias, resid, nullptr, N, K,
                               blockIdx.x, blockIdx.y, smg);
}

__global__ __launch_bounds__(256, 2)
void qkv_kernel(const float* __restrict__ y, const float* __restrict__ xn,
                const float* __restrict__ wr, const float2* __restrict__ cs,
                float* __restrict__ q, float* __restrict__ k, float* __restrict__ v)
{
    extern __shared__ float smg[];
    int z = blockIdx.z;
    const float* A = (z == 2) ? xn : y;
    const float* B = wr + (size_t)z * 1024 * 1024;
    float*       C = (z == 0) ? q : (z == 1) ? k : v;
    gemm_core<0, true, true>(A, B, C, nullptr, nullptr, cs, 1024, 1024,
                             blockIdx.x, blockIdx.y, smg);
}

// ---------------- tf32 mma flash attention, BM=128, BN=64, paired q-tiles ------
#define AT_QS 0
#define AT_KS (128*68)
#define AT_VS (AT_KS + 64*68)
#define AT_PS (AT_VS + 64*72)
#define ATTN_SMEM_FLOATS (AT_PS + 128*68)
#define ATTN_SMEM_BYTES (ATTN_SMEM_FLOATS*4)
#define NQT (TT/128)   // 16

__global__ __launch_bounds__(256, 2)
void attn_kernel(const float* __restrict__ Q, const float* __restrict__ Kk,
                 const float* __restrict__ V, float* __restrict__ O)
{
    extern __shared__ float sm[];

    const int bh = blockIdx.y;
    const int b = bh >> 4, h = bh & 15;
    const size_t ld = DD;
    const float* Qb = Q  + (size_t)b * TT * ld + h * 64;
    const float* Kb = Kk + (size_t)b * TT * ld + h * 64;
    const float* Vb = V  + (size_t)b * TT * ld + h * 64;
    float*       Ob = O  + (size_t)b * TT * ld + h * 64;

    const int tid  = threadIdx.x;
    const int lane = tid & 31;
    const int warp = tid >> 5;
    const int lr = lane >> 2;
    const int lc = lane & 3;
    const int lrow  = lane & 15;
    const int lkoff = (lane >> 4) * 4;

    const int ldr0 = tid >> 4;
    const int ldc4 = (tid & 15) << 2;

    #pragma unroll 1
    for (int pass = 0; pass < 2; pass++) {
        const int qt = pass ? (NQT - 1 - blockIdx.x) : blockIdx.x;
        const int nkt = 2 * qt + 2;
        const int row_min = qt * 128 + warp * 16;

        __syncthreads();

        #pragma unroll
        for (int j = 0; j < 4; j++) {
            int r = ldr0 + j * 16;
            cpasync16(&sm[AT_KS + r * 68 + ldc4], Kb + (size_t)r * ld + ldc4);
        }
        CP_COMMIT();
        #pragma unroll
        for (int j = 0; j < 4; j++) {
            int r = ldr0 + j * 16;
            cpasync16(&sm[AT_VS + r * 72 + ldc4], Vb + (size_t)r * ld + ldc4);
        }
        CP_COMMIT();

        for (int i = tid; i < 128 * 16; i += 256) {
            int r = i >> 4, c4 = (i & 15) << 2;
            float4 qv = *(const float4*)(Qb + (size_t)(qt * 128 + r) * ld + c4);
            qv.x *= 0.125f; qv.y *= 0.125f; qv.z *= 0.125f; qv.w *= 0.125f;
            *(float4*)&sm[AT_QS + r * 68 + c4] = qv;
        }

        float m_i[2] = {-1e30f, -1e30f};
        float l_i[2] = {0.0f, 0.0f};
        float o[8][4];
        #pragma unroll
        for (int nt = 0; nt < 8; nt++)
            #pragma unroll
            for (int r = 0; r < 4; r++) o[nt][r] = 0.0f;

        for (int kt = 0; kt < nkt; kt++) {
            const bool active = (kt * 64 <= row_min + 15);
            float s[8][4];

            CP_WAIT(1);
            __syncthreads();

            if (active) {
                #pragma unroll
                for (int nt = 0; nt < 8; nt++)
                    #pragma unroll
                    for (int r = 0; r < 4; r++) s[nt][r] = 0.0f;

                #pragma unroll
                for (int kb = 0; kb < 8; kb++) {
                    unsigned af[4];
                    unsigned qaddr = (unsigned)__cvta_generic_to_shared(
                        &sm[AT_QS + (warp * 16 + lrow) * 68 + kb * 8 + lkoff]);
                    ldmx4(af[0], af[1], af[2], af[3], qaddr);
                    #pragma unroll
                    for (int nt = 0; nt < 8; nt++) {
                        unsigned b0, b1;
                        unsigned kaddr = (unsigned)__cvta_generic_to_shared(
                            &sm[AT_KS + (nt * 8 + (lane & 7)) * 68 + kb * 8 + ((lane >> 3) & 1) * 4]);
                        ldmx2(b0, b1, kaddr);
                        mma_tf32(s[nt], af, b0, b1);
                    }
                }

                if (kt * 64 + 63 > row_min) {
                    #pragma unroll
                    for (int nt = 0; nt < 8; nt++)
                        #pragma unroll
                        for (int r = 0; r < 4; r++) {
                            int col = kt * 64 + nt * 8 + 2 * lc + (r & 1);
                            int row = row_min + lr + 8 * (r >> 1);
                            if (col > row) s[nt][r] = -1e30f;
                        }
                }

                #pragma unroll
                for (int h2 = 0; h2 < 2; h2++) {
                    float rm = -1e30f;
                    #pragma unroll
                    for (int nt = 0; nt < 8; nt++)
                        rm = fmaxf(rm, fmaxf(s[nt][2*h2], s[nt][2*h2+1]));
                    rm = fmaxf(rm, __shfl_xor_sync(0xffffffffu, rm, 1));
                    rm = fmaxf(rm, __shfl_xor_sync(0xffffffffu, rm, 2));
                    float mn = fmaxf(m_i[h2], rm);
                    float alpha = __expf(m_i[h2] - mn);
                    m_i[h2] = mn;
                    float rs = 0.0f;
                    #pragma unroll
                    for (int nt = 0; nt < 8; nt++) {
                        float p0 = __expf(s[nt][2*h2]   - mn);
                        float p1 = __expf(s[nt][2*h2+1] - mn);
                        s[nt][2*h2]   = p0;
                        s[nt][2*h2+1] = p1;
                        rs += p0 + p1;
                    }
                    rs += __shfl_xor_sync(0xffffffffu, rs, 1);
                    rs += __shfl_xor_sync(0xffffffffu, rs, 2);
                    l_i[h2] = l_i[h2] * alpha + rs;
                    #pragma unroll
                    for (int nt = 0; nt < 8; nt++) {
                        o[nt][2*h2]   *= alpha;
                        o[nt][2*h2+1] *= alpha;
                    }
                }
            }

            __syncthreads();
            if (kt + 1 < nkt) {
                #pragma unroll
                for (int j = 0; j < 4; j++) {
                    int r = ldr0 + j * 16;
                    cpasync16(&sm[AT_KS + r * 68 + ldc4],
                              Kb + (size_t)((kt + 1) * 64 + r) * ld + ldc4);
                }
            }
            CP_COMMIT();

            CP_WAIT(1);
            __syncthreads();

            if (active) {
                #pragma unroll
                for (int nt = 0; nt < 8; nt++)
                    #pragma unroll
                    for (int r = 0; r < 4; r++) {
                        int row = warp * 16 + lr + 8 * (r >> 1);
                        int col = nt * 8 + 2 * lc + (r & 1);
                        sm[AT_PS + row * 68 + col] = f2tf32f(s[nt][r]);
                    }
                __syncwarp();

                #pragma unroll
                for (int kb = 0; kb < 8; kb++) {
                    unsigned af[4];
                    unsigned paddr = (unsigned)__cvta_generic_to_shared(
                        &sm[AT_PS + (warp * 16 + lrow) * 68 + kb * 8 + lkoff]);
                    ldmx4(af[0], af[1], af[2], af[3], paddr);
                    #pragma unroll
                    for (int nt = 0; nt < 8; nt++) {
                        unsigned b0 = __float_as_uint(sm[AT_VS + (kb * 8 + lc)     * 72 + nt * 8 + lr]);
                        unsigned b1 = __float_as_uint(sm[AT_VS + (kb * 8 + lc + 4) * 72 + nt * 8 + lr]);
                        mma_tf32(o[nt], af, b0, b1);
                    }
                }
            }

            __syncthreads();
            if (kt + 1 < nkt) {
                #pragma unroll
                for (int j = 0; j < 4; j++) {
                    int r = ldr0 + j * 16;
                    cpasync16(&sm[AT_VS + r * 72 + ldc4],
                              Vb + (size_t)((kt + 1) * 64 + r) * ld + ldc4);
                }
            }
            CP_COMMIT();
        }

        #pragma unroll
        for (int h2 = 0; h2 < 2; h2++) {
            float inv = 1.0f / l_i[h2];
            int row = qt * 128 + warp * 16 + lr + 8 * h2;
            #pragma unroll
            for (int nt = 0; nt < 8; nt++) {
                int col = nt * 8 + 2 * lc;
                *(float2*)(Ob + (size_t)row * ld + col) =
                    make_float2(f2tf32f(o[nt][2*h2] * inv), f2tf32f(o[nt][2*h2+1] * inv));
            }
        }
    }
}

// ---------------- launch ----------------
extern "C" void kernel_launch(void* const* d_in, const int* in_sizes, int n_in,
                              void* d_out, int out_size)
{
    const float* x       = (const float*)d_in[0];
    const float* w_q     = (const float*)d_in[1];
    const float* w_k     = (const float*)d_in[2];
    const float* w_v     = (const float*)d_in[3];
    const float* w_o     = (const float*)d_in[4];
    const float* alpha_p = (const float*)d_in[5];
    const float* delta_p = (const float*)d_in[6];
    const float* beta    = (const float*)d_in[7];
    const float* eta     = (const float*)d_in[8];
    const float* g1      = (const float*)d_in[9];
    const float* g2      = (const float*)d_in[10];
    const float* w_in    = (const float*)d_in[11];
    const float* b_in    = (const float*)d_in[12];
    const float* w_out   = (const float*)d_in[13];
    const float* b_out   = (const float*)d_in[14];
    float* out = (float*)d_out;

    float *xn, *y, *q, *k, *v, *ao, *x1, *xn2, *hb, *wr, *e1, *e2;
    float2* cs;
    cudaGetSymbolAddress((void**)&xn,  g_xn);
    cudaGetSymbolAddress((void**)&y,   g_y);
    cudaGetSymbolAddress((void**)&q,   g_q);
    cudaGetSymbolAddress((void**)&k,   g_k);
    cudaGetSymbolAddress((void**)&v,   g_v);
    cudaGetSymbolAddress((void**)&ao,  g_ao);
    cudaGetSymbolAddress((void**)&x1,  g_x1);
    cudaGetSymbolAddress((void**)&xn2, g_xn2);
    cudaGetSymbolAddress((void**)&hb,  g_hb);
    cudaGetSymbolAddress((void**)&wr,  g_w);
    cudaGetSymbolAddress((void**)&e1,  g_e1);
    cudaGetSymbolAddress((void**)&e2,  g_e2);
    cudaGetSymbolAddress((void**)&cs,  g_cs);

    cudaFuncSetAttribute(attn_kernel, cudaFuncAttributeMaxDynamicSharedMemorySize,
                         ATTN_SMEM_BYTES);
    cudaFuncSetAttribute(qkv_kernel, cudaFuncAttributeMaxDynamicSharedMemorySize, SMEM_GEMM);
    cudaFuncSetAttribute((const void*)tgemm_kernel<1,false>, cudaFuncAttributeMaxDynamicSharedMemorySize, SMEM_GEMM);
    cudaFuncSetAttribute((const void*)tgemm_kernel<2,true>,  cudaFuncAttributeMaxDynamicSharedMemorySize, SMEM_GEMM);
    cudaFuncSetAttribute((const void*)tgemm_kernel<3,false>, cudaFuncAttributeMaxDynamicSharedMemorySize, SMEM_GEMM);

    wtrans_kernel<<<12288, dim3(32, 8)>>>(w_q, w_k, w_v, w_o, w_in, w_out, wr);
    cstab_kernel<<<(TT * 16) / 256, 256>>>(cs);

    rmsnorm_kernel<<<BT, 256>>>(x, g1, xn, 1);

    ema1_kernel<<<(BB * EG * DD) / 256, 256>>>(xn, alpha_p, delta_p, beta, e1);
    ema2_kernel<<<(BB * 16 * DD) / 256, 256>>>(e1, alpha_p, delta_p, e2);
    ema3_kernel<<<(BB * EG * DD) / 256, 256>>>(xn, alpha_p, delta_p, beta, eta, e2, y);

    qkv_kernel<<<dim3(1024 / 128, BT / 128, 3), 256, SMEM_GEMM>>>(y, xn, wr, cs, q, k, v);

    attn_kernel<<<dim3(NQT / 2, BB * HH), 256, ATTN_SMEM_BYTES>>>(q, k, v, ao);

    dim3 gN1024(1024 / 128, BT / 128);
    tgemm_kernel<1,false><<<gN1024, 256, SMEM_GEMM>>>(ao, wr + 3 * 1024 * 1024, x1,
                                                      nullptr, x, 1024, 1024);

    rmsnorm_kernel<<<BT, 256>>>(x1, g2, xn2, 1);

    dim3 gN4096(4096 / 128, BT / 128);
    tgemm_kernel<2,true><<<gN4096, 256, SMEM_GEMM>>>(xn2, wr + 4 * 1024 * 1024, hb,
                                                     b_in, nullptr, 4096, 1024);
    tgemm_kernel<3,false><<<gN1024, 256, SMEM_GEMM>>>(hb, wr + 8 * 1024 * 1024, out,
                                                      b_out, x1, 1024, 4096);
}